// round 1
// baseline (speedup 1.0000x reference)
#include <cuda_runtime.h>
#include <math.h>
#include <stdint.h>

// ---------------------------------------------------------------------------
// GAT (3 layers, single head) + mean pool + sigmoid.
// Inputs (metadata order):
//  0: x [N,11] f32          1: edge_index [2,E] i32     2: edge_attr (unused)
//  3: batch [N] i32
//  4: W1[11,128] 5: as1[128] 6: ad1[128] 7: b1[128]
//  8: W2[128,128] 9: as2 10: ad2 11: b2
// 12: W3[128,16] 13: as3[16] 14: ad3[16] 15: b3[16]
// Output: sigmoid(meanpool) [64,16] f32
// ---------------------------------------------------------------------------

#define NMAX   50000
#define EMAX   800000
#define ETOTMX (EMAX + NMAX)
#define HID    128
#define NC     16
#define NG     64

// scratch (device globals: no allocation allowed)
__device__ float g_A[NMAX * HID];     // layer output / next layer input
__device__ float g_B[NMAX * HID];
__device__ float g_h[NMAX * HID];     // transformed features h = in @ W
__device__ float g_as[NMAX];
__device__ float g_ad[NMAX];
__device__ float g_m[NMAX];
__device__ float g_den[NMAX];
__device__ float g_e[ETOTMX];
__device__ float g_pool[NG * NC];
__device__ float g_cnt[NG];

// ---------------------------------------------------------------------------

__device__ __forceinline__ void atomicMaxF(float* addr, float v) {
    // monotone int trick; initial value must be -inf (0xFF800000)
    if (v >= 0.0f) atomicMax((int*)addr, __float_as_int(v));
    else           atomicMin((unsigned int*)addr, (unsigned int)__float_as_int(v));
}

__global__ void init_layer_kernel(float* __restrict__ out, float* __restrict__ m,
                                  float* __restrict__ den, int n, int C) {
    int i = blockIdx.x * blockDim.x + threadIdx.x;
    if (i < n * C) out[i] = 0.0f;
    if (i < n) { m[i] = __int_as_float(0xFF800000); den[i] = 0.0f; }
}

// --------------------------- GEMM, C = 128 ---------------------------------
// warp handles 8 nodes; lane owns 4 output cols (lane*4 .. lane*4+3).
// Fused epilogue: alpha_s[n] = h[n,:]·a_src, alpha_d[n] = h[n,:]·a_dst.
__global__ void gemm128_kernel(const float* __restrict__ in, int K,
                               const float* __restrict__ W,
                               const float* __restrict__ a_s,
                               const float* __restrict__ a_d,
                               float* __restrict__ h,
                               float* __restrict__ as_o,
                               float* __restrict__ ad_o, int n) {
    int w    = (blockIdx.x * blockDim.x + threadIdx.x) >> 5;
    int lane = threadIdx.x & 31;
    int node0 = w * 8;
    if (node0 >= n) return;

    int nid[8];
#pragma unroll
    for (int i = 0; i < 8; i++) {
        int nn = node0 + i;
        nid[i] = nn < n ? nn : (n - 1);   // clamped duplicates write identical data
    }

    float4 acc[8];
#pragma unroll
    for (int i = 0; i < 8; i++) acc[i] = make_float4(0.f, 0.f, 0.f, 0.f);

    for (int k = 0; k < K; k++) {
        float4 wv = *(const float4*)(W + k * HID + lane * 4);
#pragma unroll
        for (int i = 0; i < 8; i++) {
            float a = __ldg(in + (size_t)nid[i] * K + k);
            acc[i].x = fmaf(a, wv.x, acc[i].x);
            acc[i].y = fmaf(a, wv.y, acc[i].y);
            acc[i].z = fmaf(a, wv.z, acc[i].z);
            acc[i].w = fmaf(a, wv.w, acc[i].w);
        }
    }

    float4 sv = *(const float4*)(a_s + lane * 4);
    float4 dv = *(const float4*)(a_d + lane * 4);

#pragma unroll
    for (int i = 0; i < 8; i++) {
        *(float4*)(h + (size_t)nid[i] * HID + lane * 4) = acc[i];
        float ps = acc[i].x * sv.x + acc[i].y * sv.y + acc[i].z * sv.z + acc[i].w * sv.w;
        float pd = acc[i].x * dv.x + acc[i].y * dv.y + acc[i].z * dv.z + acc[i].w * dv.w;
#pragma unroll
        for (int o = 16; o > 0; o >>= 1) {
            ps += __shfl_xor_sync(0xffffffffu, ps, o);
            pd += __shfl_xor_sync(0xffffffffu, pd, o);
        }
        if (lane == 0) { as_o[nid[i]] = ps; ad_o[nid[i]] = pd; }
    }
}

// --------------------------- GEMM, C = 16 (layer 3) ------------------------
__global__ void gemm16_kernel(const float* __restrict__ in,   // [n,128]
                              const float* __restrict__ W,    // [128,16]
                              const float* __restrict__ a_s,
                              const float* __restrict__ a_d,
                              float* __restrict__ h,
                              float* __restrict__ as_o,
                              float* __restrict__ ad_o, int n) {
    int t = blockIdx.x * blockDim.x + threadIdx.x;
    int node = t >> 4;
    int c = t & 15;
    if (node >= n) return;

    const float* row = in + (size_t)node * HID;
    float acc = 0.f;
#pragma unroll 8
    for (int k = 0; k < HID; k++)
        acc = fmaf(__ldg(row + k), __ldg(W + k * NC + c), acc);

    h[(size_t)node * NC + c] = acc;
    float ps = acc * a_s[c];
    float pd = acc * a_d[c];
#pragma unroll
    for (int o = 8; o > 0; o >>= 1) {
        ps += __shfl_xor_sync(0xffffffffu, ps, o, 16);
        pd += __shfl_xor_sync(0xffffffffu, pd, o, 16);
    }
    if (c == 0) { as_o[node] = ps; ad_o[node] = pd; }
}

// --------------------------- edge passes -----------------------------------
__global__ void edge_max_kernel(const int* __restrict__ src, const int* __restrict__ dst,
                                int E, int Etot,
                                const float* __restrict__ as_v,
                                const float* __restrict__ ad_v,
                                float* __restrict__ e, float* __restrict__ m) {
    int t = blockIdx.x * blockDim.x + threadIdx.x;
    if (t >= Etot) return;
    int s = t < E ? __ldg(src + t) : (t - E);
    int d = t < E ? __ldg(dst + t) : (t - E);
    float v = __ldg(as_v + s) + __ldg(ad_v + d);
    v = v > 0.f ? v : 0.2f * v;            // leaky_relu(0.2)
    e[t] = v;
    atomicMaxF(&m[d], v);
}

__global__ void edge_exp_kernel(const int* __restrict__ dst, int E, int Etot,
                                float* __restrict__ e,
                                const float* __restrict__ m,
                                float* __restrict__ den) {
    int t = blockIdx.x * blockDim.x + threadIdx.x;
    if (t >= Etot) return;
    int d = t < E ? __ldg(dst + t) : (t - E);
    float ex = expf(e[t] - __ldg(m + d));  // arg <= 0, no overflow
    e[t] = ex;
    atomicAdd(&den[d], ex);
}

__device__ __forceinline__ void red_add_v4(float* p, float a, float b, float c, float d) {
    asm volatile("red.global.add.v4.f32 [%0], {%1,%2,%3,%4};"
                 :: "l"(p), "f"(a), "f"(b), "f"(c), "f"(d) : "memory");
}

// one warp per edge; lane owns 4 feature cols
__global__ void edge_aggr128_kernel(const int* __restrict__ src, const int* __restrict__ dst,
                                    int E, int Etot,
                                    const float* __restrict__ e,
                                    const float* __restrict__ den,
                                    const float* __restrict__ h,
                                    float* __restrict__ out) {
    int w = (blockIdx.x * blockDim.x + threadIdx.x) >> 5;
    if (w >= Etot) return;
    int lane = threadIdx.x & 31;
    int s = w < E ? __ldg(src + w) : (w - E);
    int d = w < E ? __ldg(dst + w) : (w - E);
    float alpha = __ldg(e + w) / __ldg(den + d);
    float4 hv = *(const float4*)(h + (size_t)s * HID + lane * 4);
    red_add_v4(out + (size_t)d * HID + lane * 4,
               alpha * hv.x, alpha * hv.y, alpha * hv.z, alpha * hv.w);
}

// 4 threads per edge (4 cols each)
__global__ void edge_aggr16_kernel(const int* __restrict__ src, const int* __restrict__ dst,
                                   int E, int Etot,
                                   const float* __restrict__ e,
                                   const float* __restrict__ den,
                                   const float* __restrict__ h,
                                   float* __restrict__ out) {
    int t = blockIdx.x * blockDim.x + threadIdx.x;
    int w = t >> 2;
    if (w >= Etot) return;
    int c4 = (t & 3) * 4;
    int s = w < E ? __ldg(src + w) : (w - E);
    int d = w < E ? __ldg(dst + w) : (w - E);
    float alpha = __ldg(e + w) / __ldg(den + d);
    float4 hv = *(const float4*)(h + (size_t)s * NC + c4);
    red_add_v4(out + (size_t)d * NC + c4,
               alpha * hv.x, alpha * hv.y, alpha * hv.z, alpha * hv.w);
}

__global__ void relu_bias_kernel(float* __restrict__ x, const float* __restrict__ b,
                                 int total, int cmask) {
    int i = blockIdx.x * blockDim.x + threadIdx.x;
    if (i >= total) return;
    x[i] = fmaxf(x[i] + __ldg(b + (i & cmask)), 0.0f);
}

// --------------------------- pooling ----------------------------------------
__global__ void zero_pool_kernel(float* __restrict__ pool, float* __restrict__ cnt) {
    int i = blockIdx.x * blockDim.x + threadIdx.x;
    if (i < NG * NC) pool[i] = 0.f;
    if (i < NG) cnt[i] = 0.f;
}

__global__ void pool_kernel(const float* __restrict__ h, const int* __restrict__ batch,
                            int n, float* __restrict__ pool, float* __restrict__ cnt) {
    int t = blockIdx.x * blockDim.x + threadIdx.x;
    if (t >= n * NC) return;
    int node = t >> 4;
    int c = t & 15;
    int g = __ldg(batch + node);
    atomicAdd(&pool[g * NC + c], h[t]);
    if (c == 0) atomicAdd(&cnt[g], 1.0f);
}

__global__ void finalize_kernel(const float* __restrict__ pool,
                                const float* __restrict__ cnt,
                                float* __restrict__ outp) {
    int t = blockIdx.x * blockDim.x + threadIdx.x;
    if (t >= NG * NC) return;
    int g = t >> 4;
    float v = pool[t] / fmaxf(cnt[g], 1.0f);
    outp[t] = 1.0f / (1.0f + expf(-v));
}

// ---------------------------------------------------------------------------

extern "C" void kernel_launch(void* const* d_in, const int* in_sizes, int n_in,
                              void* d_out, int out_size) {
    const float* x     = (const float*)d_in[0];
    const int*   ei    = (const int*)  d_in[1];
    const int*   batch = (const int*)  d_in[3];
    const float* W1  = (const float*)d_in[4];
    const float* as1 = (const float*)d_in[5];
    const float* ad1 = (const float*)d_in[6];
    const float* b1  = (const float*)d_in[7];
    const float* W2  = (const float*)d_in[8];
    const float* as2 = (const float*)d_in[9];
    const float* ad2 = (const float*)d_in[10];
    const float* b2  = (const float*)d_in[11];
    const float* W3  = (const float*)d_in[12];
    const float* as3 = (const float*)d_in[13];
    const float* ad3 = (const float*)d_in[14];
    const float* b3  = (const float*)d_in[15];
    float* out = (float*)d_out;

    int n    = in_sizes[0] / 11;
    int E    = in_sizes[1] / 2;
    int Etot = E + n;
    const int* src = ei;
    const int* dst = ei + E;

    float *pA, *pB, *ph, *pas, *pad, *pm, *pden, *pe, *ppool, *pcnt;
    cudaGetSymbolAddress((void**)&pA,    g_A);
    cudaGetSymbolAddress((void**)&pB,    g_B);
    cudaGetSymbolAddress((void**)&ph,    g_h);
    cudaGetSymbolAddress((void**)&pas,   g_as);
    cudaGetSymbolAddress((void**)&pad,   g_ad);
    cudaGetSymbolAddress((void**)&pm,    g_m);
    cudaGetSymbolAddress((void**)&pden,  g_den);
    cudaGetSymbolAddress((void**)&pe,    g_e);
    cudaGetSymbolAddress((void**)&ppool, g_pool);
    cudaGetSymbolAddress((void**)&pcnt,  g_cnt);

    const int TB = 256;
    int gInit128  = (n * HID + TB - 1) / TB;
    int gInit16   = (n * NC + TB - 1) / TB;
    int gEdge     = (Etot + TB - 1) / TB;
    int gAggr128  = ((Etot * 32) + TB - 1) / TB;
    int gAggr16   = ((Etot * 4) + TB - 1) / TB;
    int warps128  = (n + 7) / 8;
    int gGemm128  = (warps128 * 32 + TB - 1) / TB;
    int gGemm16   = (n * NC + TB - 1) / TB;

    // ---- layer 1: x[ N,11 ] -> g_A [N,128] ----
    init_layer_kernel<<<gInit128, TB>>>(pA, pm, pden, n, HID);
    gemm128_kernel<<<gGemm128, TB>>>(x, 11, W1, as1, ad1, ph, pas, pad, n);
    edge_max_kernel<<<gEdge, TB>>>(src, dst, E, Etot, pas, pad, pe, pm);
    edge_exp_kernel<<<gEdge, TB>>>(dst, E, Etot, pe, pm, pden);
    edge_aggr128_kernel<<<gAggr128, TB>>>(src, dst, E, Etot, pe, pden, ph, pA);
    relu_bias_kernel<<<gInit128, TB>>>(pA, b1, n * HID, HID - 1);

    // ---- layer 2: g_A -> g_B [N,128] ----
    init_layer_kernel<<<gInit128, TB>>>(pB, pm, pden, n, HID);
    gemm128_kernel<<<gGemm128, TB>>>(pA, HID, W2, as2, ad2, ph, pas, pad, n);
    edge_max_kernel<<<gEdge, TB>>>(src, dst, E, Etot, pas, pad, pe, pm);
    edge_exp_kernel<<<gEdge, TB>>>(dst, E, Etot, pe, pm, pden);
    edge_aggr128_kernel<<<gAggr128, TB>>>(src, dst, E, Etot, pe, pden, ph, pB);
    relu_bias_kernel<<<gInit128, TB>>>(pB, b2, n * HID, HID - 1);

    // ---- layer 3: g_B -> g_A [N,16] ----
    init_layer_kernel<<<gInit16, TB>>>(pA, pm, pden, n, NC);
    gemm16_kernel<<<gGemm16, TB>>>(pB, W3, as3, ad3, ph, pas, pad, n);
    edge_max_kernel<<<gEdge, TB>>>(src, dst, E, Etot, pas, pad, pe, pm);
    edge_exp_kernel<<<gEdge, TB>>>(dst, E, Etot, pe, pm, pden);
    edge_aggr16_kernel<<<gAggr16, TB>>>(src, dst, E, Etot, pe, pden, ph, pA);
    relu_bias_kernel<<<gInit16, TB>>>(pA, b3, n * NC, NC - 1);

    // ---- pooling + sigmoid ----
    zero_pool_kernel<<<(NG * NC + TB - 1) / TB, TB>>>(ppool, pcnt);
    pool_kernel<<<(n * NC + TB - 1) / TB, TB>>>(pA, batch, n, ppool, pcnt);
    finalize_kernel<<<(NG * NC + TB - 1) / TB, TB>>>(ppool, pcnt, out);
}

// round 3
// speedup vs baseline: 1.4335x; 1.4335x over previous
#include <cuda_runtime.h>
#include <math.h>
#include <stdint.h>

// ---------------------------------------------------------------------------
// GAT (3 layers, single head) + mean pool + sigmoid — CSR + fused online-softmax
// aggregation (no atomics in the per-layer hot path).
// ---------------------------------------------------------------------------

#define NMAX   50000
#define EMAX   800000
#define ETOTMX (EMAX + NMAX)
#define HID    128
#define NC     16
#define NG     64

// scratch (device globals; allocation is forbidden)
__device__ float g_A[NMAX * HID];     // layer output / next layer input
__device__ float g_B[NMAX * HID];
__device__ float g_h[NMAX * HID];     // h = in @ W
__device__ float g_as[NMAX];
__device__ float g_ad[NMAX];
__device__ float g_pool[NG * NC];
__device__ float g_cnt[NG];
__device__ int   g_deg[NMAX];
__device__ int   g_rowptr[NMAX + 1];
__device__ int   g_cursor[NMAX];
__device__ int   g_col[ETOTMX];       // src node per CSR slot (grouped by dst)

// --------------------------- CSR build --------------------------------------

__global__ void zero_deg_kernel(int* __restrict__ deg, int n) {
    int i = blockIdx.x * blockDim.x + threadIdx.x;
    if (i < n) deg[i] = 0;
}

__global__ void count_deg_kernel(const int* __restrict__ dst, int E, int Etot,
                                 int* __restrict__ deg) {
    int t = blockIdx.x * blockDim.x + threadIdx.x;
    if (t >= Etot) return;
    int d = t < E ? __ldg(dst + t) : (t - E);
    atomicAdd(&deg[d], 1);
}

// single-block exclusive scan over deg -> rowptr, cursor
__global__ void scan_kernel(const int* __restrict__ deg, int* __restrict__ rowptr,
                            int* __restrict__ cursor, int n) {
    __shared__ int s_carry;
    __shared__ int warp_sums[32];
    int lane = threadIdx.x & 31, wid = threadIdx.x >> 5;
    if (threadIdx.x == 0) { s_carry = 0; rowptr[0] = 0; }
    __syncthreads();
    for (int base = 0; base < n; base += 1024) {
        int i = base + (int)threadIdx.x;
        int v = i < n ? deg[i] : 0;
        int x = v;
#pragma unroll
        for (int o = 1; o < 32; o <<= 1) {
            int t = __shfl_up_sync(0xffffffffu, x, o);
            if (lane >= o) x += t;
        }
        if (lane == 31) warp_sums[wid] = x;
        __syncthreads();
        if (wid == 0) {
            int s = warp_sums[lane];
#pragma unroll
            for (int o = 1; o < 32; o <<= 1) {
                int t = __shfl_up_sync(0xffffffffu, s, o);
                if (lane >= o) s += t;
            }
            warp_sums[lane] = s;
        }
        __syncthreads();
        int incl = x + (wid > 0 ? warp_sums[wid - 1] : 0) + s_carry;
        if (i < n) { rowptr[i + 1] = incl; cursor[i] = incl - v; }
        __syncthreads();
        if (threadIdx.x == 1023) s_carry = incl;  // padding lanes add 0
        __syncthreads();
    }
}

__global__ void scatter_kernel(const int* __restrict__ src, const int* __restrict__ dst,
                               int E, int Etot,
                               int* __restrict__ cursor, int* __restrict__ col) {
    int t = blockIdx.x * blockDim.x + threadIdx.x;
    if (t >= Etot) return;
    int s = t < E ? __ldg(src + t) : (t - E);
    int d = t < E ? __ldg(dst + t) : (t - E);
    int pos = atomicAdd(&cursor[d], 1);
    col[pos] = s;
}

// --------------------------- GEMM, C = 128 ---------------------------------
// warp handles 8 nodes; lane owns 4 output cols. Fused alpha_src/alpha_dst dots.
__global__ void gemm128_kernel(const float* __restrict__ in, int K,
                               const float* __restrict__ W,
                               const float* __restrict__ a_s,
                               const float* __restrict__ a_d,
                               float* __restrict__ h,
                               float* __restrict__ as_o,
                               float* __restrict__ ad_o, int n) {
    int w    = (blockIdx.x * blockDim.x + threadIdx.x) >> 5;
    int lane = threadIdx.x & 31;
    int node0 = w * 8;
    if (node0 >= n) return;

    int nid[8];
#pragma unroll
    for (int i = 0; i < 8; i++) {
        int nn = node0 + i;
        nid[i] = nn < n ? nn : (n - 1);
    }

    float4 acc[8];
#pragma unroll
    for (int i = 0; i < 8; i++) acc[i] = make_float4(0.f, 0.f, 0.f, 0.f);

    for (int k = 0; k < K; k++) {
        float4 wv = *(const float4*)(W + k * HID + lane * 4);
#pragma unroll
        for (int i = 0; i < 8; i++) {
            float a = __ldg(in + (size_t)nid[i] * K + k);
            acc[i].x = fmaf(a, wv.x, acc[i].x);
            acc[i].y = fmaf(a, wv.y, acc[i].y);
            acc[i].z = fmaf(a, wv.z, acc[i].z);
            acc[i].w = fmaf(a, wv.w, acc[i].w);
        }
    }

    float4 sv = *(const float4*)(a_s + lane * 4);
    float4 dv = *(const float4*)(a_d + lane * 4);

#pragma unroll
    for (int i = 0; i < 8; i++) {
        *(float4*)(h + (size_t)nid[i] * HID + lane * 4) = acc[i];
        float ps = acc[i].x * sv.x + acc[i].y * sv.y + acc[i].z * sv.z + acc[i].w * sv.w;
        float pd = acc[i].x * dv.x + acc[i].y * dv.y + acc[i].z * dv.z + acc[i].w * dv.w;
#pragma unroll
        for (int o = 16; o > 0; o >>= 1) {
            ps += __shfl_xor_sync(0xffffffffu, ps, o);
            pd += __shfl_xor_sync(0xffffffffu, pd, o);
        }
        if (lane == 0) { as_o[nid[i]] = ps; ad_o[nid[i]] = pd; }
    }
}

// --------------------------- GEMM, C = 16 (layer 3) ------------------------
__global__ void gemm16_kernel(const float* __restrict__ in,
                              const float* __restrict__ W,
                              const float* __restrict__ a_s,
                              const float* __restrict__ a_d,
                              float* __restrict__ h,
                              float* __restrict__ as_o,
                              float* __restrict__ ad_o, int n) {
    int t = blockIdx.x * blockDim.x + threadIdx.x;
    int node = t >> 4;
    int c = t & 15;
    if (node >= n) return;

    const float* row = in + (size_t)node * HID;
    float acc = 0.f;
#pragma unroll 8
    for (int k = 0; k < HID; k++)
        acc = fmaf(__ldg(row + k), __ldg(W + k * NC + c), acc);

    h[(size_t)node * NC + c] = acc;
    float ps = acc * a_s[c];
    float pd = acc * a_d[c];
#pragma unroll
    for (int o = 8; o > 0; o >>= 1) {
        ps += __shfl_xor_sync(0xffffffffu, ps, o, 16);
        pd += __shfl_xor_sync(0xffffffffu, pd, o, 16);
    }
    if (c == 0) { as_o[node] = ps; ad_o[node] = pd; }
}

// ------------------ fused online-softmax aggregation, C=128 -----------------
// one warp per dst node; lane owns 4 cols. Epilogue: relu(acc/den + b).
__global__ void fused_aggr128_kernel(const int* __restrict__ rowptr,
                                     const int* __restrict__ col,
                                     const float* __restrict__ as_v,
                                     const float* __restrict__ ad_v,
                                     const float* __restrict__ h,
                                     const float* __restrict__ bias,
                                     float* __restrict__ out, int n) {
    int node = (blockIdx.x * blockDim.x + threadIdx.x) >> 5;
    if (node >= n) return;
    int lane = threadIdx.x & 31;

    float advv = __ldg(ad_v + node);
    int beg = __ldg(rowptr + node);
    int end = __ldg(rowptr + node + 1);

    float m = __int_as_float(0xFF800000);  // -inf (self-loop guarantees >=1 edge)
    float den = 0.0f;
    float4 acc = make_float4(0.f, 0.f, 0.f, 0.f);

    // software-pipelined gather
    int s = __ldg(col + beg);
    float asv = __ldg(as_v + s);
    float4 hv = *(const float4*)(h + (size_t)s * HID + lane * 4);

    for (int i = beg; i < end; i++) {
        int   s2;  float as2;  float4 hv2;
        if (i + 1 < end) {
            s2  = __ldg(col + i + 1);
            as2 = __ldg(as_v + s2);
            hv2 = *(const float4*)(h + (size_t)s2 * HID + lane * 4);
        }
        float e = asv + advv;
        e = e > 0.f ? e : 0.2f * e;             // leaky_relu(0.2)
        float nm = fmaxf(m, e);
        float scale = __expf(m - nm);           // first iter: exp(-inf)=0
        float wgt   = __expf(e - nm);
        den = den * scale + wgt;
        acc.x = fmaf(acc.x, scale, wgt * hv.x);
        acc.y = fmaf(acc.y, scale, wgt * hv.y);
        acc.z = fmaf(acc.z, scale, wgt * hv.z);
        acc.w = fmaf(acc.w, scale, wgt * hv.w);
        m = nm;
        if (i + 1 < end) { s = s2; asv = as2; hv = hv2; }
    }

    float inv = 1.0f / den;
    float4 bv = *(const float4*)(bias + lane * 4);
    float4 o;
    o.x = fmaxf(fmaf(acc.x, inv, bv.x), 0.f);
    o.y = fmaxf(fmaf(acc.y, inv, bv.y), 0.f);
    o.z = fmaxf(fmaf(acc.z, inv, bv.z), 0.f);
    o.w = fmaxf(fmaf(acc.w, inv, bv.w), 0.f);
    *(float4*)(out + (size_t)node * HID + lane * 4) = o;
}

// ------------- fused aggregation C=16 + pooling epilogue (layer 3) ----------
// half-warp per node; lane owns 1 col. Epilogue: relu(acc/den+b) -> pool atomics.
__global__ void fused_aggr16_pool_kernel(const int* __restrict__ rowptr,
                                         const int* __restrict__ col,
                                         const float* __restrict__ as_v,
                                         const float* __restrict__ ad_v,
                                         const float* __restrict__ h,
                                         const float* __restrict__ bias,
                                         const int* __restrict__ batch,
                                         float* __restrict__ pool, int n) {
    int w = (blockIdx.x * blockDim.x + threadIdx.x) >> 5;
    int lane = threadIdx.x & 31;
    int node = w * 2 + (lane >> 4);
    int c = lane & 15;
    bool active = node < n;

    float advv = active ? __ldg(ad_v + node) : 0.f;
    int beg = active ? __ldg(rowptr + node) : 0;
    int end = active ? __ldg(rowptr + node + 1) : 0;

    float m = __int_as_float(0xFF800000);
    float den = 0.0f, acc = 0.0f;

    for (int i = beg; i < end; i++) {
        int s = __ldg(col + i);
        float e = __ldg(as_v + s) + advv;
        e = e > 0.f ? e : 0.2f * e;
        float nm = fmaxf(m, e);
        float scale = __expf(m - nm);
        float wgt   = __expf(e - nm);
        den = den * scale + wgt;
        acc = fmaf(acc, scale, wgt * __ldg(h + (size_t)s * NC + c));
        m = nm;
    }

    if (active) {
        float val = fmaxf(acc / den + __ldg(bias + c), 0.f);
        int g = __ldg(batch + node);
        atomicAdd(&pool[g * NC + c], val);
    }
}

// --------------------------- pooling tail -----------------------------------
__global__ void zero_pool_kernel(float* __restrict__ pool, float* __restrict__ cnt) {
    int i = blockIdx.x * blockDim.x + threadIdx.x;
    if (i < NG * NC) pool[i] = 0.f;
    if (i < NG) cnt[i] = 0.f;
}

__global__ void cnt_kernel(const int* __restrict__ batch, int n, float* __restrict__ cnt) {
    int i = blockIdx.x * blockDim.x + threadIdx.x;
    if (i >= n) return;
    atomicAdd(&cnt[__ldg(batch + i)], 1.0f);
}

__global__ void finalize_kernel(const float* __restrict__ pool,
                                const float* __restrict__ cnt,
                                float* __restrict__ outp) {
    int t = blockIdx.x * blockDim.x + threadIdx.x;
    if (t >= NG * NC) return;
    int g = t >> 4;
    float v = pool[t] / fmaxf(cnt[g], 1.0f);
    outp[t] = 1.0f / (1.0f + expf(-v));
}

// ---------------------------------------------------------------------------

extern "C" void kernel_launch(void* const* d_in, const int* in_sizes, int n_in,
                              void* d_out, int out_size) {
    const float* x     = (const float*)d_in[0];
    const int*   ei    = (const int*)  d_in[1];
    const int*   batch = (const int*)  d_in[3];
    const float* W1  = (const float*)d_in[4];
    const float* as1 = (const float*)d_in[5];
    const float* ad1 = (const float*)d_in[6];
    const float* b1  = (const float*)d_in[7];
    const float* W2  = (const float*)d_in[8];
    const float* as2 = (const float*)d_in[9];
    const float* ad2 = (const float*)d_in[10];
    const float* b2  = (const float*)d_in[11];
    const float* W3  = (const float*)d_in[12];
    const float* as3 = (const float*)d_in[13];
    const float* ad3 = (const float*)d_in[14];
    const float* b3  = (const float*)d_in[15];
    float* out = (float*)d_out;

    int n    = in_sizes[0] / 11;
    int E    = in_sizes[1] / 2;
    int Etot = E + n;
    const int* src = ei;
    const int* dst = ei + E;

    float *pA, *pB, *ph, *pas, *pad, *ppool, *pcnt;
    int *pdeg, *prow, *pcur, *pcol;
    cudaGetSymbolAddress((void**)&pA,    g_A);
    cudaGetSymbolAddress((void**)&pB,    g_B);
    cudaGetSymbolAddress((void**)&ph,    g_h);
    cudaGetSymbolAddress((void**)&pas,   g_as);
    cudaGetSymbolAddress((void**)&pad,   g_ad);
    cudaGetSymbolAddress((void**)&ppool, g_pool);
    cudaGetSymbolAddress((void**)&pcnt,  g_cnt);
    cudaGetSymbolAddress((void**)&pdeg,  g_deg);
    cudaGetSymbolAddress((void**)&prow,  g_rowptr);
    cudaGetSymbolAddress((void**)&pcur,  g_cursor);
    cudaGetSymbolAddress((void**)&pcol,  g_col);

    const int TB = 256;
    int gN       = (n + TB - 1) / TB;
    int gEdge    = (Etot + TB - 1) / TB;
    int warps128 = (n + 7) / 8;
    int gGemm128 = (warps128 * 32 + TB - 1) / TB;
    int gGemm16  = (n * NC + TB - 1) / TB;
    int gAggr128 = (n * 32 + TB - 1) / TB;             // warp per node
    int gAggr16  = (((n + 1) / 2) * 32 + TB - 1) / TB; // half-warp per node
    int gPool    = (NG * NC + TB - 1) / TB;            // covers all 1024 elems

    // ---- CSR build (edges grouped by dst; self-loops appended) ----
    zero_deg_kernel<<<gN, TB>>>(pdeg, n);
    count_deg_kernel<<<gEdge, TB>>>(dst, E, Etot, pdeg);
    scan_kernel<<<1, 1024>>>(pdeg, prow, pcur, n);
    scatter_kernel<<<gEdge, TB>>>(src, dst, E, Etot, pcur, pcol);

    // ---- layer 1 ----
    gemm128_kernel<<<gGemm128, TB>>>(x, 11, W1, as1, ad1, ph, pas, pad, n);
    fused_aggr128_kernel<<<gAggr128, TB>>>(prow, pcol, pas, pad, ph, b1, pA, n);

    // ---- layer 2 ----
    gemm128_kernel<<<gGemm128, TB>>>(pA, HID, W2, as2, ad2, ph, pas, pad, n);
    fused_aggr128_kernel<<<gAggr128, TB>>>(prow, pcol, pas, pad, ph, b2, pB, n);

    // ---- layer 3 + pooling ----
    zero_pool_kernel<<<gPool, TB>>>(ppool, pcnt);
    cnt_kernel<<<gN, TB>>>(batch, n, pcnt);
    gemm16_kernel<<<gGemm16, TB>>>(pB, W3, as3, ad3, ph, pas, pad, n);
    fused_aggr16_pool_kernel<<<gAggr16, TB>>>(prow, pcol, pas, pad, ph, b3, batch, ppool, n);
    finalize_kernel<<<gPool, TB>>>(ppool, pcnt, out);
}

// round 4
// speedup vs baseline: 1.6236x; 1.1327x over previous
#include <cuda_runtime.h>
#include <cuda_fp16.h>
#include <math.h>
#include <stdint.h>

// ---------------------------------------------------------------------------
// GAT (3 layers, single head) + mean pool + sigmoid.
// CSR grouped by dst + fused online-softmax aggregation (no hot-path atomics).
// h (post-GEMM features) stored fp16 to halve gather traffic; all attention
// math and accumulation in fp32.
// ---------------------------------------------------------------------------

#define NMAX   50000
#define EMAX   800000
#define ETOTMX (EMAX + NMAX)
#define HID    128
#define NC     16
#define NG     64

__device__ float  g_A[NMAX * HID];    // layer output / next layer input (fp32)
__device__ float  g_B[NMAX * HID];
__device__ __half g_h[NMAX * HID];    // h = in @ W  (fp16, gathered by aggr)
__device__ float  g_as[NMAX];
__device__ float  g_ad[NMAX];
__device__ float  g_pool[NG * NC];
__device__ float  g_cnt[NG];
__device__ int    g_deg[NMAX];
__device__ int    g_rowptr[NMAX + 1];
__device__ int    g_cursor[NMAX];
__device__ int    g_col[ETOTMX];      // src per CSR slot (grouped by dst)

// --------------------------- CSR build --------------------------------------

__global__ void zero_deg_kernel(int* __restrict__ deg, int n,
                                float* __restrict__ pool, float* __restrict__ cnt) {
    int i = blockIdx.x * blockDim.x + threadIdx.x;
    if (i < n) deg[i] = 0;
    if (i < NG * NC) pool[i] = 0.f;
    if (i < NG) cnt[i] = 0.f;
}

__global__ void count_deg_kernel(const int* __restrict__ dst, int E, int Etot,
                                 int* __restrict__ deg) {
    int t = blockIdx.x * blockDim.x + threadIdx.x;
    if (t >= Etot) return;
    int d = t < E ? __ldg(dst + t) : (t - E);
    atomicAdd(&deg[d], 1);
}

// single-block exclusive scan over deg -> rowptr, cursor
__global__ void scan_kernel(const int* __restrict__ deg, int* __restrict__ rowptr,
                            int* __restrict__ cursor, int n) {
    __shared__ int s_carry;
    __shared__ int warp_sums[32];
    int lane = threadIdx.x & 31, wid = threadIdx.x >> 5;
    if (threadIdx.x == 0) { s_carry = 0; rowptr[0] = 0; }
    __syncthreads();
    for (int base = 0; base < n; base += 1024) {
        int i = base + (int)threadIdx.x;
        int v = i < n ? deg[i] : 0;
        int x = v;
#pragma unroll
        for (int o = 1; o < 32; o <<= 1) {
            int t = __shfl_up_sync(0xffffffffu, x, o);
            if (lane >= o) x += t;
        }
        if (lane == 31) warp_sums[wid] = x;
        __syncthreads();
        if (wid == 0) {
            int s = warp_sums[lane];
#pragma unroll
            for (int o = 1; o < 32; o <<= 1) {
                int t = __shfl_up_sync(0xffffffffu, s, o);
                if (lane >= o) s += t;
            }
            warp_sums[lane] = s;
        }
        __syncthreads();
        int incl = x + (wid > 0 ? warp_sums[wid - 1] : 0) + s_carry;
        if (i < n) { rowptr[i + 1] = incl; cursor[i] = incl - v; }
        __syncthreads();
        if (threadIdx.x == 1023) s_carry = incl;
        __syncthreads();
    }
}

__global__ void scatter_kernel(const int* __restrict__ src, const int* __restrict__ dst,
                               int E, int Etot,
                               int* __restrict__ cursor, int* __restrict__ col) {
    int t = blockIdx.x * blockDim.x + threadIdx.x;
    if (t >= Etot) return;
    int s = t < E ? __ldg(src + t) : (t - E);
    int d = t < E ? __ldg(dst + t) : (t - E);
    int pos = atomicAdd(&cursor[d], 1);
    col[pos] = s;
}

// --------------------------- GEMM, C = 128 ---------------------------------
// warp handles 8 nodes; lane owns 4 cols. fp32 math, fp16 h output.
// Fused alpha_src/alpha_dst dot products (fp32).
__global__ void gemm128_kernel(const float* __restrict__ in, int K,
                               const float* __restrict__ W,
                               const float* __restrict__ a_s,
                               const float* __restrict__ a_d,
                               __half* __restrict__ h,
                               float* __restrict__ as_o,
                               float* __restrict__ ad_o, int n) {
    int w    = (blockIdx.x * blockDim.x + threadIdx.x) >> 5;
    int lane = threadIdx.x & 31;
    int node0 = w * 8;
    if (node0 >= n) return;

    int nid[8];
#pragma unroll
    for (int i = 0; i < 8; i++) {
        int nn = node0 + i;
        nid[i] = nn < n ? nn : (n - 1);
    }

    float4 acc[8];
#pragma unroll
    for (int i = 0; i < 8; i++) acc[i] = make_float4(0.f, 0.f, 0.f, 0.f);

    for (int k = 0; k < K; k++) {
        float4 wv = *(const float4*)(W + k * HID + lane * 4);
#pragma unroll
        for (int i = 0; i < 8; i++) {
            float a = __ldg(in + (size_t)nid[i] * K + k);
            acc[i].x = fmaf(a, wv.x, acc[i].x);
            acc[i].y = fmaf(a, wv.y, acc[i].y);
            acc[i].z = fmaf(a, wv.z, acc[i].z);
            acc[i].w = fmaf(a, wv.w, acc[i].w);
        }
    }

    float4 sv = *(const float4*)(a_s + lane * 4);
    float4 dv = *(const float4*)(a_d + lane * 4);

#pragma unroll
    for (int i = 0; i < 8; i++) {
        __half2 p0 = __floats2half2_rn(acc[i].x, acc[i].y);
        __half2 p1 = __floats2half2_rn(acc[i].z, acc[i].w);
        uint2 packed = make_uint2(*(unsigned*)&p0, *(unsigned*)&p1);
        *(uint2*)(h + (size_t)nid[i] * HID + lane * 4) = packed;

        float ps = acc[i].x * sv.x + acc[i].y * sv.y + acc[i].z * sv.z + acc[i].w * sv.w;
        float pd = acc[i].x * dv.x + acc[i].y * dv.y + acc[i].z * dv.z + acc[i].w * dv.w;
#pragma unroll
        for (int o = 16; o > 0; o >>= 1) {
            ps += __shfl_xor_sync(0xffffffffu, ps, o);
            pd += __shfl_xor_sync(0xffffffffu, pd, o);
        }
        if (lane == 0) { as_o[nid[i]] = ps; ad_o[nid[i]] = pd; }
    }
}

// --------------------------- GEMM, C = 16 (layer 3) ------------------------
__global__ void gemm16_kernel(const float* __restrict__ in,
                              const float* __restrict__ W,
                              const float* __restrict__ a_s,
                              const float* __restrict__ a_d,
                              __half* __restrict__ h,
                              float* __restrict__ as_o,
                              float* __restrict__ ad_o, int n) {
    int t = blockIdx.x * blockDim.x + threadIdx.x;
    int node = t >> 4;
    int c = t & 15;
    if (node >= n) return;

    const float* row = in + (size_t)node * HID;
    float acc = 0.f;
#pragma unroll 8
    for (int k = 0; k < HID; k++)
        acc = fmaf(__ldg(row + k), __ldg(W + k * NC + c), acc);

    h[(size_t)node * NC + c] = __float2half_rn(acc);
    float ps = acc * a_s[c];
    float pd = acc * a_d[c];
#pragma unroll
    for (int o = 8; o > 0; o >>= 1) {
        ps += __shfl_xor_sync(0xffffffffu, ps, o, 16);
        pd += __shfl_xor_sync(0xffffffffu, pd, o, 16);
    }
    if (c == 0) { as_o[node] = ps; ad_o[node] = pd; }
}

// ------------------ fused online-softmax aggregation, C=128 -----------------
// warp per dst node; lane owns 4 cols. 4-edge chunks: all loads issued up
// front (MLP ~12), then sequential online-softmax updates.
__global__ void fused_aggr128_kernel(const int* __restrict__ rowptr,
                                     const int* __restrict__ col,
                                     const float* __restrict__ as_v,
                                     const float* __restrict__ ad_v,
                                     const __half* __restrict__ h,
                                     const float* __restrict__ bias,
                                     float* __restrict__ out, int n) {
    int node = (blockIdx.x * blockDim.x + threadIdx.x) >> 5;
    if (node >= n) return;
    int lane = threadIdx.x & 31;

    float advv = __ldg(ad_v + node);
    int beg = __ldg(rowptr + node);
    int end = __ldg(rowptr + node + 1);

    const float NEG_INF = __int_as_float(0xFF800000);
    float m = NEG_INF, den = 0.0f;
    float4 acc = make_float4(0.f, 0.f, 0.f, 0.f);

    for (int i = beg; i < end; i += 4) {
        int   sb[4];
        float eb[4];
        uint2 hb[4];
        // issue all independent loads for the chunk
#pragma unroll
        for (int j = 0; j < 4; j++) {
            bool act = (i + j) < end;
            sb[j] = __ldg(col + (act ? i + j : beg));
        }
#pragma unroll
        for (int j = 0; j < 4; j++) {
            bool act = (i + j) < end;
            float e = act ? (__ldg(as_v + sb[j]) + advv) : NEG_INF;
            eb[j] = e > 0.f ? e : 0.2f * e;     // leaky(−inf)=−inf
            hb[j] = *(const uint2*)(h + (size_t)sb[j] * HID + lane * 4);
        }
        // sequential online-softmax update
#pragma unroll
        for (int j = 0; j < 4; j++) {
            float e = eb[j];
            float nm = fmaxf(m, e);             // first edge always active
            float scale = __expf(m - nm);
            float wgt   = __expf(e - nm);       // inactive: exp(-inf-nm)=0
            __half2 h0 = *(__half2*)&hb[j].x;
            __half2 h1 = *(__half2*)&hb[j].y;
            float2 f0 = __half22float2(h0);
            float2 f1 = __half22float2(h1);
            den = den * scale + wgt;
            acc.x = fmaf(acc.x, scale, wgt * f0.x);
            acc.y = fmaf(acc.y, scale, wgt * f0.y);
            acc.z = fmaf(acc.z, scale, wgt * f1.x);
            acc.w = fmaf(acc.w, scale, wgt * f1.y);
            m = nm;
        }
    }

    float inv = 1.0f / den;
    float4 bv = *(const float4*)(bias + lane * 4);
    float4 o;
    o.x = fmaxf(fmaf(acc.x, inv, bv.x), 0.f);
    o.y = fmaxf(fmaf(acc.y, inv, bv.y), 0.f);
    o.z = fmaxf(fmaf(acc.z, inv, bv.z), 0.f);
    o.w = fmaxf(fmaf(acc.w, inv, bv.w), 0.f);
    *(float4*)(out + (size_t)node * HID + lane * 4) = o;
}

// ------------- fused aggregation C=16 + pooling epilogue (layer 3) ----------
// half-warp per node; lane owns 1 col; also accumulates graph node counts.
__global__ void fused_aggr16_pool_kernel(const int* __restrict__ rowptr,
                                         const int* __restrict__ col,
                                         const float* __restrict__ as_v,
                                         const float* __restrict__ ad_v,
                                         const __half* __restrict__ h,
                                         const float* __restrict__ bias,
                                         const int* __restrict__ batch,
                                         float* __restrict__ pool,
                                         float* __restrict__ cnt, int n) {
    int w = (blockIdx.x * blockDim.x + threadIdx.x) >> 5;
    int lane = threadIdx.x & 31;
    int node = w * 2 + (lane >> 4);
    int c = lane & 15;
    bool active = node < n;

    float advv = active ? __ldg(ad_v + node) : 0.f;
    int beg = active ? __ldg(rowptr + node) : 0;
    int end = active ? __ldg(rowptr + node + 1) : 0;

    const float NEG_INF = __int_as_float(0xFF800000);
    float m = NEG_INF, den = 0.0f, acc = 0.0f;

    for (int i = beg; i < end; i += 4) {
        int   sb[4];
        float eb[4];
        float hb[4];
#pragma unroll
        for (int j = 0; j < 4; j++) {
            bool act = (i + j) < end;
            sb[j] = __ldg(col + (act ? i + j : beg));
        }
#pragma unroll
        for (int j = 0; j < 4; j++) {
            bool act = (i + j) < end;
            float e = act ? (__ldg(as_v + sb[j]) + advv) : NEG_INF;
            eb[j] = e > 0.f ? e : 0.2f * e;
            hb[j] = __half2float(__ldg(h + (size_t)sb[j] * NC + c));
        }
#pragma unroll
        for (int j = 0; j < 4; j++) {
            float e = eb[j];
            float nm = fmaxf(m, e);
            float scale = __expf(m - nm);
            float wgt   = __expf(e - nm);
            den = den * scale + wgt;
            acc = fmaf(acc, scale, wgt * hb[j]);
            m = nm;
        }
    }

    if (active) {
        float val = fmaxf(acc / den + __ldg(bias + c), 0.f);
        int g = __ldg(batch + node);
        atomicAdd(&pool[g * NC + c], val);
        if (c == 0) atomicAdd(&cnt[g], 1.0f);
    }
}

__global__ void finalize_kernel(const float* __restrict__ pool,
                                const float* __restrict__ cnt,
                                float* __restrict__ outp) {
    int t = blockIdx.x * blockDim.x + threadIdx.x;
    if (t >= NG * NC) return;
    int g = t >> 4;
    float v = pool[t] / fmaxf(cnt[g], 1.0f);
    outp[t] = 1.0f / (1.0f + expf(-v));
}

// ---------------------------------------------------------------------------

extern "C" void kernel_launch(void* const* d_in, const int* in_sizes, int n_in,
                              void* d_out, int out_size) {
    const float* x     = (const float*)d_in[0];
    const int*   ei    = (const int*)  d_in[1];
    const int*   batch = (const int*)  d_in[3];
    const float* W1  = (const float*)d_in[4];
    const float* as1 = (const float*)d_in[5];
    const float* ad1 = (const float*)d_in[6];
    const float* b1  = (const float*)d_in[7];
    const float* W2  = (const float*)d_in[8];
    const float* as2 = (const float*)d_in[9];
    const float* ad2 = (const float*)d_in[10];
    const float* b2  = (const float*)d_in[11];
    const float* W3  = (const float*)d_in[12];
    const float* as3 = (const float*)d_in[13];
    const float* ad3 = (const float*)d_in[14];
    const float* b3  = (const float*)d_in[15];
    float* out = (float*)d_out;

    int n    = in_sizes[0] / 11;
    int E    = in_sizes[1] / 2;
    int Etot = E + n;
    const int* src = ei;
    const int* dst = ei + E;

    float *pA, *pB, *pas, *pad, *ppool, *pcnt;
    __half* ph;
    int *pdeg, *prow, *pcur, *pcol;
    cudaGetSymbolAddress((void**)&pA,    g_A);
    cudaGetSymbolAddress((void**)&pB,    g_B);
    cudaGetSymbolAddress((void**)&ph,    g_h);
    cudaGetSymbolAddress((void**)&pas,   g_as);
    cudaGetSymbolAddress((void**)&pad,   g_ad);
    cudaGetSymbolAddress((void**)&ppool, g_pool);
    cudaGetSymbolAddress((void**)&pcnt,  g_cnt);
    cudaGetSymbolAddress((void**)&pdeg,  g_deg);
    cudaGetSymbolAddress((void**)&prow,  g_rowptr);
    cudaGetSymbolAddress((void**)&pcur,  g_cursor);
    cudaGetSymbolAddress((void**)&pcol,  g_col);

    const int TB = 256;
    int gN       = (n + TB - 1) / TB;
    int gEdge    = (Etot + TB - 1) / TB;
    int warps128 = (n + 7) / 8;
    int gGemm128 = (warps128 * 32 + TB - 1) / TB;
    int gGemm16  = (n * NC + TB - 1) / TB;
    int gAggr128 = (n * 32 + TB - 1) / TB;
    int gAggr16  = (((n + 1) / 2) * 32 + TB - 1) / TB;
    int gPool    = (NG * NC + TB - 1) / TB;

    // ---- CSR build ----
    zero_deg_kernel<<<gN, TB>>>(pdeg, n, ppool, pcnt);
    count_deg_kernel<<<gEdge, TB>>>(dst, E, Etot, pdeg);
    scan_kernel<<<1, 1024>>>(pdeg, prow, pcur, n);
    scatter_kernel<<<gEdge, TB>>>(src, dst, E, Etot, pcur, pcol);

    // ---- layer 1 ----
    gemm128_kernel<<<gGemm128, TB>>>(x, 11, W1, as1, ad1, ph, pas, pad, n);
    fused_aggr128_kernel<<<gAggr128, TB>>>(prow, pcol, pas, pad, ph, b1, pA, n);

    // ---- layer 2 ----
    gemm128_kernel<<<gGemm128, TB>>>(pA, HID, W2, as2, ad2, ph, pas, pad, n);
    fused_aggr128_kernel<<<gAggr128, TB>>>(prow, pcol, pas, pad, ph, b2, pB, n);

    // ---- layer 3 + pooling ----
    gemm16_kernel<<<gGemm16, TB>>>(pB, W3, as3, ad3, ph, pas, pad, n);
    fused_aggr16_pool_kernel<<<gAggr16, TB>>>(prow, pcol, pas, pad, ph, b3, batch,
                                              ppool, pcnt, n);
    finalize_kernel<<<gPool, TB>>>(ppool, pcnt, out);
}

// round 5
// speedup vs baseline: 1.7108x; 1.0537x over previous
#include <cuda_runtime.h>
#include <cuda_fp16.h>
#include <mma.h>
#include <math.h>
#include <stdint.h>

using namespace nvcuda;

// ---------------------------------------------------------------------------
// GAT (3 layers) + mean pool + sigmoid.
// CSR grouped by dst + fused online-softmax aggregation.
// Layer-2 GEMM on tensor cores (wmma fp16, fp32 accum).
// ---------------------------------------------------------------------------

#define NMAX   50000
#define NPAD   50048            // multiple of 128 for wmma tiling
#define EMAX   800000
#define ETOTMX (EMAX + NMAX)
#define HID    128
#define NC     16
#define NG     64

__device__ __align__(16) __half g_A[NPAD * HID];   // aggr out L1 (fp16, wmma input)
__device__ __align__(16) __half g_B[NPAD * HID];   // aggr out L2 (fp16, gemm16 input)
__device__ __align__(16) __half g_h[NMAX * HID];   // transformed features (fp16)
__device__ __align__(16) float  g_hf[NPAD * HID];  // wmma fp32 output staging
__device__ __align__(16) __half g_Wh[HID * HID];   // W2 in fp16
__device__ float  g_as[NMAX];
__device__ float  g_ad[NMAX];
__device__ float  g_pool[NG * NC];
__device__ float  g_cnt[NG];
__device__ int    g_deg[NMAX];
__device__ int    g_rowptr[NMAX + 1];
__device__ int    g_cursor[NMAX];
__device__ int    g_col[ETOTMX];

// --------------------------- CSR build --------------------------------------

__global__ void zero_deg_kernel(int* __restrict__ deg, int n,
                                float* __restrict__ pool, float* __restrict__ cnt) {
    int i = blockIdx.x * blockDim.x + threadIdx.x;
    if (i < n) deg[i] = 0;
    if (i < NG * NC) pool[i] = 0.f;
    if (i < NG) cnt[i] = 0.f;
}

// 4 edges per thread: batch loads, then batch atomics (raise MLP)
__global__ void count_deg_kernel(const int* __restrict__ dst, int E, int Etot,
                                 int* __restrict__ deg) {
    int t = (blockIdx.x * blockDim.x + threadIdx.x) * 4;
    int d[4];
#pragma unroll
    for (int j = 0; j < 4; j++) {
        int i = t + j;
        d[j] = (i < Etot) ? (i < E ? __ldg(dst + i) : (i - E)) : -1;
    }
#pragma unroll
    for (int j = 0; j < 4; j++)
        if (d[j] >= 0) atomicAdd(&deg[d[j]], 1);
}

__global__ void scan_kernel(const int* __restrict__ deg, int* __restrict__ rowptr,
                            int* __restrict__ cursor, int n) {
    __shared__ int s_carry;
    __shared__ int warp_sums[32];
    int lane = threadIdx.x & 31, wid = threadIdx.x >> 5;
    if (threadIdx.x == 0) { s_carry = 0; rowptr[0] = 0; }
    __syncthreads();
    for (int base = 0; base < n; base += 1024) {
        int i = base + (int)threadIdx.x;
        int v = i < n ? deg[i] : 0;
        int x = v;
#pragma unroll
        for (int o = 1; o < 32; o <<= 1) {
            int t = __shfl_up_sync(0xffffffffu, x, o);
            if (lane >= o) x += t;
        }
        if (lane == 31) warp_sums[wid] = x;
        __syncthreads();
        if (wid == 0) {
            int s = warp_sums[lane];
#pragma unroll
            for (int o = 1; o < 32; o <<= 1) {
                int t = __shfl_up_sync(0xffffffffu, s, o);
                if (lane >= o) s += t;
            }
            warp_sums[lane] = s;
        }
        __syncthreads();
        int incl = x + (wid > 0 ? warp_sums[wid - 1] : 0) + s_carry;
        if (i < n) { rowptr[i + 1] = incl; cursor[i] = incl - v; }
        __syncthreads();
        if (threadIdx.x == 1023) s_carry = incl;
        __syncthreads();
    }
}

__global__ void scatter_kernel(const int* __restrict__ src, const int* __restrict__ dst,
                               int E, int Etot,
                               int* __restrict__ cursor, int* __restrict__ col) {
    int t = (blockIdx.x * blockDim.x + threadIdx.x) * 4;
    int s[4], d[4];
#pragma unroll
    for (int j = 0; j < 4; j++) {
        int i = t + j;
        bool act = i < Etot;
        s[j] = act ? (i < E ? __ldg(src + i) : (i - E)) : 0;
        d[j] = act ? (i < E ? __ldg(dst + i) : (i - E)) : -1;
    }
#pragma unroll
    for (int j = 0; j < 4; j++) {
        if (d[j] >= 0) {
            int pos = atomicAdd(&cursor[d[j]], 1);
            col[pos] = s[j];
        }
    }
}

// --------------------------- layer-1 GEMM (K=11, FFMA) ----------------------
__global__ void gemm128_kernel(const float* __restrict__ in, int K,
                               const float* __restrict__ W,
                               const float* __restrict__ a_s,
                               const float* __restrict__ a_d,
                               __half* __restrict__ h,
                               float* __restrict__ as_o,
                               float* __restrict__ ad_o, int n) {
    int w    = (blockIdx.x * blockDim.x + threadIdx.x) >> 5;
    int lane = threadIdx.x & 31;
    int node0 = w * 8;
    if (node0 >= n) return;

    int nid[8];
#pragma unroll
    for (int i = 0; i < 8; i++) {
        int nn = node0 + i;
        nid[i] = nn < n ? nn : (n - 1);
    }

    float4 acc[8];
#pragma unroll
    for (int i = 0; i < 8; i++) acc[i] = make_float4(0.f, 0.f, 0.f, 0.f);

    for (int k = 0; k < K; k++) {
        float4 wv = *(const float4*)(W + k * HID + lane * 4);
#pragma unroll
        for (int i = 0; i < 8; i++) {
            float a = __ldg(in + (size_t)nid[i] * K + k);
            acc[i].x = fmaf(a, wv.x, acc[i].x);
            acc[i].y = fmaf(a, wv.y, acc[i].y);
            acc[i].z = fmaf(a, wv.z, acc[i].z);
            acc[i].w = fmaf(a, wv.w, acc[i].w);
        }
    }

    float4 sv = *(const float4*)(a_s + lane * 4);
    float4 dv = *(const float4*)(a_d + lane * 4);

#pragma unroll
    for (int i = 0; i < 8; i++) {
        __half2 p0 = __floats2half2_rn(acc[i].x, acc[i].y);
        __half2 p1 = __floats2half2_rn(acc[i].z, acc[i].w);
        uint2 packed = make_uint2(*(unsigned*)&p0, *(unsigned*)&p1);
        *(uint2*)(h + (size_t)nid[i] * HID + lane * 4) = packed;

        float ps = acc[i].x * sv.x + acc[i].y * sv.y + acc[i].z * sv.z + acc[i].w * sv.w;
        float pd = acc[i].x * dv.x + acc[i].y * dv.y + acc[i].z * dv.z + acc[i].w * dv.w;
#pragma unroll
        for (int o = 16; o > 0; o >>= 1) {
            ps += __shfl_xor_sync(0xffffffffu, ps, o);
            pd += __shfl_xor_sync(0xffffffffu, pd, o);
        }
        if (lane == 0) { as_o[nid[i]] = ps; ad_o[nid[i]] = pd; }
    }
}

// --------------------------- layer-2 GEMM (wmma fp16) -----------------------
__global__ void convertW_kernel(const float* __restrict__ W, __half* __restrict__ Wh,
                                int total) {
    int i = blockIdx.x * blockDim.x + threadIdx.x;
    if (i < total) Wh[i] = __float2half_rn(W[i]);
}

__global__ __launch_bounds__(256) void wmma_gemm128_kernel(
        const __half* __restrict__ A,     // [NPAD,128] row-major
        const __half* __restrict__ Wh,    // [128,128] row-major
        float* __restrict__ C, int nPad) {
    int warp = threadIdx.x >> 5;
    int row0 = blockIdx.x * 128 + warp * 16;
    if (row0 >= nPad) return;

    wmma::fragment<wmma::accumulator, 16, 16, 16, float> acc[8];
#pragma unroll
    for (int i = 0; i < 8; i++) wmma::fill_fragment(acc[i], 0.f);

#pragma unroll
    for (int k = 0; k < 8; k++) {
        wmma::fragment<wmma::matrix_a, 16, 16, 16, __half, wmma::row_major> a;
        wmma::load_matrix_sync(a, A + (size_t)row0 * HID + k * 16, HID);
#pragma unroll
        for (int nt = 0; nt < 8; nt++) {
            wmma::fragment<wmma::matrix_b, 16, 16, 16, __half, wmma::row_major> b;
            wmma::load_matrix_sync(b, Wh + k * 16 * HID + nt * 16, HID);
            wmma::mma_sync(acc[nt], a, b, acc[nt]);
        }
    }
#pragma unroll
    for (int nt = 0; nt < 8; nt++)
        wmma::store_matrix_sync(C + (size_t)row0 * HID + nt * 16, acc[nt], HID,
                                wmma::mem_row_major);
}

// epilogue: hf32 -> h fp16, alpha dots. warp per node.
__global__ void epi128_kernel(const float* __restrict__ hf,
                              const float* __restrict__ a_s,
                              const float* __restrict__ a_d,
                              __half* __restrict__ h,
                              float* __restrict__ as_o,
                              float* __restrict__ ad_o, int n) {
    int node = (blockIdx.x * blockDim.x + threadIdx.x) >> 5;
    if (node >= n) return;
    int lane = threadIdx.x & 31;
    float4 v = *(const float4*)(hf + (size_t)node * HID + lane * 4);
    float4 sv = *(const float4*)(a_s + lane * 4);
    float4 dv = *(const float4*)(a_d + lane * 4);
    __half2 p0 = __floats2half2_rn(v.x, v.y);
    __half2 p1 = __floats2half2_rn(v.z, v.w);
    uint2 packed = make_uint2(*(unsigned*)&p0, *(unsigned*)&p1);
    *(uint2*)(h + (size_t)node * HID + lane * 4) = packed;
    float ps = v.x * sv.x + v.y * sv.y + v.z * sv.z + v.w * sv.w;
    float pd = v.x * dv.x + v.y * dv.y + v.z * dv.z + v.w * dv.w;
#pragma unroll
    for (int o = 16; o > 0; o >>= 1) {
        ps += __shfl_xor_sync(0xffffffffu, ps, o);
        pd += __shfl_xor_sync(0xffffffffu, pd, o);
    }
    if (lane == 0) { as_o[node] = ps; ad_o[node] = pd; }
}

// --------------------------- layer-3 GEMM (fp16 in, C=16) -------------------
__global__ void gemm16_kernel(const __half* __restrict__ in,
                              const float* __restrict__ W,
                              const float* __restrict__ a_s,
                              const float* __restrict__ a_d,
                              __half* __restrict__ h,
                              float* __restrict__ as_o,
                              float* __restrict__ ad_o, int n) {
    int t = blockIdx.x * blockDim.x + threadIdx.x;
    int node = t >> 4;
    int c = t & 15;
    if (node >= n) return;

    const __half* row = in + (size_t)node * HID;
    float acc = 0.f;
#pragma unroll 8
    for (int k = 0; k < HID; k++)
        acc = fmaf(__half2float(__ldg(row + k)), __ldg(W + k * NC + c), acc);

    h[(size_t)node * NC + c] = __float2half_rn(acc);
    float ps = acc * a_s[c];
    float pd = acc * a_d[c];
#pragma unroll
    for (int o = 8; o > 0; o >>= 1) {
        ps += __shfl_xor_sync(0xffffffffu, ps, o, 16);
        pd += __shfl_xor_sync(0xffffffffu, pd, o, 16);
    }
    if (c == 0) { as_o[node] = ps; ad_o[node] = pd; }
}

// ------------------ fused online-softmax aggregation, C=128 -----------------
// warp per dst node; lane owns 4 cols; 8-edge chunks (MLP ~24). fp16 output.
__global__ void fused_aggr128_kernel(const int* __restrict__ rowptr,
                                     const int* __restrict__ col,
                                     const float* __restrict__ as_v,
                                     const float* __restrict__ ad_v,
                                     const __half* __restrict__ h,
                                     const float* __restrict__ bias,
                                     __half* __restrict__ out, int n) {
    int node = (blockIdx.x * blockDim.x + threadIdx.x) >> 5;
    if (node >= n) return;
    int lane = threadIdx.x & 31;

    float advv = __ldg(ad_v + node);
    int beg = __ldg(rowptr + node);
    int end = __ldg(rowptr + node + 1);

    const float NEG_INF = __int_as_float(0xFF800000);
    float m = NEG_INF, den = 0.0f;
    float4 acc = make_float4(0.f, 0.f, 0.f, 0.f);

    for (int i = beg; i < end; i += 8) {
        int   sb[8];
        float eb[8];
        uint2 hb[8];
#pragma unroll
        for (int j = 0; j < 8; j++) {
            bool act = (i + j) < end;
            sb[j] = __ldg(col + (act ? i + j : beg));
        }
#pragma unroll
        for (int j = 0; j < 8; j++) {
            bool act = (i + j) < end;
            float e = act ? (__ldg(as_v + sb[j]) + advv) : NEG_INF;
            eb[j] = e > 0.f ? e : 0.2f * e;
            hb[j] = *(const uint2*)(h + (size_t)sb[j] * HID + lane * 4);
        }
#pragma unroll
        for (int j = 0; j < 8; j++) {
            float e = eb[j];
            float nm = fmaxf(m, e);
            float scale = __expf(m - nm);
            float wgt   = __expf(e - nm);
            __half2 h0 = *(__half2*)&hb[j].x;
            __half2 h1 = *(__half2*)&hb[j].y;
            float2 f0 = __half22float2(h0);
            float2 f1 = __half22float2(h1);
            den = den * scale + wgt;
            acc.x = fmaf(acc.x, scale, wgt * f0.x);
            acc.y = fmaf(acc.y, scale, wgt * f0.y);
            acc.z = fmaf(acc.z, scale, wgt * f1.x);
            acc.w = fmaf(acc.w, scale, wgt * f1.y);
            m = nm;
        }
    }

    float inv = 1.0f / den;
    float4 bv = *(const float4*)(bias + lane * 4);
    float ox = fmaxf(fmaf(acc.x, inv, bv.x), 0.f);
    float oy = fmaxf(fmaf(acc.y, inv, bv.y), 0.f);
    float oz = fmaxf(fmaf(acc.z, inv, bv.z), 0.f);
    float ow = fmaxf(fmaf(acc.w, inv, bv.w), 0.f);
    __half2 p0 = __floats2half2_rn(ox, oy);
    __half2 p1 = __floats2half2_rn(oz, ow);
    uint2 packed = make_uint2(*(unsigned*)&p0, *(unsigned*)&p1);
    *(uint2*)(out + (size_t)node * HID + lane * 4) = packed;
}

// ------------- fused aggregation C=16 + pooling (layer 3) -------------------
__global__ void fused_aggr16_pool_kernel(const int* __restrict__ rowptr,
                                         const int* __restrict__ col,
                                         const float* __restrict__ as_v,
                                         const float* __restrict__ ad_v,
                                         const __half* __restrict__ h,
                                         const float* __restrict__ bias,
                                         const int* __restrict__ batch,
                                         float* __restrict__ pool,
                                         float* __restrict__ cnt, int n) {
    int w = (blockIdx.x * blockDim.x + threadIdx.x) >> 5;
    int lane = threadIdx.x & 31;
    int node = w * 2 + (lane >> 4);
    int c = lane & 15;
    bool active = node < n;

    float advv = active ? __ldg(ad_v + node) : 0.f;
    int beg = active ? __ldg(rowptr + node) : 0;
    int end = active ? __ldg(rowptr + node + 1) : 0;

    const float NEG_INF = __int_as_float(0xFF800000);
    float m = NEG_INF, den = 0.0f, acc = 0.0f;

    for (int i = beg; i < end; i += 8) {
        int   sb[8];
        float eb[8];
        float hb[8];
#pragma unroll
        for (int j = 0; j < 8; j++) {
            bool act = (i + j) < end;
            sb[j] = __ldg(col + (act ? i + j : beg));
        }
#pragma unroll
        for (int j = 0; j < 8; j++) {
            bool act = (i + j) < end;
            float e = act ? (__ldg(as_v + sb[j]) + advv) : NEG_INF;
            eb[j] = e > 0.f ? e : 0.2f * e;
            hb[j] = __half2float(__ldg(h + (size_t)sb[j] * NC + c));
        }
#pragma unroll
        for (int j = 0; j < 8; j++) {
            float e = eb[j];
            float nm = fmaxf(m, e);
            float scale = __expf(m - nm);
            float wgt   = __expf(e - nm);
            den = den * scale + wgt;
            acc = fmaf(acc, scale, wgt * hb[j]);
            m = nm;
        }
    }

    if (active) {
        float val = fmaxf(acc / den + __ldg(bias + c), 0.f);
        int g = __ldg(batch + node);
        atomicAdd(&pool[g * NC + c], val);
        if (c == 0) atomicAdd(&cnt[g], 1.0f);
    }
}

__global__ void finalize_kernel(const float* __restrict__ pool,
                                const float* __restrict__ cnt,
                                float* __restrict__ outp) {
    int t = blockIdx.x * blockDim.x + threadIdx.x;
    if (t >= NG * NC) return;
    int g = t >> 4;
    float v = pool[t] / fmaxf(cnt[g], 1.0f);
    outp[t] = 1.0f / (1.0f + expf(-v));
}

// ---------------------------------------------------------------------------

extern "C" void kernel_launch(void* const* d_in, const int* in_sizes, int n_in,
                              void* d_out, int out_size) {
    const float* x     = (const float*)d_in[0];
    const int*   ei    = (const int*)  d_in[1];
    const int*   batch = (const int*)  d_in[3];
    const float* W1  = (const float*)d_in[4];
    const float* as1 = (const float*)d_in[5];
    const float* ad1 = (const float*)d_in[6];
    const float* b1  = (const float*)d_in[7];
    const float* W2  = (const float*)d_in[8];
    const float* as2 = (const float*)d_in[9];
    const float* ad2 = (const float*)d_in[10];
    const float* b2  = (const float*)d_in[11];
    const float* W3  = (const float*)d_in[12];
    const float* as3 = (const float*)d_in[13];
    const float* ad3 = (const float*)d_in[14];
    const float* b3  = (const float*)d_in[15];
    float* out = (float*)d_out;

    int n    = in_sizes[0] / 11;
    int E    = in_sizes[1] / 2;
    int Etot = E + n;
    const int* src = ei;
    const int* dst = ei + E;

    float *phf, *pas, *pad, *ppool, *pcnt;
    __half *pA, *pB, *ph, *pWh;
    int *pdeg, *prow, *pcur, *pcol;
    cudaGetSymbolAddress((void**)&pA,    g_A);
    cudaGetSymbolAddress((void**)&pB,    g_B);
    cudaGetSymbolAddress((void**)&ph,    g_h);
    cudaGetSymbolAddress((void**)&phf,   g_hf);
    cudaGetSymbolAddress((void**)&pWh,   g_Wh);
    cudaGetSymbolAddress((void**)&pas,   g_as);
    cudaGetSymbolAddress((void**)&pad,   g_ad);
    cudaGetSymbolAddress((void**)&ppool, g_pool);
    cudaGetSymbolAddress((void**)&pcnt,  g_cnt);
    cudaGetSymbolAddress((void**)&pdeg,  g_deg);
    cudaGetSymbolAddress((void**)&prow,  g_rowptr);
    cudaGetSymbolAddress((void**)&pcur,  g_cursor);
    cudaGetSymbolAddress((void**)&pcol,  g_col);

    const int TB = 256;
    int nPad     = (n + 127) & ~127;
    int gN       = (n + TB - 1) / TB;
    int gEdge4   = (Etot + TB * 4 - 1) / (TB * 4);
    int warps128 = (n + 7) / 8;
    int gGemm128 = (warps128 * 32 + TB - 1) / TB;
    int gWmma    = nPad / 128;
    int gNodeWarp= (n * 32 + TB - 1) / TB;
    int gGemm16  = (n * NC + TB - 1) / TB;
    int gAggr16  = (((n + 1) / 2) * 32 + TB - 1) / TB;
    int gPool    = (NG * NC + TB - 1) / TB;

    // ---- CSR build + W2 conversion ----
    zero_deg_kernel<<<gN, TB>>>(pdeg, n, ppool, pcnt);
    convertW_kernel<<<(HID * HID + TB - 1) / TB, TB>>>(W2, pWh, HID * HID);
    count_deg_kernel<<<gEdge4, TB>>>(dst, E, Etot, pdeg);
    scan_kernel<<<1, 1024>>>(pdeg, prow, pcur, n);
    scatter_kernel<<<gEdge4, TB>>>(src, dst, E, Etot, pcur, pcol);

    // ---- layer 1 (FFMA GEMM, K=11) ----
    gemm128_kernel<<<gGemm128, TB>>>(x, 11, W1, as1, ad1, ph, pas, pad, n);
    fused_aggr128_kernel<<<gNodeWarp, TB>>>(prow, pcol, pas, pad, ph, b1, pA, n);

    // ---- layer 2 (tensor-core GEMM) ----
    wmma_gemm128_kernel<<<gWmma, 256>>>(pA, pWh, phf, nPad);
    epi128_kernel<<<gNodeWarp, TB>>>(phf, as2, ad2, ph, pas, pad, n);
    fused_aggr128_kernel<<<gNodeWarp, TB>>>(prow, pcol, pas, pad, ph, b2, pB, n);

    // ---- layer 3 + pooling ----
    gemm16_kernel<<<gGemm16, TB>>>(pB, W3, as3, ad3, ph, pas, pad, n);
    fused_aggr16_pool_kernel<<<gAggr16, TB>>>(prow, pcol, pas, pad, ph, b3, batch,
                                              ppool, pcnt, n);
    finalize_kernel<<<gPool, TB>>>(ppool, pcnt, out);
}

// round 6
// speedup vs baseline: 1.9035x; 1.1126x over previous
#include <cuda_runtime.h>
#include <cuda_fp16.h>
#include <mma.h>
#include <math.h>
#include <stdint.h>

using namespace nvcuda;

// ---------------------------------------------------------------------------
// GAT (3 layers) + mean pool + sigmoid.
// CSR grouped by dst + fused online-softmax aggregation.
// Layer-2 GEMM on tensor cores (wmma fp16, fp32 accum) with fused epilogue.
// Multi-block CSR scan (was the single-block bottleneck: 49.5us).
// ---------------------------------------------------------------------------

#define NMAX   50000
#define NPAD   50048            // multiple of 128
#define EMAX   800000
#define ETOTMX (EMAX + NMAX)
#define HID    128
#define NC     16
#define NG     64
#define SCAN_CHUNK 1024         // elements per scan block

__device__ __align__(16) __half g_A[NPAD * HID];   // aggr out L1 (fp16, wmma in)
__device__ __align__(16) __half g_B[NPAD * HID];   // aggr out L2 (fp16)
__device__ __align__(16) __half g_h[NMAX * HID];   // transformed features (fp16)
__device__ __align__(16) __half g_Wh[HID * HID];   // W2 fp16
__device__ float  g_as[NMAX];
__device__ float  g_ad[NMAX];
__device__ float  g_pool[NG * NC];
__device__ float  g_cnt[NG];
__device__ int    g_deg[NMAX];
__device__ int    g_rowptr[NMAX + 1];
__device__ int    g_cursor[NMAX];
__device__ int    g_partial[128];                  // scan block partials
__device__ int    g_col[ETOTMX];

// --------------------------- CSR build --------------------------------------

__global__ void zero_deg_kernel(int* __restrict__ deg, int n,
                                float* __restrict__ pool, float* __restrict__ cnt) {
    int i = blockIdx.x * blockDim.x + threadIdx.x;
    if (i < n) deg[i] = 0;
    if (i < NG * NC) pool[i] = 0.f;
    if (i < NG) cnt[i] = 0.f;
}

__global__ void count_deg_kernel(const int* __restrict__ dst, int E, int Etot,
                                 int* __restrict__ deg) {
    int t = (blockIdx.x * blockDim.x + threadIdx.x) * 4;
    int d[4];
#pragma unroll
    for (int j = 0; j < 4; j++) {
        int i = t + j;
        d[j] = (i < Etot) ? (i < E ? __ldg(dst + i) : (i - E)) : -1;
    }
#pragma unroll
    for (int j = 0; j < 4; j++)
        if (d[j] >= 0) atomicAdd(&deg[d[j]], 1);
}

// ---- 3-phase multi-block scan ----
// phase 1: per-block (1024 elems) sums
__global__ void scan_partial_kernel(const int* __restrict__ deg,
                                    int* __restrict__ partial, int n) {
    __shared__ int ws[8];
    int base = blockIdx.x * SCAN_CHUNK + threadIdx.x * 4;
    int s = 0;
#pragma unroll
    for (int j = 0; j < 4; j++) {
        int i = base + j;
        if (i < n) s += __ldg(deg + i);
    }
#pragma unroll
    for (int o = 16; o > 0; o >>= 1) s += __shfl_xor_sync(0xffffffffu, s, o);
    int lane = threadIdx.x & 31, wid = threadIdx.x >> 5;
    if (lane == 0) ws[wid] = s;
    __syncthreads();
    if (wid == 0 && lane < 8) {
        int v = ws[lane];
#pragma unroll
        for (int o = 4; o > 0; o >>= 1) v += __shfl_xor_sync(0xffu, v, o);
        if (lane == 0) partial[blockIdx.x] = v;
    }
}

// phase 2: exclusive scan of block partials (nb <= 64), one block of 64
__global__ void scan_offsets_kernel(int* __restrict__ partial, int nb) {
    __shared__ int tmp[64];
    int t = threadIdx.x;
    int v = t < nb ? partial[t] : 0;
    tmp[t] = v;
    __syncthreads();
#pragma unroll
    for (int o = 1; o < 64; o <<= 1) {
        int u = (t >= o) ? tmp[t - o] : 0;
        __syncthreads();
        tmp[t] += u;
        __syncthreads();
    }
    if (t < nb) partial[t] = tmp[t] - v;   // exclusive
}

// phase 3: local scan + block offset -> rowptr, cursor
__global__ void scan_final_kernel(const int* __restrict__ deg,
                                  const int* __restrict__ partial,
                                  int* __restrict__ rowptr,
                                  int* __restrict__ cursor, int n) {
    __shared__ int ws[8];
    int t = threadIdx.x, lane = t & 31, wid = t >> 5;
    int base = blockIdx.x * SCAN_CHUNK + t * 4;
    int v[4];
#pragma unroll
    for (int j = 0; j < 4; j++) {
        int i = base + j;
        v[j] = (i < n) ? __ldg(deg + i) : 0;
    }
    int tot = v[0] + v[1] + v[2] + v[3];
    int x = tot;
#pragma unroll
    for (int o = 1; o < 32; o <<= 1) {
        int u = __shfl_up_sync(0xffffffffu, x, o);
        if (lane >= o) x += u;
    }
    int warp_excl = x - tot;
    if (lane == 31) ws[wid] = x;
    __syncthreads();
    if (wid == 0) {
        int val = (lane < 8) ? ws[lane] : 0;
#pragma unroll
        for (int o = 1; o < 8; o <<= 1) {
            int u = __shfl_up_sync(0xffffffffu, val, o);
            if (lane >= o) val += u;
        }
        if (lane < 8) ws[lane] = val;      // inclusive warp totals
    }
    __syncthreads();
    int off = __ldg(partial + blockIdx.x) + (wid > 0 ? ws[wid - 1] : 0) + warp_excl;
    int run = off;
#pragma unroll
    for (int j = 0; j < 4; j++) {
        run += v[j];
        int i = base + j;
        if (i < n) { rowptr[i + 1] = run; cursor[i] = run - v[j]; }
    }
    if (blockIdx.x == 0 && t == 0) rowptr[0] = 0;
}

__global__ void scatter_kernel(const int* __restrict__ src, const int* __restrict__ dst,
                               int E, int Etot,
                               int* __restrict__ cursor, int* __restrict__ col) {
    int t = (blockIdx.x * blockDim.x + threadIdx.x) * 4;
    int s[4], d[4];
#pragma unroll
    for (int j = 0; j < 4; j++) {
        int i = t + j;
        bool act = i < Etot;
        s[j] = act ? (i < E ? __ldg(src + i) : (i - E)) : 0;
        d[j] = act ? (i < E ? __ldg(dst + i) : (i - E)) : -1;
    }
#pragma unroll
    for (int j = 0; j < 4; j++) {
        if (d[j] >= 0) {
            int pos = atomicAdd(&cursor[d[j]], 1);
            col[pos] = s[j];
        }
    }
}

// --------------------------- layer-1 GEMM (K=11, FFMA) ----------------------
__global__ void gemm128_kernel(const float* __restrict__ in, int K,
                               const float* __restrict__ W,
                               const float* __restrict__ a_s,
                               const float* __restrict__ a_d,
                               __half* __restrict__ h,
                               float* __restrict__ as_o,
                               float* __restrict__ ad_o, int n) {
    int w    = (blockIdx.x * blockDim.x + threadIdx.x) >> 5;
    int lane = threadIdx.x & 31;
    int node0 = w * 8;
    if (node0 >= n) return;

    int nid[8];
#pragma unroll
    for (int i = 0; i < 8; i++) {
        int nn = node0 + i;
        nid[i] = nn < n ? nn : (n - 1);
    }

    float4 acc[8];
#pragma unroll
    for (int i = 0; i < 8; i++) acc[i] = make_float4(0.f, 0.f, 0.f, 0.f);

    for (int k = 0; k < K; k++) {
        float4 wv = *(const float4*)(W + k * HID + lane * 4);
#pragma unroll
        for (int i = 0; i < 8; i++) {
            float a = __ldg(in + (size_t)nid[i] * K + k);
            acc[i].x = fmaf(a, wv.x, acc[i].x);
            acc[i].y = fmaf(a, wv.y, acc[i].y);
            acc[i].z = fmaf(a, wv.z, acc[i].z);
            acc[i].w = fmaf(a, wv.w, acc[i].w);
        }
    }

    float4 sv = *(const float4*)(a_s + lane * 4);
    float4 dv = *(const float4*)(a_d + lane * 4);

#pragma unroll
    for (int i = 0; i < 8; i++) {
        __half2 p0 = __floats2half2_rn(acc[i].x, acc[i].y);
        __half2 p1 = __floats2half2_rn(acc[i].z, acc[i].w);
        uint2 packed = make_uint2(*(unsigned*)&p0, *(unsigned*)&p1);
        *(uint2*)(h + (size_t)nid[i] * HID + lane * 4) = packed;

        float ps = acc[i].x * sv.x + acc[i].y * sv.y + acc[i].z * sv.z + acc[i].w * sv.w;
        float pd = acc[i].x * dv.x + acc[i].y * dv.y + acc[i].z * dv.z + acc[i].w * dv.w;
#pragma unroll
        for (int o = 16; o > 0; o >>= 1) {
            ps += __shfl_xor_sync(0xffffffffu, ps, o);
            pd += __shfl_xor_sync(0xffffffffu, pd, o);
        }
        if (lane == 0) { as_o[nid[i]] = ps; ad_o[nid[i]] = pd; }
    }
}

// --------------------------- layer-2 GEMM (wmma, fused epilogue) ------------
__global__ void convertW_kernel(const float* __restrict__ W, __half* __restrict__ Wh,
                                int total) {
    int i = blockIdx.x * blockDim.x + threadIdx.x;
    if (i < total) Wh[i] = __float2half_rn(W[i]);
}

// 128 threads (4 warps), 64 rows per block; epilogue via smem staging.
__global__ __launch_bounds__(128) void wmma_gemm128_fused_kernel(
        const __half* __restrict__ A,     // [NPAD,128] row-major
        const __half* __restrict__ Wh,    // [128,128] row-major
        const float* __restrict__ a_s,
        const float* __restrict__ a_d,
        __half* __restrict__ h,
        float* __restrict__ as_o,
        float* __restrict__ ad_o, int nPad, int n) {
    __shared__ float s_c[64 * HID];       // 32 KB
    int warp = threadIdx.x >> 5;
    int lane = threadIdx.x & 31;
    int row0 = blockIdx.x * 64 + warp * 16;
    if (row0 >= nPad) return;

    wmma::fragment<wmma::accumulator, 16, 16, 16, float> acc[8];
#pragma unroll
    for (int i = 0; i < 8; i++) wmma::fill_fragment(acc[i], 0.f);

#pragma unroll
    for (int k = 0; k < 8; k++) {
        wmma::fragment<wmma::matrix_a, 16, 16, 16, __half, wmma::row_major> a;
        wmma::load_matrix_sync(a, A + (size_t)row0 * HID + k * 16, HID);
#pragma unroll
        for (int nt = 0; nt < 8; nt++) {
            wmma::fragment<wmma::matrix_b, 16, 16, 16, __half, wmma::row_major> b;
            wmma::load_matrix_sync(b, Wh + k * 16 * HID + nt * 16, HID);
            wmma::mma_sync(acc[nt], a, b, acc[nt]);
        }
    }
    float* my = s_c + warp * 16 * HID;
#pragma unroll
    for (int nt = 0; nt < 8; nt++)
        wmma::store_matrix_sync(my + nt * 16, acc[nt], HID, wmma::mem_row_major);
    __syncwarp();

    float4 sv = *(const float4*)(a_s + lane * 4);
    float4 dv = *(const float4*)(a_d + lane * 4);
#pragma unroll
    for (int r = 0; r < 16; r++) {
        int row = row0 + r;
        if (row >= n) break;
        float4 v = *(const float4*)(my + r * HID + lane * 4);
        __half2 p0 = __floats2half2_rn(v.x, v.y);
        __half2 p1 = __floats2half2_rn(v.z, v.w);
        uint2 packed = make_uint2(*(unsigned*)&p0, *(unsigned*)&p1);
        *(uint2*)(h + (size_t)row * HID + lane * 4) = packed;
        float ps = v.x * sv.x + v.y * sv.y + v.z * sv.z + v.w * sv.w;
        float pd = v.x * dv.x + v.y * dv.y + v.z * dv.z + v.w * dv.w;
#pragma unroll
        for (int o = 16; o > 0; o >>= 1) {
            ps += __shfl_xor_sync(0xffffffffu, ps, o);
            pd += __shfl_xor_sync(0xffffffffu, pd, o);
        }
        if (lane == 0) { as_o[row] = ps; ad_o[row] = pd; }
    }
}

// --------------------------- layer-3 GEMM (fp16 in, C=16) -------------------
__global__ void gemm16_kernel(const __half* __restrict__ in,
                              const float* __restrict__ W,
                              const float* __restrict__ a_s,
                              const float* __restrict__ a_d,
                              __half* __restrict__ h,
                              float* __restrict__ as_o,
                              float* __restrict__ ad_o, int n) {
    int t = blockIdx.x * blockDim.x + threadIdx.x;
    int node = t >> 4;
    int c = t & 15;
    if (node >= n) return;

    const __half* row = in + (size_t)node * HID;
    float acc = 0.f;
#pragma unroll 8
    for (int k = 0; k < HID; k++)
        acc = fmaf(__half2float(__ldg(row + k)), __ldg(W + k * NC + c), acc);

    h[(size_t)node * NC + c] = __float2half_rn(acc);
    float ps = acc * a_s[c];
    float pd = acc * a_d[c];
#pragma unroll
    for (int o = 8; o > 0; o >>= 1) {
        ps += __shfl_xor_sync(0xffffffffu, ps, o, 16);
        pd += __shfl_xor_sync(0xffffffffu, pd, o, 16);
    }
    if (c == 0) { as_o[node] = ps; ad_o[node] = pd; }
}

// ------------------ fused online-softmax aggregation, C=128 -----------------
__global__ void fused_aggr128_kernel(const int* __restrict__ rowptr,
                                     const int* __restrict__ col,
                                     const float* __restrict__ as_v,
                                     const float* __restrict__ ad_v,
                                     const __half* __restrict__ h,
                                     const float* __restrict__ bias,
                                     __half* __restrict__ out, int n) {
    int node = (blockIdx.x * blockDim.x + threadIdx.x) >> 5;
    if (node >= n) return;
    int lane = threadIdx.x & 31;

    float advv = __ldg(ad_v + node);
    int beg = __ldg(rowptr + node);
    int end = __ldg(rowptr + node + 1);

    const float NEG_INF = __int_as_float(0xFF800000);
    float m = NEG_INF, den = 0.0f;
    float4 acc = make_float4(0.f, 0.f, 0.f, 0.f);

    for (int i = beg; i < end; i += 8) {
        int   sb[8];
        float eb[8];
        uint2 hb[8];
#pragma unroll
        for (int j = 0; j < 8; j++) {
            bool act = (i + j) < end;
            sb[j] = __ldg(col + (act ? i + j : beg));
        }
#pragma unroll
        for (int j = 0; j < 8; j++) {
            bool act = (i + j) < end;
            float e = act ? (__ldg(as_v + sb[j]) + advv) : NEG_INF;
            eb[j] = e > 0.f ? e : 0.2f * e;
            hb[j] = *(const uint2*)(h + (size_t)sb[j] * HID + lane * 4);
        }
#pragma unroll
        for (int j = 0; j < 8; j++) {
            float e = eb[j];
            float nm = fmaxf(m, e);
            float scale = __expf(m - nm);
            float wgt   = __expf(e - nm);
            __half2 h0 = *(__half2*)&hb[j].x;
            __half2 h1 = *(__half2*)&hb[j].y;
            float2 f0 = __half22float2(h0);
            float2 f1 = __half22float2(h1);
            den = den * scale + wgt;
            acc.x = fmaf(acc.x, scale, wgt * f0.x);
            acc.y = fmaf(acc.y, scale, wgt * f0.y);
            acc.z = fmaf(acc.z, scale, wgt * f1.x);
            acc.w = fmaf(acc.w, scale, wgt * f1.y);
            m = nm;
        }
    }

    float inv = 1.0f / den;
    float4 bv = *(const float4*)(bias + lane * 4);
    float ox = fmaxf(fmaf(acc.x, inv, bv.x), 0.f);
    float oy = fmaxf(fmaf(acc.y, inv, bv.y), 0.f);
    float oz = fmaxf(fmaf(acc.z, inv, bv.z), 0.f);
    float ow = fmaxf(fmaf(acc.w, inv, bv.w), 0.f);
    __half2 p0 = __floats2half2_rn(ox, oy);
    __half2 p1 = __floats2half2_rn(oz, ow);
    uint2 packed = make_uint2(*(unsigned*)&p0, *(unsigned*)&p1);
    *(uint2*)(out + (size_t)node * HID + lane * 4) = packed;
}

// ------------- fused aggregation C=16 + pooling (layer 3) -------------------
__global__ void fused_aggr16_pool_kernel(const int* __restrict__ rowptr,
                                         const int* __restrict__ col,
                                         const float* __restrict__ as_v,
                                         const float* __restrict__ ad_v,
                                         const __half* __restrict__ h,
                                         const float* __restrict__ bias,
                                         const int* __restrict__ batch,
                                         float* __restrict__ pool,
                                         float* __restrict__ cnt, int n) {
    int w = (blockIdx.x * blockDim.x + threadIdx.x) >> 5;
    int lane = threadIdx.x & 31;
    int node = w * 2 + (lane >> 4);
    int c = lane & 15;
    bool active = node < n;

    float advv = active ? __ldg(ad_v + node) : 0.f;
    int beg = active ? __ldg(rowptr + node) : 0;
    int end = active ? __ldg(rowptr + node + 1) : 0;

    const float NEG_INF = __int_as_float(0xFF800000);
    float m = NEG_INF, den = 0.0f, acc = 0.0f;

    for (int i = beg; i < end; i += 8) {
        int   sb[8];
        float eb[8];
        float hb[8];
#pragma unroll
        for (int j = 0; j < 8; j++) {
            bool act = (i + j) < end;
            sb[j] = __ldg(col + (act ? i + j : beg));
        }
#pragma unroll
        for (int j = 0; j < 8; j++) {
            bool act = (i + j) < end;
            float e = act ? (__ldg(as_v + sb[j]) + advv) : NEG_INF;
            eb[j] = e > 0.f ? e : 0.2f * e;
            hb[j] = __half2float(__ldg(h + (size_t)sb[j] * NC + c));
        }
#pragma unroll
        for (int j = 0; j < 8; j++) {
            float e = eb[j];
            float nm = fmaxf(m, e);
            float scale = __expf(m - nm);
            float wgt   = __expf(e - nm);
            den = den * scale + wgt;
            acc = fmaf(acc, scale, wgt * hb[j]);
            m = nm;
        }
    }

    if (active) {
        float val = fmaxf(acc / den + __ldg(bias + c), 0.f);
        int g = __ldg(batch + node);
        atomicAdd(&pool[g * NC + c], val);
        if (c == 0) atomicAdd(&cnt[g], 1.0f);
    }
}

__global__ void finalize_kernel(const float* __restrict__ pool,
                                const float* __restrict__ cnt,
                                float* __restrict__ outp) {
    int t = blockIdx.x * blockDim.x + threadIdx.x;
    if (t >= NG * NC) return;
    int g = t >> 4;
    float v = pool[t] / fmaxf(cnt[g], 1.0f);
    outp[t] = 1.0f / (1.0f + expf(-v));
}

// ---------------------------------------------------------------------------

extern "C" void kernel_launch(void* const* d_in, const int* in_sizes, int n_in,
                              void* d_out, int out_size) {
    const float* x     = (const float*)d_in[0];
    const int*   ei    = (const int*)  d_in[1];
    const int*   batch = (const int*)  d_in[3];
    const float* W1  = (const float*)d_in[4];
    const float* as1 = (const float*)d_in[5];
    const float* ad1 = (const float*)d_in[6];
    const float* b1  = (const float*)d_in[7];
    const float* W2  = (const float*)d_in[8];
    const float* as2 = (const float*)d_in[9];
    const float* ad2 = (const float*)d_in[10];
    const float* b2  = (const float*)d_in[11];
    const float* W3  = (const float*)d_in[12];
    const float* as3 = (const float*)d_in[13];
    const float* ad3 = (const float*)d_in[14];
    const float* b3  = (const float*)d_in[15];
    float* out = (float*)d_out;

    int n    = in_sizes[0] / 11;
    int E    = in_sizes[1] / 2;
    int Etot = E + n;
    const int* src = ei;
    const int* dst = ei + E;

    float *pas, *pad, *ppool, *pcnt;
    __half *pA, *pB, *ph, *pWh;
    int *pdeg, *prow, *pcur, *pcol, *ppart;
    cudaGetSymbolAddress((void**)&pA,    g_A);
    cudaGetSymbolAddress((void**)&pB,    g_B);
    cudaGetSymbolAddress((void**)&ph,    g_h);
    cudaGetSymbolAddress((void**)&pWh,   g_Wh);
    cudaGetSymbolAddress((void**)&pas,   g_as);
    cudaGetSymbolAddress((void**)&pad,   g_ad);
    cudaGetSymbolAddress((void**)&ppool, g_pool);
    cudaGetSymbolAddress((void**)&pcnt,  g_cnt);
    cudaGetSymbolAddress((void**)&pdeg,  g_deg);
    cudaGetSymbolAddress((void**)&prow,  g_rowptr);
    cudaGetSymbolAddress((void**)&pcur,  g_cursor);
    cudaGetSymbolAddress((void**)&pcol,  g_col);
    cudaGetSymbolAddress((void**)&ppart, g_partial);

    const int TB = 256;
    int nPad     = (n + 127) & ~127;
    int nb       = (n + SCAN_CHUNK - 1) / SCAN_CHUNK;     // scan blocks (<=64)
    int gN       = (n + TB - 1) / TB;
    int gEdge4   = (Etot + TB * 4 - 1) / (TB * 4);
    int warps128 = (n + 7) / 8;
    int gGemm128 = (warps128 * 32 + TB - 1) / TB;
    int gWmma    = nPad / 64;
    int gNodeWarp= (n * 32 + TB - 1) / TB;
    int gGemm16  = (n * NC + TB - 1) / TB;
    int gAggr16  = (((n + 1) / 2) * 32 + TB - 1) / TB;
    int gPool    = (NG * NC + TB - 1) / TB;

    // ---- CSR build + W2 conversion ----
    zero_deg_kernel<<<gN, TB>>>(pdeg, n, ppool, pcnt);
    convertW_kernel<<<(HID * HID + TB - 1) / TB, TB>>>(W2, pWh, HID * HID);
    count_deg_kernel<<<gEdge4, TB>>>(dst, E, Etot, pdeg);
    scan_partial_kernel<<<nb, 256>>>(pdeg, ppart, n);
    scan_offsets_kernel<<<1, 64>>>(ppart, nb);
    scan_final_kernel<<<nb, 256>>>(pdeg, ppart, prow, pcur, n);
    scatter_kernel<<<gEdge4, TB>>>(src, dst, E, Etot, pcur, pcol);

    // ---- layer 1 (FFMA GEMM, K=11) ----
    gemm128_kernel<<<gGemm128, TB>>>(x, 11, W1, as1, ad1, ph, pas, pad, n);
    fused_aggr128_kernel<<<gNodeWarp, TB>>>(prow, pcol, pas, pad, ph, b1, pA, n);

    // ---- layer 2 (tensor-core GEMM, fused epilogue) ----
    wmma_gemm128_fused_kernel<<<gWmma, 128>>>(pA, pWh, as2, ad2, ph, pas, pad, nPad, n);
    fused_aggr128_kernel<<<gNodeWarp, TB>>>(prow, pcol, pas, pad, ph, b2, pB, n);

    // ---- layer 3 + pooling ----
    gemm16_kernel<<<gGemm16, TB>>>(pB, W3, as3, ad3, ph, pas, pad, n);
    fused_aggr16_pool_kernel<<<gAggr16, TB>>>(prow, pcol, pas, pad, ph, b3, batch,
                                              ppool, pcnt, n);
    finalize_kernel<<<gPool, TB>>>(ppool, pcnt, out);
}

// round 7
// speedup vs baseline: 2.0686x; 1.0868x over previous
#include <cuda_runtime.h>
#include <cuda_fp16.h>
#include <mma.h>
#include <math.h>
#include <stdint.h>

using namespace nvcuda;

// ---------------------------------------------------------------------------
// GAT (3 layers) + mean pool + sigmoid.
// Key identity: GAT message is linear in h, so layer 1 aggregates RAW x
// (11-dim, 44B/edge) instead of h (128-dim, 256B/edge), and attention logits
// come from x·(W@a) mat-vecs. Layer-2 GEMM on wmma tensor cores.
// ---------------------------------------------------------------------------

#define NMAX   50000
#define NPAD   50048
#define EMAX   800000
#define ETOTMX (EMAX + NMAX)
#define HID    128
#define F_IN   11
#define NC     16
#define NG     64
#define SCAN_CHUNK 1024

__device__ __align__(16) __half g_A[NPAD * HID];   // layer-1 output (fp16)
__device__ __align__(16) __half g_G2[NPAD * HID];  // aggr of A (wmma input)
__device__ __align__(16) __half g_C[NPAD * HID];   // layer-2 output (fp16)
__device__ __align__(16) __half g_h16[NMAX * NC];  // h3 = C @ W3 (fp16)
__device__ __align__(16) __half g_Wh[HID * HID];   // W2 fp16
__device__ float  g_G1[NMAX * F_IN];               // aggr of x (fp32)
__device__ float  g_as[NMAX];
__device__ float  g_ad[NMAX];
__device__ float  g_ws1[F_IN],  g_wd1[F_IN];
__device__ float  g_ws2[HID],   g_wd2[HID];
__device__ float  g_ws3[HID],   g_wd3[HID];
__device__ float  g_pool[NG * NC];
__device__ float  g_cnt[NG];
__device__ int    g_deg[NMAX];
__device__ int    g_rowptr[NMAX + 1];
__device__ int    g_cursor[NMAX];
__device__ int    g_partial[128];
__device__ int    g_col[ETOTMX];

// --------------------------- CSR build --------------------------------------

__global__ void zero_deg_kernel(int* __restrict__ deg, int n,
                                float* __restrict__ pool, float* __restrict__ cnt) {
    int i = blockIdx.x * blockDim.x + threadIdx.x;
    if (i < n) deg[i] = 0;
    if (i < NG * NC) pool[i] = 0.f;
    if (i < NG) cnt[i] = 0.f;
}

__global__ void count_deg_kernel(const int* __restrict__ dst, int E, int Etot,
                                 int* __restrict__ deg) {
    int t = (blockIdx.x * blockDim.x + threadIdx.x) * 4;
    int d[4];
#pragma unroll
    for (int j = 0; j < 4; j++) {
        int i = t + j;
        d[j] = (i < Etot) ? (i < E ? __ldg(dst + i) : (i - E)) : -1;
    }
#pragma unroll
    for (int j = 0; j < 4; j++)
        if (d[j] >= 0) atomicAdd(&deg[d[j]], 1);
}

__global__ void scan_partial_kernel(const int* __restrict__ deg,
                                    int* __restrict__ partial, int n) {
    __shared__ int ws[8];
    int base = blockIdx.x * SCAN_CHUNK + threadIdx.x * 4;
    int s = 0;
#pragma unroll
    for (int j = 0; j < 4; j++) {
        int i = base + j;
        if (i < n) s += __ldg(deg + i);
    }
#pragma unroll
    for (int o = 16; o > 0; o >>= 1) s += __shfl_xor_sync(0xffffffffu, s, o);
    int lane = threadIdx.x & 31, wid = threadIdx.x >> 5;
    if (lane == 0) ws[wid] = s;
    __syncthreads();
    if (wid == 0 && lane < 8) {
        int v = ws[lane];
#pragma unroll
        for (int o = 4; o > 0; o >>= 1) v += __shfl_xor_sync(0xffu, v, o);
        if (lane == 0) partial[blockIdx.x] = v;
    }
}

__global__ void scan_offsets_kernel(int* __restrict__ partial, int nb) {
    __shared__ int tmp[64];
    int t = threadIdx.x;
    int v = t < nb ? partial[t] : 0;
    tmp[t] = v;
    __syncthreads();
#pragma unroll
    for (int o = 1; o < 64; o <<= 1) {
        int u = (t >= o) ? tmp[t - o] : 0;
        __syncthreads();
        tmp[t] += u;
        __syncthreads();
    }
    if (t < nb) partial[t] = tmp[t] - v;
}

__global__ void scan_final_kernel(const int* __restrict__ deg,
                                  const int* __restrict__ partial,
                                  int* __restrict__ rowptr,
                                  int* __restrict__ cursor, int n) {
    __shared__ int ws[8];
    int t = threadIdx.x, lane = t & 31, wid = t >> 5;
    int base = blockIdx.x * SCAN_CHUNK + t * 4;
    int v[4];
#pragma unroll
    for (int j = 0; j < 4; j++) {
        int i = base + j;
        v[j] = (i < n) ? __ldg(deg + i) : 0;
    }
    int tot = v[0] + v[1] + v[2] + v[3];
    int x = tot;
#pragma unroll
    for (int o = 1; o < 32; o <<= 1) {
        int u = __shfl_up_sync(0xffffffffu, x, o);
        if (lane >= o) x += u;
    }
    int warp_excl = x - tot;
    if (lane == 31) ws[wid] = x;
    __syncthreads();
    if (wid == 0) {
        int val = (lane < 8) ? ws[lane] : 0;
#pragma unroll
        for (int o = 1; o < 8; o <<= 1) {
            int u = __shfl_up_sync(0xffffffffu, val, o);
            if (lane >= o) val += u;
        }
        if (lane < 8) ws[lane] = val;
    }
    __syncthreads();
    int off = __ldg(partial + blockIdx.x) + (wid > 0 ? ws[wid - 1] : 0) + warp_excl;
    int run = off;
#pragma unroll
    for (int j = 0; j < 4; j++) {
        run += v[j];
        int i = base + j;
        if (i < n) { rowptr[i + 1] = run; cursor[i] = run - v[j]; }
    }
    if (blockIdx.x == 0 && t == 0) rowptr[0] = 0;
}

__global__ void scatter_kernel(const int* __restrict__ src, const int* __restrict__ dst,
                               int E, int Etot,
                               int* __restrict__ cursor, int* __restrict__ col) {
    int t = (blockIdx.x * blockDim.x + threadIdx.x) * 4;
    int s[4], d[4];
#pragma unroll
    for (int j = 0; j < 4; j++) {
        int i = t + j;
        bool act = i < Etot;
        s[j] = act ? (i < E ? __ldg(src + i) : (i - E)) : 0;
        d[j] = act ? (i < E ? __ldg(dst + i) : (i - E)) : -1;
    }
#pragma unroll
    for (int j = 0; j < 4; j++) {
        if (d[j] >= 0) {
            int pos = atomicAdd(&cursor[d[j]], 1);
            col[pos] = s[j];
        }
    }
}

// --------------------------- precompute w = W @ a ---------------------------
// block 0: ws1/wd1 (11 of 128-dots), block 1: ws2/wd2 (128 of 128-dots),
// block 2: ws3/wd3 (128 of 16-dots). W2 -> fp16 also done here (block 3..).
__global__ void precompute_kernel(const float* __restrict__ W1,
                                  const float* __restrict__ a_s1, const float* __restrict__ a_d1,
                                  const float* __restrict__ W2,
                                  const float* __restrict__ a_s2, const float* __restrict__ a_d2,
                                  const float* __restrict__ W3,
                                  const float* __restrict__ a_s3, const float* __restrict__ a_d3,
                                  float* __restrict__ ws1, float* __restrict__ wd1,
                                  float* __restrict__ ws2, float* __restrict__ wd2,
                                  float* __restrict__ ws3, float* __restrict__ wd3,
                                  __half* __restrict__ Wh) {
    int k = threadIdx.x;
    if (blockIdx.x == 0) {
        if (k < F_IN) {
            float s = 0.f, d = 0.f;
            for (int c = 0; c < HID; c++) {
                float w = __ldg(W1 + k * HID + c);
                s = fmaf(w, __ldg(a_s1 + c), s);
                d = fmaf(w, __ldg(a_d1 + c), d);
            }
            ws1[k] = s; wd1[k] = d;
        }
    } else if (blockIdx.x == 1) {
        float s = 0.f, d = 0.f;
        for (int c = 0; c < HID; c++) {
            float w = __ldg(W2 + k * HID + c);
            s = fmaf(w, __ldg(a_s2 + c), s);
            d = fmaf(w, __ldg(a_d2 + c), d);
        }
        ws2[k] = s; wd2[k] = d;
    } else if (blockIdx.x == 2) {
        float s = 0.f, d = 0.f;
        for (int c = 0; c < NC; c++) {
            float w = __ldg(W3 + k * NC + c);
            s = fmaf(w, __ldg(a_s3 + c), s);
            d = fmaf(w, __ldg(a_d3 + c), d);
        }
        ws3[k] = s; wd3[k] = d;
    } else {
        // blocks 3..130: W2 -> fp16 (128 elems per block)
        int i = (blockIdx.x - 3) * HID + k;
        if (i < HID * HID) Wh[i] = __float2half_rn(__ldg(W2 + i));
    }
}

// --------------------------- layer-1 logits ---------------------------------
__global__ void asad1_kernel(const float* __restrict__ x,
                             const float* __restrict__ ws1, const float* __restrict__ wd1,
                             float* __restrict__ as_o, float* __restrict__ ad_o, int n) {
    int i = blockIdx.x * blockDim.x + threadIdx.x;
    if (i >= n) return;
    const float* row = x + (size_t)i * F_IN;
    float s = 0.f, d = 0.f;
#pragma unroll
    for (int k = 0; k < F_IN; k++) {
        float v = __ldg(row + k);
        s = fmaf(v, __ldg(ws1 + k), s);
        d = fmaf(v, __ldg(wd1 + k), d);
    }
    as_o[i] = s; ad_o[i] = d;
}

// ------------------ layer-1 aggregation of raw x (11-dim) -------------------
// 16-lane group per node; lane c<11 owns feature c. Raw softmax sum (no bias).
__global__ void aggr11_kernel(const int* __restrict__ rowptr,
                              const int* __restrict__ col,
                              const float* __restrict__ as_v,
                              const float* __restrict__ ad_v,
                              const float* __restrict__ x,
                              float* __restrict__ G, int n) {
    int w = (blockIdx.x * blockDim.x + threadIdx.x) >> 5;
    int lane = threadIdx.x & 31;
    int node = w * 2 + (lane >> 4);
    int c = lane & 15;
    if (node >= n) return;

    float advv = __ldg(ad_v + node);
    int beg = __ldg(rowptr + node);
    int end = __ldg(rowptr + node + 1);

    const float NEG_INF = __int_as_float(0xFF800000);
    float m = NEG_INF, den = 0.0f, acc = 0.0f;

    for (int i = beg; i < end; i += 8) {
        int   sb[8];
        float eb[8];
        float xb[8];
#pragma unroll
        for (int j = 0; j < 8; j++) {
            bool act = (i + j) < end;
            sb[j] = __ldg(col + (act ? i + j : beg));
        }
#pragma unroll
        for (int j = 0; j < 8; j++) {
            bool act = (i + j) < end;
            float e = act ? (__ldg(as_v + sb[j]) + advv) : NEG_INF;
            eb[j] = e > 0.f ? e : 0.2f * e;
            xb[j] = (c < F_IN) ? __ldg(x + (size_t)sb[j] * F_IN + c) : 0.f;
        }
#pragma unroll
        for (int j = 0; j < 8; j++) {
            float e = eb[j];
            float nm = fmaxf(m, e);
            float scale = __expf(m - nm);
            float wgt   = __expf(e - nm);
            den = den * scale + wgt;
            acc = fmaf(acc, scale, wgt * xb[j]);
            m = nm;
        }
    }
    if (c < F_IN) G[(size_t)node * F_IN + c] = acc / den;
}

// --------------- layer-1 GEMM: A = relu(G1@W1+b1), epi: as2/ad2 -------------
__global__ void gemmK11_kernel(const float* __restrict__ in,   // [n,11]
                               const float* __restrict__ W,    // [11,128]
                               const float* __restrict__ bias, // b1[128]
                               const float* __restrict__ ws2,
                               const float* __restrict__ wd2,
                               __half* __restrict__ A,
                               float* __restrict__ as_o,
                               float* __restrict__ ad_o, int n) {
    int w    = (blockIdx.x * blockDim.x + threadIdx.x) >> 5;
    int lane = threadIdx.x & 31;
    int node0 = w * 8;
    if (node0 >= n) return;

    int nid[8];
#pragma unroll
    for (int i = 0; i < 8; i++) {
        int nn = node0 + i;
        nid[i] = nn < n ? nn : (n - 1);
    }

    float4 bv = *(const float4*)(bias + lane * 4);
    float4 acc[8];
#pragma unroll
    for (int i = 0; i < 8; i++) acc[i] = bv;   // start from bias

#pragma unroll
    for (int k = 0; k < F_IN; k++) {
        float4 wv = *(const float4*)(W + k * HID + lane * 4);
#pragma unroll
        for (int i = 0; i < 8; i++) {
            float a = __ldg(in + (size_t)nid[i] * F_IN + k);
            acc[i].x = fmaf(a, wv.x, acc[i].x);
            acc[i].y = fmaf(a, wv.y, acc[i].y);
            acc[i].z = fmaf(a, wv.z, acc[i].z);
            acc[i].w = fmaf(a, wv.w, acc[i].w);
        }
    }

    float4 sv = *(const float4*)(ws2 + lane * 4);
    float4 dv = *(const float4*)(wd2 + lane * 4);

#pragma unroll
    for (int i = 0; i < 8; i++) {
        float ox = fmaxf(acc[i].x, 0.f);
        float oy = fmaxf(acc[i].y, 0.f);
        float oz = fmaxf(acc[i].z, 0.f);
        float ow = fmaxf(acc[i].w, 0.f);
        __half2 p0 = __floats2half2_rn(ox, oy);
        __half2 p1 = __floats2half2_rn(oz, ow);
        uint2 packed = make_uint2(*(unsigned*)&p0, *(unsigned*)&p1);
        *(uint2*)(A + (size_t)nid[i] * HID + lane * 4) = packed;

        float ps = ox * sv.x + oy * sv.y + oz * sv.z + ow * sv.w;
        float pd = ox * dv.x + oy * dv.y + oz * dv.z + ow * dv.w;
#pragma unroll
        for (int o = 16; o > 0; o >>= 1) {
            ps += __shfl_xor_sync(0xffffffffu, ps, o);
            pd += __shfl_xor_sync(0xffffffffu, pd, o);
        }
        if (lane == 0) { as_o[nid[i]] = ps; ad_o[nid[i]] = pd; }
    }
}

// ------------------ raw softmax aggregation, C=128 (fp16) -------------------
__global__ void aggr128_raw_kernel(const int* __restrict__ rowptr,
                                   const int* __restrict__ col,
                                   const float* __restrict__ as_v,
                                   const float* __restrict__ ad_v,
                                   const __half* __restrict__ h,
                                   __half* __restrict__ out, int n) {
    int node = (blockIdx.x * blockDim.x + threadIdx.x) >> 5;
    if (node >= n) return;
    int lane = threadIdx.x & 31;

    float advv = __ldg(ad_v + node);
    int beg = __ldg(rowptr + node);
    int end = __ldg(rowptr + node + 1);

    const float NEG_INF = __int_as_float(0xFF800000);
    float m = NEG_INF, den = 0.0f;
    float4 acc = make_float4(0.f, 0.f, 0.f, 0.f);

    for (int i = beg; i < end; i += 8) {
        int   sb[8];
        float eb[8];
        uint2 hb[8];
#pragma unroll
        for (int j = 0; j < 8; j++) {
            bool act = (i + j) < end;
            sb[j] = __ldg(col + (act ? i + j : beg));
        }
#pragma unroll
        for (int j = 0; j < 8; j++) {
            bool act = (i + j) < end;
            float e = act ? (__ldg(as_v + sb[j]) + advv) : NEG_INF;
            eb[j] = e > 0.f ? e : 0.2f * e;
            hb[j] = *(const uint2*)(h + (size_t)sb[j] * HID + lane * 4);
        }
#pragma unroll
        for (int j = 0; j < 8; j++) {
            float e = eb[j];
            float nm = fmaxf(m, e);
            float scale = __expf(m - nm);
            float wgt   = __expf(e - nm);
            __half2 h0 = *(__half2*)&hb[j].x;
            __half2 h1 = *(__half2*)&hb[j].y;
            float2 f0 = __half22float2(h0);
            float2 f1 = __half22float2(h1);
            den = den * scale + wgt;
            acc.x = fmaf(acc.x, scale, wgt * f0.x);
            acc.y = fmaf(acc.y, scale, wgt * f0.y);
            acc.z = fmaf(acc.z, scale, wgt * f1.x);
            acc.w = fmaf(acc.w, scale, wgt * f1.y);
            m = nm;
        }
    }

    float inv = 1.0f / den;
    __half2 p0 = __floats2half2_rn(acc.x * inv, acc.y * inv);
    __half2 p1 = __floats2half2_rn(acc.z * inv, acc.w * inv);
    uint2 packed = make_uint2(*(unsigned*)&p0, *(unsigned*)&p1);
    *(uint2*)(out + (size_t)node * HID + lane * 4) = packed;
}

// -------- layer-2 wmma GEMM: C = relu(G2@W2+b2), epi: as3/ad3 ---------------
__global__ __launch_bounds__(128) void wmma_gemm128_fused_kernel(
        const __half* __restrict__ A,     // [NPAD,128]
        const __half* __restrict__ Wh,    // [128,128]
        const float* __restrict__ bias,   // b2
        const float* __restrict__ ws3,
        const float* __restrict__ wd3,
        __half* __restrict__ Cout,
        float* __restrict__ as_o,
        float* __restrict__ ad_o, int nPad, int n) {
    __shared__ float s_c[64 * HID];
    int warp = threadIdx.x >> 5;
    int lane = threadIdx.x & 31;
    int row0 = blockIdx.x * 64 + warp * 16;
    if (row0 >= nPad) return;

    wmma::fragment<wmma::accumulator, 16, 16, 16, float> acc[8];
#pragma unroll
    for (int i = 0; i < 8; i++) wmma::fill_fragment(acc[i], 0.f);

#pragma unroll
    for (int k = 0; k < 8; k++) {
        wmma::fragment<wmma::matrix_a, 16, 16, 16, __half, wmma::row_major> a;
        wmma::load_matrix_sync(a, A + (size_t)row0 * HID + k * 16, HID);
#pragma unroll
        for (int nt = 0; nt < 8; nt++) {
            wmma::fragment<wmma::matrix_b, 16, 16, 16, __half, wmma::row_major> b;
            wmma::load_matrix_sync(b, Wh + k * 16 * HID + nt * 16, HID);
            wmma::mma_sync(acc[nt], a, b, acc[nt]);
        }
    }
    float* my = s_c + warp * 16 * HID;
#pragma unroll
    for (int nt = 0; nt < 8; nt++)
        wmma::store_matrix_sync(my + nt * 16, acc[nt], HID, wmma::mem_row_major);
    __syncwarp();

    float4 bv = *(const float4*)(bias + lane * 4);
    float4 sv = *(const float4*)(ws3 + lane * 4);
    float4 dv = *(const float4*)(wd3 + lane * 4);
#pragma unroll
    for (int r = 0; r < 16; r++) {
        int row = row0 + r;
        if (row >= n) break;
        float4 v = *(const float4*)(my + r * HID + lane * 4);
        float ox = fmaxf(v.x + bv.x, 0.f);
        float oy = fmaxf(v.y + bv.y, 0.f);
        float oz = fmaxf(v.z + bv.z, 0.f);
        float ow = fmaxf(v.w + bv.w, 0.f);
        __half2 p0 = __floats2half2_rn(ox, oy);
        __half2 p1 = __floats2half2_rn(oz, ow);
        uint2 packed = make_uint2(*(unsigned*)&p0, *(unsigned*)&p1);
        *(uint2*)(Cout + (size_t)row * HID + lane * 4) = packed;
        float ps = ox * sv.x + oy * sv.y + oz * sv.z + ow * sv.w;
        float pd = ox * dv.x + oy * dv.y + oz * dv.z + ow * dv.w;
#pragma unroll
        for (int o = 16; o > 0; o >>= 1) {
            ps += __shfl_xor_sync(0xffffffffu, ps, o);
            pd += __shfl_xor_sync(0xffffffffu, pd, o);
        }
        if (lane == 0) { as_o[row] = ps; ad_o[row] = pd; }
    }
}

// --------------------------- layer-3 GEMM (no epilogue) ---------------------
__global__ void gemm16_kernel(const __half* __restrict__ in,
                              const float* __restrict__ W,
                              __half* __restrict__ h, int n) {
    int t = blockIdx.x * blockDim.x + threadIdx.x;
    int node = t >> 4;
    int c = t & 15;
    if (node >= n) return;

    const __half* row = in + (size_t)node * HID;
    float acc = 0.f;
#pragma unroll 8
    for (int k = 0; k < HID; k++)
        acc = fmaf(__half2float(__ldg(row + k)), __ldg(W + k * NC + c), acc);

    h[(size_t)node * NC + c] = __float2half_rn(acc);
}

// ------------- fused aggregation C=16 + pooling (layer 3) -------------------
__global__ void fused_aggr16_pool_kernel(const int* __restrict__ rowptr,
                                         const int* __restrict__ col,
                                         const float* __restrict__ as_v,
                                         const float* __restrict__ ad_v,
                                         const __half* __restrict__ h,
                                         const float* __restrict__ bias,
                                         const int* __restrict__ batch,
                                         float* __restrict__ pool,
                                         float* __restrict__ cnt, int n) {
    int w = (blockIdx.x * blockDim.x + threadIdx.x) >> 5;
    int lane = threadIdx.x & 31;
    int node = w * 2 + (lane >> 4);
    int c = lane & 15;
    bool active = node < n;

    float advv = active ? __ldg(ad_v + node) : 0.f;
    int beg = active ? __ldg(rowptr + node) : 0;
    int end = active ? __ldg(rowptr + node + 1) : 0;

    const float NEG_INF = __int_as_float(0xFF800000);
    float m = NEG_INF, den = 0.0f, acc = 0.0f;

    for (int i = beg; i < end; i += 8) {
        int   sb[8];
        float eb[8];
        float hb[8];
#pragma unroll
        for (int j = 0; j < 8; j++) {
            bool act = (i + j) < end;
            sb[j] = __ldg(col + (act ? i + j : beg));
        }
#pragma unroll
        for (int j = 0; j < 8; j++) {
            bool act = (i + j) < end;
            float e = act ? (__ldg(as_v + sb[j]) + advv) : NEG_INF;
            eb[j] = e > 0.f ? e : 0.2f * e;
            hb[j] = __half2float(__ldg(h + (size_t)sb[j] * NC + c));
        }
#pragma unroll
        for (int j = 0; j < 8; j++) {
            float e = eb[j];
            float nm = fmaxf(m, e);
            float scale = __expf(m - nm);
            float wgt   = __expf(e - nm);
            den = den * scale + wgt;
            acc = fmaf(acc, scale, wgt * hb[j]);
            m = nm;
        }
    }

    if (active) {
        float val = fmaxf(acc / den + __ldg(bias + c), 0.f);
        int g = __ldg(batch + node);
        atomicAdd(&pool[g * NC + c], val);
        if (c == 0) atomicAdd(&cnt[g], 1.0f);
    }
}

__global__ void finalize_kernel(const float* __restrict__ pool,
                                const float* __restrict__ cnt,
                                float* __restrict__ outp) {
    int t = blockIdx.x * blockDim.x + threadIdx.x;
    if (t >= NG * NC) return;
    int g = t >> 4;
    float v = pool[t] / fmaxf(cnt[g], 1.0f);
    outp[t] = 1.0f / (1.0f + expf(-v));
}

// ---------------------------------------------------------------------------

extern "C" void kernel_launch(void* const* d_in, const int* in_sizes, int n_in,
                              void* d_out, int out_size) {
    const float* x     = (const float*)d_in[0];
    const int*   ei    = (const int*)  d_in[1];
    const int*   batch = (const int*)  d_in[3];
    const float* W1  = (const float*)d_in[4];
    const float* as1 = (const float*)d_in[5];
    const float* ad1 = (const float*)d_in[6];
    const float* b1  = (const float*)d_in[7];
    const float* W2  = (const float*)d_in[8];
    const float* as2 = (const float*)d_in[9];
    const float* ad2 = (const float*)d_in[10];
    const float* b2  = (const float*)d_in[11];
    const float* W3  = (const float*)d_in[12];
    const float* as3 = (const float*)d_in[13];
    const float* ad3 = (const float*)d_in[14];
    const float* b3  = (const float*)d_in[15];
    float* out = (float*)d_out;

    int n    = in_sizes[0] / F_IN;
    int E    = in_sizes[1] / 2;
    int Etot = E + n;
    const int* src = ei;
    const int* dst = ei + E;

    float *pas, *pad, *ppool, *pcnt, *pG1;
    float *pws1, *pwd1, *pws2, *pwd2, *pws3, *pwd3;
    __half *pA, *pG2, *pC, *ph16, *pWh;
    int *pdeg, *prow, *pcur, *pcol, *ppart;
    cudaGetSymbolAddress((void**)&pA,    g_A);
    cudaGetSymbolAddress((void**)&pG2,   g_G2);
    cudaGetSymbolAddress((void**)&pC,    g_C);
    cudaGetSymbolAddress((void**)&ph16,  g_h16);
    cudaGetSymbolAddress((void**)&pWh,   g_Wh);
    cudaGetSymbolAddress((void**)&pG1,   g_G1);
    cudaGetSymbolAddress((void**)&pas,   g_as);
    cudaGetSymbolAddress((void**)&pad,   g_ad);
    cudaGetSymbolAddress((void**)&pws1,  g_ws1);
    cudaGetSymbolAddress((void**)&pwd1,  g_wd1);
    cudaGetSymbolAddress((void**)&pws2,  g_ws2);
    cudaGetSymbolAddress((void**)&pwd2,  g_wd2);
    cudaGetSymbolAddress((void**)&pws3,  g_ws3);
    cudaGetSymbolAddress((void**)&pwd3,  g_wd3);
    cudaGetSymbolAddress((void**)&ppool, g_pool);
    cudaGetSymbolAddress((void**)&pcnt,  g_cnt);
    cudaGetSymbolAddress((void**)&pdeg,  g_deg);
    cudaGetSymbolAddress((void**)&prow,  g_rowptr);
    cudaGetSymbolAddress((void**)&pcur,  g_cursor);
    cudaGetSymbolAddress((void**)&pcol,  g_col);
    cudaGetSymbolAddress((void**)&ppart, g_partial);

    const int TB = 256;
    int nPad     = (n + 127) & ~127;
    int nb       = (n + SCAN_CHUNK - 1) / SCAN_CHUNK;
    int gN       = (n + TB - 1) / TB;
    int gEdge4   = (Etot + TB * 4 - 1) / (TB * 4);
    int warps128 = (n + 7) / 8;
    int gGemmK11 = (warps128 * 32 + TB - 1) / TB;
    int gWmma    = nPad / 64;
    int gNodeWarp= (n * 32 + TB - 1) / TB;
    int gHalfWarp= (((n + 1) / 2) * 32 + TB - 1) / TB;
    int gGemm16  = (n * NC + TB - 1) / TB;
    int gPool    = (NG * NC + TB - 1) / TB;

    // ---- CSR build + precompute (independent; precompute overlaps) ----
    zero_deg_kernel<<<gN, TB>>>(pdeg, n, ppool, pcnt);
    precompute_kernel<<<3 + HID, HID>>>(W1, as1, ad1, W2, as2, ad2, W3, as3, ad3,
                                        pws1, pwd1, pws2, pwd2, pws3, pwd3, pWh);
    count_deg_kernel<<<gEdge4, TB>>>(dst, E, Etot, pdeg);
    scan_partial_kernel<<<nb, 256>>>(pdeg, ppart, n);
    scan_offsets_kernel<<<1, 64>>>(ppart, nb);
    scan_final_kernel<<<nb, 256>>>(pdeg, ppart, prow, pcur, n);
    scatter_kernel<<<gEdge4, TB>>>(src, dst, E, Etot, pcur, pcol);

    // ---- layer 1: logits from x, aggregate raw x, then GEMM ----
    asad1_kernel<<<gN, TB>>>(x, pws1, pwd1, pas, pad, n);
    aggr11_kernel<<<gHalfWarp, TB>>>(prow, pcol, pas, pad, x, pG1, n);
    gemmK11_kernel<<<gGemmK11, TB>>>(pG1, W1, b1, pws2, pwd2, pA, pas, pad, n);

    // ---- layer 2: aggregate A, wmma GEMM (bias+relu+as3/ad3 fused) ----
    aggr128_raw_kernel<<<gNodeWarp, TB>>>(prow, pcol, pas, pad, pA, pG2, n);
    wmma_gemm128_fused_kernel<<<gWmma, 128>>>(pG2, pWh, b2, pws3, pwd3, pC,
                                              pas, pad, nPad, n);

    // ---- layer 3 + pooling ----
    gemm16_kernel<<<gGemm16, TB>>>(pC, W3, ph16, n);
    fused_aggr16_pool_kernel<<<gHalfWarp, TB>>>(prow, pcol, pas, pad, ph16, b3,
                                                batch, ppool, pcnt, n);
    finalize_kernel<<<gPool, TB>>>(ppool, pcnt, out);
}

// round 8
// speedup vs baseline: 2.2236x; 1.0749x over previous
#include <cuda_runtime.h>
#include <cuda_fp16.h>
#include <mma.h>
#include <math.h>
#include <stdint.h>

using namespace nvcuda;

// ---------------------------------------------------------------------------
// GAT (3 layers) + mean pool + sigmoid.
// - Layer 1 aggregates RAW x (11-dim) via linearity; logits from x·(W@a).
// - Layer-2 GEMM on wmma tensor cores, epilogue fused.
// - Aggregations: lane-split online softmax (exp computed once per edge, not
//   per lane) + per-chunk accumulator rescale -> ~2x fewer instructions.
// ---------------------------------------------------------------------------

#define NMAX   50000
#define NPAD   50048
#define EMAX   800000
#define ETOTMX (EMAX + NMAX)
#define HID    128
#define F_IN   11
#define NC     16
#define NG     64
#define SCAN_CHUNK 1024
#define FULLM  0xffffffffu

__device__ __align__(16) __half g_A[NPAD * HID];   // layer-1 output (fp16)
__device__ __align__(16) __half g_G2[NPAD * HID];  // aggr of A (wmma input)
__device__ __align__(16) __half g_C[NPAD * HID];   // layer-2 output (fp16)
__device__ __align__(16) __half g_h16[NMAX * NC];  // h3 = C @ W3 (fp16)
__device__ __align__(16) __half g_Wh[HID * HID];   // W2 fp16
__device__ float  g_G1[NMAX * F_IN];               // aggr of x (fp32)
__device__ float  g_as[NMAX];
__device__ float  g_ad[NMAX];
__device__ float  g_ws1[F_IN],  g_wd1[F_IN];
__device__ float  g_ws2[HID],   g_wd2[HID];
__device__ float  g_ws3[HID],   g_wd3[HID];
__device__ float  g_pool[NG * NC];
__device__ float  g_cnt[NG];
__device__ int    g_deg[NMAX];
__device__ int    g_rowptr[NMAX + 1];
__device__ int    g_cursor[NMAX];
__device__ int    g_partial[128];
__device__ int    g_col[ETOTMX];

// --------------------------- CSR build --------------------------------------

__global__ void zero_deg_kernel(int* __restrict__ deg, int n,
                                float* __restrict__ pool, float* __restrict__ cnt) {
    int i = blockIdx.x * blockDim.x + threadIdx.x;
    if (i < n) deg[i] = 0;
    if (i < NG * NC) pool[i] = 0.f;
    if (i < NG) cnt[i] = 0.f;
}

__global__ void count_deg_kernel(const int* __restrict__ dst, int E, int Etot,
                                 int* __restrict__ deg) {
    int t = (blockIdx.x * blockDim.x + threadIdx.x) * 4;
    int d[4];
#pragma unroll
    for (int j = 0; j < 4; j++) {
        int i = t + j;
        d[j] = (i < Etot) ? (i < E ? __ldg(dst + i) : (i - E)) : -1;
    }
#pragma unroll
    for (int j = 0; j < 4; j++)
        if (d[j] >= 0) atomicAdd(&deg[d[j]], 1);
}

__global__ void scan_partial_kernel(const int* __restrict__ deg,
                                    int* __restrict__ partial, int n) {
    __shared__ int ws[8];
    int base = blockIdx.x * SCAN_CHUNK + threadIdx.x * 4;
    int s = 0;
#pragma unroll
    for (int j = 0; j < 4; j++) {
        int i = base + j;
        if (i < n) s += __ldg(deg + i);
    }
#pragma unroll
    for (int o = 16; o > 0; o >>= 1) s += __shfl_xor_sync(FULLM, s, o);
    int lane = threadIdx.x & 31, wid = threadIdx.x >> 5;
    if (lane == 0) ws[wid] = s;
    __syncthreads();
    if (wid == 0 && lane < 8) {
        int v = ws[lane];
#pragma unroll
        for (int o = 4; o > 0; o >>= 1) v += __shfl_xor_sync(0xffu, v, o);
        if (lane == 0) partial[blockIdx.x] = v;
    }
}

__global__ void scan_offsets_kernel(int* __restrict__ partial, int nb) {
    __shared__ int tmp[64];
    int t = threadIdx.x;
    int v = t < nb ? partial[t] : 0;
    tmp[t] = v;
    __syncthreads();
#pragma unroll
    for (int o = 1; o < 64; o <<= 1) {
        int u = (t >= o) ? tmp[t - o] : 0;
        __syncthreads();
        tmp[t] += u;
        __syncthreads();
    }
    if (t < nb) partial[t] = tmp[t] - v;
}

__global__ void scan_final_kernel(const int* __restrict__ deg,
                                  const int* __restrict__ partial,
                                  int* __restrict__ rowptr,
                                  int* __restrict__ cursor, int n) {
    __shared__ int ws[8];
    int t = threadIdx.x, lane = t & 31, wid = t >> 5;
    int base = blockIdx.x * SCAN_CHUNK + t * 4;
    int v[4];
#pragma unroll
    for (int j = 0; j < 4; j++) {
        int i = base + j;
        v[j] = (i < n) ? __ldg(deg + i) : 0;
    }
    int tot = v[0] + v[1] + v[2] + v[3];
    int x = tot;
#pragma unroll
    for (int o = 1; o < 32; o <<= 1) {
        int u = __shfl_up_sync(FULLM, x, o);
        if (lane >= o) x += u;
    }
    int warp_excl = x - tot;
    if (lane == 31) ws[wid] = x;
    __syncthreads();
    if (wid == 0) {
        int val = (lane < 8) ? ws[lane] : 0;
#pragma unroll
        for (int o = 1; o < 8; o <<= 1) {
            int u = __shfl_up_sync(FULLM, val, o);
            if (lane >= o) val += u;
        }
        if (lane < 8) ws[lane] = val;
    }
    __syncthreads();
    int off = __ldg(partial + blockIdx.x) + (wid > 0 ? ws[wid - 1] : 0) + warp_excl;
    int run = off;
#pragma unroll
    for (int j = 0; j < 4; j++) {
        run += v[j];
        int i = base + j;
        if (i < n) { rowptr[i + 1] = run; cursor[i] = run - v[j]; }
    }
    if (blockIdx.x == 0 && t == 0) rowptr[0] = 0;
}

__global__ void scatter_kernel(const int* __restrict__ src, const int* __restrict__ dst,
                               int E, int Etot,
                               int* __restrict__ cursor, int* __restrict__ col) {
    int t = (blockIdx.x * blockDim.x + threadIdx.x) * 4;
    int s[4], d[4];
#pragma unroll
    for (int j = 0; j < 4; j++) {
        int i = t + j;
        bool act = i < Etot;
        s[j] = act ? (i < E ? __ldg(src + i) : (i - E)) : 0;
        d[j] = act ? (i < E ? __ldg(dst + i) : (i - E)) : -1;
    }
#pragma unroll
    for (int j = 0; j < 4; j++) {
        if (d[j] >= 0) {
            int pos = atomicAdd(&cursor[d[j]], 1);
            col[pos] = s[j];
        }
    }
}

// --------------------------- precompute w = W @ a ---------------------------
__global__ void precompute_kernel(const float* __restrict__ W1,
                                  const float* __restrict__ a_s1, const float* __restrict__ a_d1,
                                  const float* __restrict__ W2,
                                  const float* __restrict__ a_s2, const float* __restrict__ a_d2,
                                  const float* __restrict__ W3,
                                  const float* __restrict__ a_s3, const float* __restrict__ a_d3,
                                  float* __restrict__ ws1, float* __restrict__ wd1,
                                  float* __restrict__ ws2, float* __restrict__ wd2,
                                  float* __restrict__ ws3, float* __restrict__ wd3,
                                  __half* __restrict__ Wh) {
    int k = threadIdx.x;
    if (blockIdx.x == 0) {
        if (k < F_IN) {
            float s = 0.f, d = 0.f;
            for (int c = 0; c < HID; c++) {
                float w = __ldg(W1 + k * HID + c);
                s = fmaf(w, __ldg(a_s1 + c), s);
                d = fmaf(w, __ldg(a_d1 + c), d);
            }
            ws1[k] = s; wd1[k] = d;
        }
    } else if (blockIdx.x == 1) {
        float s = 0.f, d = 0.f;
        for (int c = 0; c < HID; c++) {
            float w = __ldg(W2 + k * HID + c);
            s = fmaf(w, __ldg(a_s2 + c), s);
            d = fmaf(w, __ldg(a_d2 + c), d);
        }
        ws2[k] = s; wd2[k] = d;
    } else if (blockIdx.x == 2) {
        float s = 0.f, d = 0.f;
        for (int c = 0; c < NC; c++) {
            float w = __ldg(W3 + k * NC + c);
            s = fmaf(w, __ldg(a_s3 + c), s);
            d = fmaf(w, __ldg(a_d3 + c), d);
        }
        ws3[k] = s; wd3[k] = d;
    } else {
        int i = (blockIdx.x - 3) * HID + k;
        if (i < HID * HID) Wh[i] = __float2half_rn(__ldg(W2 + i));
    }
}

// --------------------------- layer-1 logits ---------------------------------
__global__ void asad1_kernel(const float* __restrict__ x,
                             const float* __restrict__ ws1, const float* __restrict__ wd1,
                             float* __restrict__ as_o, float* __restrict__ ad_o, int n) {
    int i = blockIdx.x * blockDim.x + threadIdx.x;
    if (i >= n) return;
    const float* row = x + (size_t)i * F_IN;
    float s = 0.f, d = 0.f;
#pragma unroll
    for (int k = 0; k < F_IN; k++) {
        float v = __ldg(row + k);
        s = fmaf(v, __ldg(ws1 + k), s);
        d = fmaf(v, __ldg(wd1 + k), d);
    }
    as_o[i] = s; ad_o[i] = d;
}

// ------------------ layer-1 aggregation of raw x (11-dim) -------------------
// 16-lane group per node. Lane-split softmax, chunk rescale.
__global__ void aggr11_kernel(const int* __restrict__ rowptr,
                              const int* __restrict__ col,
                              const float* __restrict__ as_v,
                              const float* __restrict__ ad_v,
                              const float* __restrict__ x,
                              float* __restrict__ G, int n) {
    int w = (blockIdx.x * blockDim.x + threadIdx.x) >> 5;
    int lane = threadIdx.x & 31;
    int local = lane & 15;
    int node = w * 2 + (lane >> 4);
    int c = local;
    if (node >= n) return;

    float advv = __ldg(ad_v + node);
    int beg = __ldg(rowptr + node);
    int end = __ldg(rowptr + node + 1);

    const float NEG_INF = __int_as_float(0xFF800000);
    float m = NEG_INF, den = 0.0f, acc = 0.0f;

    for (int i = beg; i < end; i += 8) {
        int sb[8];
#pragma unroll
        for (int j = 0; j < 8; j++) {
            bool act = (i + j) < end;
            sb[j] = __ldg(col + (act ? i + j : beg));
        }
        float xb[8];
#pragma unroll
        for (int j = 0; j < 8; j++)
            xb[j] = (c < F_IN) ? __ldg(x + (size_t)sb[j] * F_IN + c) : 0.f;

        // local lanes 0..7 own one edge each
        bool eact = (local < 8) && (i + local) < end;
        float e = eact ? (__ldg(as_v + sb[local & 7]) + advv) : NEG_INF;
        e = e > 0.f ? e : 0.2f * e;
        float cmax = e;
        cmax = fmaxf(cmax, __shfl_xor_sync(FULLM, cmax, 1, 8));
        cmax = fmaxf(cmax, __shfl_xor_sync(FULLM, cmax, 2, 8));
        cmax = fmaxf(cmax, __shfl_xor_sync(FULLM, cmax, 4, 8));
        cmax = __shfl_sync(FULLM, cmax, 0, 16);      // group lane 0
        float nm = fmaxf(m, cmax);
        float scale = __expf(m - nm);
        float wgt = __expf(e - nm);                  // 0 for inactive
        float wsum = wgt;
        wsum += __shfl_xor_sync(FULLM, wsum, 1, 8);
        wsum += __shfl_xor_sync(FULLM, wsum, 2, 8);
        wsum += __shfl_xor_sync(FULLM, wsum, 4, 8);
        wsum = __shfl_sync(FULLM, wsum, 0, 16);
        den = den * scale + wsum;
        acc *= scale;
#pragma unroll
        for (int j = 0; j < 8; j++) {
            float wj = __shfl_sync(FULLM, wgt, j, 16);
            acc = fmaf(wj, xb[j], acc);
        }
        m = nm;
    }
    if (c < F_IN) G[(size_t)node * F_IN + c] = acc / den;
}

// --------------- layer-1 GEMM: A = relu(G1@W1+b1), epi: as2/ad2 -------------
__global__ void gemmK11_kernel(const float* __restrict__ in,
                               const float* __restrict__ W,
                               const float* __restrict__ bias,
                               const float* __restrict__ ws2,
                               const float* __restrict__ wd2,
                               __half* __restrict__ A,
                               float* __restrict__ as_o,
                               float* __restrict__ ad_o, int n) {
    int w    = (blockIdx.x * blockDim.x + threadIdx.x) >> 5;
    int lane = threadIdx.x & 31;
    int node0 = w * 8;
    if (node0 >= n) return;

    int nid[8];
#pragma unroll
    for (int i = 0; i < 8; i++) {
        int nn = node0 + i;
        nid[i] = nn < n ? nn : (n - 1);
    }

    float4 bv = *(const float4*)(bias + lane * 4);
    float4 acc[8];
#pragma unroll
    for (int i = 0; i < 8; i++) acc[i] = bv;

#pragma unroll
    for (int k = 0; k < F_IN; k++) {
        float4 wv = *(const float4*)(W + k * HID + lane * 4);
#pragma unroll
        for (int i = 0; i < 8; i++) {
            float a = __ldg(in + (size_t)nid[i] * F_IN + k);
            acc[i].x = fmaf(a, wv.x, acc[i].x);
            acc[i].y = fmaf(a, wv.y, acc[i].y);
            acc[i].z = fmaf(a, wv.z, acc[i].z);
            acc[i].w = fmaf(a, wv.w, acc[i].w);
        }
    }

    float4 sv = *(const float4*)(ws2 + lane * 4);
    float4 dv = *(const float4*)(wd2 + lane * 4);

#pragma unroll
    for (int i = 0; i < 8; i++) {
        float ox = fmaxf(acc[i].x, 0.f);
        float oy = fmaxf(acc[i].y, 0.f);
        float oz = fmaxf(acc[i].z, 0.f);
        float ow = fmaxf(acc[i].w, 0.f);
        __half2 p0 = __floats2half2_rn(ox, oy);
        __half2 p1 = __floats2half2_rn(oz, ow);
        uint2 packed = make_uint2(*(unsigned*)&p0, *(unsigned*)&p1);
        *(uint2*)(A + (size_t)nid[i] * HID + lane * 4) = packed;

        float ps = ox * sv.x + oy * sv.y + oz * sv.z + ow * sv.w;
        float pd = ox * dv.x + oy * dv.y + oz * dv.z + ow * dv.w;
#pragma unroll
        for (int o = 16; o > 0; o >>= 1) {
            ps += __shfl_xor_sync(FULLM, ps, o);
            pd += __shfl_xor_sync(FULLM, pd, o);
        }
        if (lane == 0) { as_o[nid[i]] = ps; ad_o[nid[i]] = pd; }
    }
}

// ------------------ raw softmax aggregation, C=128 (fp16) -------------------
// warp per node. Lane-split softmax (lanes 0..7 own edges), chunk rescale.
__global__ void aggr128_raw_kernel(const int* __restrict__ rowptr,
                                   const int* __restrict__ col,
                                   const float* __restrict__ as_v,
                                   const float* __restrict__ ad_v,
                                   const __half* __restrict__ h,
                                   __half* __restrict__ out, int n) {
    int node = (blockIdx.x * blockDim.x + threadIdx.x) >> 5;
    if (node >= n) return;
    int lane = threadIdx.x & 31;

    float advv = __ldg(ad_v + node);
    int beg = __ldg(rowptr + node);
    int end = __ldg(rowptr + node + 1);

    const float NEG_INF = __int_as_float(0xFF800000);
    float m = NEG_INF, den = 0.0f;
    float4 acc = make_float4(0.f, 0.f, 0.f, 0.f);

    for (int i = beg; i < end; i += 8) {
        int sb[8];
#pragma unroll
        for (int j = 0; j < 8; j++) {
            bool act = (i + j) < end;
            sb[j] = __ldg(col + (act ? i + j : beg));
        }
        uint2 hb[8];
#pragma unroll
        for (int j = 0; j < 8; j++)
            hb[j] = *(const uint2*)(h + (size_t)sb[j] * HID + lane * 4);

        bool eact = (lane < 8) && (i + lane) < end;
        float e = eact ? (__ldg(as_v + sb[lane & 7]) + advv) : NEG_INF;
        e = e > 0.f ? e : 0.2f * e;
        float cmax = e;
        cmax = fmaxf(cmax, __shfl_xor_sync(FULLM, cmax, 1, 8));
        cmax = fmaxf(cmax, __shfl_xor_sync(FULLM, cmax, 2, 8));
        cmax = fmaxf(cmax, __shfl_xor_sync(FULLM, cmax, 4, 8));
        cmax = __shfl_sync(FULLM, cmax, 0, 32);      // warp lane 0
        float nm = fmaxf(m, cmax);
        float scale = __expf(m - nm);
        float wgt = __expf(e - nm);
        float wsum = wgt;
        wsum += __shfl_xor_sync(FULLM, wsum, 1, 8);
        wsum += __shfl_xor_sync(FULLM, wsum, 2, 8);
        wsum += __shfl_xor_sync(FULLM, wsum, 4, 8);
        wsum = __shfl_sync(FULLM, wsum, 0, 32);
        den = den * scale + wsum;
        acc.x *= scale; acc.y *= scale; acc.z *= scale; acc.w *= scale;
#pragma unroll
        for (int j = 0; j < 8; j++) {
            float wj = __shfl_sync(FULLM, wgt, j, 32);
            __half2 h0 = *(__half2*)&hb[j].x;
            __half2 h1 = *(__half2*)&hb[j].y;
            float2 f0 = __half22float2(h0);
            float2 f1 = __half22float2(h1);
            acc.x = fmaf(wj, f0.x, acc.x);
            acc.y = fmaf(wj, f0.y, acc.y);
            acc.z = fmaf(wj, f1.x, acc.z);
            acc.w = fmaf(wj, f1.y, acc.w);
        }
        m = nm;
    }

    float inv = 1.0f / den;
    __half2 p0 = __floats2half2_rn(acc.x * inv, acc.y * inv);
    __half2 p1 = __floats2half2_rn(acc.z * inv, acc.w * inv);
    uint2 packed = make_uint2(*(unsigned*)&p0, *(unsigned*)&p1);
    *(uint2*)(out + (size_t)node * HID + lane * 4) = packed;
}

// -------- layer-2 wmma GEMM: C = relu(G2@W2+b2), epi: as3/ad3 ---------------
__global__ __launch_bounds__(128) void wmma_gemm128_fused_kernel(
        const __half* __restrict__ A,
        const __half* __restrict__ Wh,
        const float* __restrict__ bias,
        const float* __restrict__ ws3,
        const float* __restrict__ wd3,
        __half* __restrict__ Cout,
        float* __restrict__ as_o,
        float* __restrict__ ad_o, int nPad, int n) {
    __shared__ float s_c[64 * HID];
    int warp = threadIdx.x >> 5;
    int lane = threadIdx.x & 31;
    int row0 = blockIdx.x * 64 + warp * 16;
    if (row0 >= nPad) return;

    wmma::fragment<wmma::accumulator, 16, 16, 16, float> acc[8];
#pragma unroll
    for (int i = 0; i < 8; i++) wmma::fill_fragment(acc[i], 0.f);

#pragma unroll
    for (int k = 0; k < 8; k++) {
        wmma::fragment<wmma::matrix_a, 16, 16, 16, __half, wmma::row_major> a;
        wmma::load_matrix_sync(a, A + (size_t)row0 * HID + k * 16, HID);
#pragma unroll
        for (int nt = 0; nt < 8; nt++) {
            wmma::fragment<wmma::matrix_b, 16, 16, 16, __half, wmma::row_major> b;
            wmma::load_matrix_sync(b, Wh + k * 16 * HID + nt * 16, HID);
            wmma::mma_sync(acc[nt], a, b, acc[nt]);
        }
    }
    float* my = s_c + warp * 16 * HID;
#pragma unroll
    for (int nt = 0; nt < 8; nt++)
        wmma::store_matrix_sync(my + nt * 16, acc[nt], HID, wmma::mem_row_major);
    __syncwarp();

    float4 bv = *(const float4*)(bias + lane * 4);
    float4 sv = *(const float4*)(ws3 + lane * 4);
    float4 dv = *(const float4*)(wd3 + lane * 4);
#pragma unroll
    for (int r = 0; r < 16; r++) {
        int row = row0 + r;
        if (row >= n) break;
        float4 v = *(const float4*)(my + r * HID + lane * 4);
        float ox = fmaxf(v.x + bv.x, 0.f);
        float oy = fmaxf(v.y + bv.y, 0.f);
        float oz = fmaxf(v.z + bv.z, 0.f);
        float ow = fmaxf(v.w + bv.w, 0.f);
        __half2 p0 = __floats2half2_rn(ox, oy);
        __half2 p1 = __floats2half2_rn(oz, ow);
        uint2 packed = make_uint2(*(unsigned*)&p0, *(unsigned*)&p1);
        *(uint2*)(Cout + (size_t)row * HID + lane * 4) = packed;
        float ps = ox * sv.x + oy * sv.y + oz * sv.z + ow * sv.w;
        float pd = ox * dv.x + oy * dv.y + oz * dv.z + ow * dv.w;
#pragma unroll
        for (int o = 16; o > 0; o >>= 1) {
            ps += __shfl_xor_sync(FULLM, ps, o);
            pd += __shfl_xor_sync(FULLM, pd, o);
        }
        if (lane == 0) { as_o[row] = ps; ad_o[row] = pd; }
    }
}

// --------------------------- layer-3 GEMM -----------------------------------
__global__ void gemm16_kernel(const __half* __restrict__ in,
                              const float* __restrict__ W,
                              __half* __restrict__ h, int n) {
    int t = blockIdx.x * blockDim.x + threadIdx.x;
    int node = t >> 4;
    int c = t & 15;
    if (node >= n) return;

    const __half* row = in + (size_t)node * HID;
    float acc = 0.f;
#pragma unroll 8
    for (int k = 0; k < HID; k++)
        acc = fmaf(__half2float(__ldg(row + k)), __ldg(W + k * NC + c), acc);

    h[(size_t)node * NC + c] = __float2half_rn(acc);
}

// ------------- fused aggregation C=16 + pooling (layer 3) -------------------
__global__ void fused_aggr16_pool_kernel(const int* __restrict__ rowptr,
                                         const int* __restrict__ col,
                                         const float* __restrict__ as_v,
                                         const float* __restrict__ ad_v,
                                         const __half* __restrict__ h,
                                         const float* __restrict__ bias,
                                         const int* __restrict__ batch,
                                         float* __restrict__ pool,
                                         float* __restrict__ cnt, int n) {
    int w = (blockIdx.x * blockDim.x + threadIdx.x) >> 5;
    int lane = threadIdx.x & 31;
    int local = lane & 15;
    int node = w * 2 + (lane >> 4);
    int c = local;
    bool active = node < n;

    float advv = active ? __ldg(ad_v + node) : 0.f;
    int beg = active ? __ldg(rowptr + node) : 0;
    int end = active ? __ldg(rowptr + node + 1) : 0;

    const float NEG_INF = __int_as_float(0xFF800000);
    float m = NEG_INF, den = 0.0f, acc = 0.0f;

    for (int i = beg; i < end; i += 8) {
        int sb[8];
#pragma unroll
        for (int j = 0; j < 8; j++) {
            bool act = (i + j) < end;
            sb[j] = __ldg(col + (act ? i + j : beg));
        }
        float hb[8];
#pragma unroll
        for (int j = 0; j < 8; j++)
            hb[j] = __half2float(__ldg(h + (size_t)sb[j] * NC + c));

        bool eact = (local < 8) && (i + local) < end;
        float e = eact ? (__ldg(as_v + sb[local & 7]) + advv) : NEG_INF;
        e = e > 0.f ? e : 0.2f * e;
        float cmax = e;
        cmax = fmaxf(cmax, __shfl_xor_sync(FULLM, cmax, 1, 8));
        cmax = fmaxf(cmax, __shfl_xor_sync(FULLM, cmax, 2, 8));
        cmax = fmaxf(cmax, __shfl_xor_sync(FULLM, cmax, 4, 8));
        cmax = __shfl_sync(FULLM, cmax, 0, 16);
        float nm = fmaxf(m, cmax);
        float scale = __expf(m - nm);
        float wgt = __expf(e - nm);
        float wsum = wgt;
        wsum += __shfl_xor_sync(FULLM, wsum, 1, 8);
        wsum += __shfl_xor_sync(FULLM, wsum, 2, 8);
        wsum += __shfl_xor_sync(FULLM, wsum, 4, 8);
        wsum = __shfl_sync(FULLM, wsum, 0, 16);
        den = den * scale + wsum;
        acc *= scale;
#pragma unroll
        for (int j = 0; j < 8; j++) {
            float wj = __shfl_sync(FULLM, wgt, j, 16);
            acc = fmaf(wj, hb[j], acc);
        }
        m = nm;
    }

    if (active) {
        float val = fmaxf(acc / den + __ldg(bias + c), 0.f);
        int g = __ldg(batch + node);
        atomicAdd(&pool[g * NC + c], val);
        if (c == 0) atomicAdd(&cnt[g], 1.0f);
    }
}

__global__ void finalize_kernel(const float* __restrict__ pool,
                                const float* __restrict__ cnt,
                                float* __restrict__ outp) {
    int t = blockIdx.x * blockDim.x + threadIdx.x;
    if (t >= NG * NC) return;
    int g = t >> 4;
    float v = pool[t] / fmaxf(cnt[g], 1.0f);
    outp[t] = 1.0f / (1.0f + expf(-v));
}

// ---------------------------------------------------------------------------

extern "C" void kernel_launch(void* const* d_in, const int* in_sizes, int n_in,
                              void* d_out, int out_size) {
    const float* x     = (const float*)d_in[0];
    const int*   ei    = (const int*)  d_in[1];
    const int*   batch = (const int*)  d_in[3];
    const float* W1  = (const float*)d_in[4];
    const float* as1 = (const float*)d_in[5];
    const float* ad1 = (const float*)d_in[6];
    const float* b1  = (const float*)d_in[7];
    const float* W2  = (const float*)d_in[8];
    const float* as2 = (const float*)d_in[9];
    const float* ad2 = (const float*)d_in[10];
    const float* b2  = (const float*)d_in[11];
    const float* W3  = (const float*)d_in[12];
    const float* as3 = (const float*)d_in[13];
    const float* ad3 = (const float*)d_in[14];
    const float* b3  = (const float*)d_in[15];
    float* out = (float*)d_out;

    int n    = in_sizes[0] / F_IN;
    int E    = in_sizes[1] / 2;
    int Etot = E + n;
    const int* src = ei;
    const int* dst = ei + E;

    float *pas, *pad, *ppool, *pcnt, *pG1;
    float *pws1, *pwd1, *pws2, *pwd2, *pws3, *pwd3;
    __half *pA, *pG2, *pC, *ph16, *pWh;
    int *pdeg, *prow, *pcur, *pcol, *ppart;
    cudaGetSymbolAddress((void**)&pA,    g_A);
    cudaGetSymbolAddress((void**)&pG2,   g_G2);
    cudaGetSymbolAddress((void**)&pC,    g_C);
    cudaGetSymbolAddress((void**)&ph16,  g_h16);
    cudaGetSymbolAddress((void**)&pWh,   g_Wh);
    cudaGetSymbolAddress((void**)&pG1,   g_G1);
    cudaGetSymbolAddress((void**)&pas,   g_as);
    cudaGetSymbolAddress((void**)&pad,   g_ad);
    cudaGetSymbolAddress((void**)&pws1,  g_ws1);
    cudaGetSymbolAddress((void**)&pwd1,  g_wd1);
    cudaGetSymbolAddress((void**)&pws2,  g_ws2);
    cudaGetSymbolAddress((void**)&pwd2,  g_wd2);
    cudaGetSymbolAddress((void**)&pws3,  g_ws3);
    cudaGetSymbolAddress((void**)&pwd3,  g_wd3);
    cudaGetSymbolAddress((void**)&ppool, g_pool);
    cudaGetSymbolAddress((void**)&pcnt,  g_cnt);
    cudaGetSymbolAddress((void**)&pdeg,  g_deg);
    cudaGetSymbolAddress((void**)&prow,  g_rowptr);
    cudaGetSymbolAddress((void**)&pcur,  g_cursor);
    cudaGetSymbolAddress((void**)&pcol,  g_col);
    cudaGetSymbolAddress((void**)&ppart, g_partial);

    const int TB = 256;
    int nPad     = (n + 127) & ~127;
    int nb       = (n + SCAN_CHUNK - 1) / SCAN_CHUNK;
    int gN       = (n + TB - 1) / TB;
    int gEdge4   = (Etot + TB * 4 - 1) / (TB * 4);
    int warps128 = (n + 7) / 8;
    int gGemmK11 = (warps128 * 32 + TB - 1) / TB;
    int gWmma    = nPad / 64;
    int gNodeWarp= (n * 32 + TB - 1) / TB;
    int gHalfWarp= (((n + 1) / 2) * 32 + TB - 1) / TB;
    int gGemm16  = (n * NC + TB - 1) / TB;
    int gPool    = (NG * NC + TB - 1) / TB;

    // ---- CSR build + precompute ----
    zero_deg_kernel<<<gN, TB>>>(pdeg, n, ppool, pcnt);
    precompute_kernel<<<3 + HID, HID>>>(W1, as1, ad1, W2, as2, ad2, W3, as3, ad3,
                                        pws1, pwd1, pws2, pwd2, pws3, pwd3, pWh);
    count_deg_kernel<<<gEdge4, TB>>>(dst, E, Etot, pdeg);
    scan_partial_kernel<<<nb, 256>>>(pdeg, ppart, n);
    scan_offsets_kernel<<<1, 64>>>(ppart, nb);
    scan_final_kernel<<<nb, 256>>>(pdeg, ppart, prow, pcur, n);
    scatter_kernel<<<gEdge4, TB>>>(src, dst, E, Etot, pcur, pcol);

    // ---- layer 1 ----
    asad1_kernel<<<gN, TB>>>(x, pws1, pwd1, pas, pad, n);
    aggr11_kernel<<<gHalfWarp, TB>>>(prow, pcol, pas, pad, x, pG1, n);
    gemmK11_kernel<<<gGemmK11, TB>>>(pG1, W1, b1, pws2, pwd2, pA, pas, pad, n);

    // ---- layer 2 ----
    aggr128_raw_kernel<<<gNodeWarp, TB>>>(prow, pcol, pas, pad, pA, pG2, n);
    wmma_gemm128_fused_kernel<<<gWmma, 128>>>(pG2, pWh, b2, pws3, pwd3, pC,
                                              pas, pad, nPad, n);

    // ---- layer 3 + pooling ----
    gemm16_kernel<<<gGemm16, TB>>>(pC, W3, ph16, n);
    fused_aggr16_pool_kernel<<<gHalfWarp, TB>>>(prow, pcol, pas, pad, ph16, b3,
                                                batch, ppool, pcnt, n);
    finalize_kernel<<<gPool, TB>>>(ppool, pcnt, out);
}

// round 9
// speedup vs baseline: 2.5692x; 1.1554x over previous
#include <cuda_runtime.h>
#include <cuda_fp16.h>
#include <mma.h>
#include <math.h>
#include <stdint.h>

using namespace nvcuda;

// ---------------------------------------------------------------------------
// GAT (3 layers) + mean pool + sigmoid.
// - Layer 1 aggregates RAW x (11-dim) via linearity; logits from x·(W@a).
// - Layer-2 GEMM on wmma; layer-3 GEMM fused into the same kernel via a
//   second smem-staged wmma pass (C never hits global memory).
// - Lane-split online softmax + chunk rescale in all aggregations.
// - Fused setup / count kernels; scan offsets folded into scan_final.
// ---------------------------------------------------------------------------

#define NMAX   50000
#define NPAD   50048
#define EMAX   800000
#define ETOTMX (EMAX + NMAX)
#define HID    128
#define F_IN   11
#define NC     16
#define NG     64
#define SCAN_CHUNK 1024
#define FULLM  0xffffffffu

__device__ __align__(16) __half g_A[NPAD * HID];    // layer-1 output (fp16)
__device__ __align__(16) __half g_G2[NPAD * HID];   // aggr of A (wmma input)
__device__ __align__(16) __half g_h16[NPAD * NC];   // h3 = relu(C)@W3 (fp16)
__device__ __align__(16) __half g_Wh[HID * HID];    // W2 fp16
__device__ __align__(16) __half g_Wh3[HID * NC];    // W3 fp16
__device__ float  g_G1[NMAX * F_IN];                // aggr of x (fp32)
__device__ float  g_as[NMAX];
__device__ float  g_ad[NMAX];
__device__ float  g_ws1[F_IN],  g_wd1[F_IN];
__device__ float  g_ws2[HID],   g_wd2[HID];
__device__ float  g_ws3[HID],   g_wd3[HID];
__device__ float  g_pool[NG * NC];
__device__ float  g_cnt[NG];
__device__ int    g_deg[NMAX];
__device__ int    g_rowptr[NMAX + 1];
__device__ int    g_cursor[NMAX];
__device__ int    g_partial[128];
__device__ int    g_col[ETOTMX];

// --------------------------- setup: zeroing + precompute --------------------
// block ranges: [0,gN): deg/pool/cnt zero; gN: ws2/wd2 + ws3/wd3;
// gN+1: ws1/wd1; [gN+2,gN+66): W2->fp16; [gN+66,gN+74): W3->fp16.
__global__ void setup_kernel(const float* __restrict__ W1,
                             const float* __restrict__ a_s1, const float* __restrict__ a_d1,
                             const float* __restrict__ W2,
                             const float* __restrict__ a_s2, const float* __restrict__ a_d2,
                             const float* __restrict__ W3,
                             const float* __restrict__ a_s3, const float* __restrict__ a_d3,
                             float* __restrict__ ws1, float* __restrict__ wd1,
                             float* __restrict__ ws2, float* __restrict__ wd2,
                             float* __restrict__ ws3, float* __restrict__ wd3,
                             __half* __restrict__ Wh, __half* __restrict__ Wh3,
                             int* __restrict__ deg,
                             float* __restrict__ pool, float* __restrict__ cnt,
                             int n, int nodeBlocks) {
    int b = blockIdx.x, t = threadIdx.x;
    if (b < nodeBlocks) {
        int i = b * 256 + t;
        if (i < n) deg[i] = 0;
        if (i < NG * NC) pool[i] = 0.f;
        if (i < NG) cnt[i] = 0.f;
    } else if (b == nodeBlocks) {
        if (t < HID) {
            float s = 0.f, d = 0.f;
            for (int c = 0; c < HID; c++) {
                float w = __ldg(W2 + t * HID + c);
                s = fmaf(w, __ldg(a_s2 + c), s);
                d = fmaf(w, __ldg(a_d2 + c), d);
            }
            ws2[t] = s; wd2[t] = d;
        } else {
            int k = t - HID;
            float s = 0.f, d = 0.f;
            for (int c = 0; c < NC; c++) {
                float w = __ldg(W3 + k * NC + c);
                s = fmaf(w, __ldg(a_s3 + c), s);
                d = fmaf(w, __ldg(a_d3 + c), d);
            }
            ws3[k] = s; wd3[k] = d;
        }
    } else if (b == nodeBlocks + 1) {
        if (t < F_IN) {
            float s = 0.f, d = 0.f;
            for (int c = 0; c < HID; c++) {
                float w = __ldg(W1 + t * HID + c);
                s = fmaf(w, __ldg(a_s1 + c), s);
                d = fmaf(w, __ldg(a_d1 + c), d);
            }
            ws1[t] = s; wd1[t] = d;
        }
    } else if (b < nodeBlocks + 66) {
        int i = (b - nodeBlocks - 2) * 256 + t;
        if (i < HID * HID) Wh[i] = __float2half_rn(__ldg(W2 + i));
    } else {
        int i = (b - nodeBlocks - 66) * 256 + t;
        if (i < HID * NC) Wh3[i] = __float2half_rn(__ldg(W3 + i));
    }
}

// ----------------- count_deg + layer-1 logits (fused) -----------------------
__global__ void count_asad_kernel(const int* __restrict__ dst, int E, int Etot,
                                  int* __restrict__ deg,
                                  const float* __restrict__ x,
                                  const float* __restrict__ ws1,
                                  const float* __restrict__ wd1,
                                  float* __restrict__ as_o, float* __restrict__ ad_o,
                                  int n, int edgeBlocks) {
    int b = blockIdx.x, tt = threadIdx.x;
    if (b < edgeBlocks) {
        int t = (b * 256 + tt) * 4;
        int d[4];
#pragma unroll
        for (int j = 0; j < 4; j++) {
            int i = t + j;
            d[j] = (i < Etot) ? (i < E ? __ldg(dst + i) : (i - E)) : -1;
        }
#pragma unroll
        for (int j = 0; j < 4; j++)
            if (d[j] >= 0) atomicAdd(&deg[d[j]], 1);
    } else {
        int i = (b - edgeBlocks) * 256 + tt;
        if (i >= n) return;
        const float* row = x + (size_t)i * F_IN;
        float s = 0.f, d = 0.f;
#pragma unroll
        for (int k = 0; k < F_IN; k++) {
            float v = __ldg(row + k);
            s = fmaf(v, __ldg(ws1 + k), s);
            d = fmaf(v, __ldg(wd1 + k), d);
        }
        as_o[i] = s; ad_o[i] = d;
    }
}

// --------------------------- scan (2 kernels) -------------------------------
__global__ void scan_partial_kernel(const int* __restrict__ deg,
                                    int* __restrict__ partial, int n) {
    __shared__ int ws[8];
    int base = blockIdx.x * SCAN_CHUNK + threadIdx.x * 4;
    int s = 0;
#pragma unroll
    for (int j = 0; j < 4; j++) {
        int i = base + j;
        if (i < n) s += __ldg(deg + i);
    }
#pragma unroll
    for (int o = 16; o > 0; o >>= 1) s += __shfl_xor_sync(FULLM, s, o);
    int lane = threadIdx.x & 31, wid = threadIdx.x >> 5;
    if (lane == 0) ws[wid] = s;
    __syncthreads();
    if (wid == 0 && lane < 8) {
        int v = ws[lane];
#pragma unroll
        for (int o = 4; o > 0; o >>= 1) v += __shfl_xor_sync(0xffu, v, o);
        if (lane == 0) partial[blockIdx.x] = v;
    }
}

// local scan + offset derived in-block from raw partials
__global__ void scan_final_kernel(const int* __restrict__ deg,
                                  const int* __restrict__ partial,
                                  int* __restrict__ rowptr,
                                  int* __restrict__ cursor, int n, int nb) {
    __shared__ int ws[8];
    __shared__ int w2s[2];
    __shared__ int s_off;
    int t = threadIdx.x, lane = t & 31, wid = t >> 5;

    // block offset = sum of partial[0..bid)
    int pv = 0;
    if (t < 64 && t < blockIdx.x && t < nb) pv = __ldg(partial + t);
    if (t < 64) {
#pragma unroll
        for (int o = 16; o > 0; o >>= 1) pv += __shfl_xor_sync(FULLM, pv, o);
        if (lane == 0) w2s[wid] = pv;
    }
    __syncthreads();
    if (t == 0) s_off = w2s[0] + w2s[1];

    int base = blockIdx.x * SCAN_CHUNK + t * 4;
    int v[4];
#pragma unroll
    for (int j = 0; j < 4; j++) {
        int i = base + j;
        v[j] = (i < n) ? __ldg(deg + i) : 0;
    }
    int tot = v[0] + v[1] + v[2] + v[3];
    int x = tot;
#pragma unroll
    for (int o = 1; o < 32; o <<= 1) {
        int u = __shfl_up_sync(FULLM, x, o);
        if (lane >= o) x += u;
    }
    int warp_excl = x - tot;
    if (lane == 31) ws[wid] = x;
    __syncthreads();
    if (wid == 0) {
        int val = (lane < 8) ? ws[lane] : 0;
#pragma unroll
        for (int o = 1; o < 8; o <<= 1) {
            int u = __shfl_up_sync(FULLM, val, o);
            if (lane >= o) val += u;
        }
        if (lane < 8) ws[lane] = val;
    }
    __syncthreads();
    int off = s_off + (wid > 0 ? ws[wid - 1] : 0) + warp_excl;
    int run = off;
#pragma unroll
    for (int j = 0; j < 4; j++) {
        run += v[j];
        int i = base + j;
        if (i < n) { rowptr[i + 1] = run; cursor[i] = run - v[j]; }
    }
    if (blockIdx.x == 0 && t == 0) rowptr[0] = 0;
}

__global__ void scatter_kernel(const int* __restrict__ src, const int* __restrict__ dst,
                               int E, int Etot,
                               int* __restrict__ cursor, int* __restrict__ col) {
    int t = (blockIdx.x * blockDim.x + threadIdx.x) * 4;
    int s[4], d[4];
#pragma unroll
    for (int j = 0; j < 4; j++) {
        int i = t + j;
        bool act = i < Etot;
        s[j] = act ? (i < E ? __ldg(src + i) : (i - E)) : 0;
        d[j] = act ? (i < E ? __ldg(dst + i) : (i - E)) : -1;
    }
#pragma unroll
    for (int j = 0; j < 4; j++) {
        if (d[j] >= 0) {
            int pos = atomicAdd(&cursor[d[j]], 1);
            col[pos] = s[j];
        }
    }
}

// ------------------ layer-1 aggregation of raw x (11-dim) -------------------
__global__ void aggr11_kernel(const int* __restrict__ rowptr,
                              const int* __restrict__ col,
                              const float* __restrict__ as_v,
                              const float* __restrict__ ad_v,
                              const float* __restrict__ x,
                              float* __restrict__ G, int n) {
    int w = (blockIdx.x * blockDim.x + threadIdx.x) >> 5;
    int lane = threadIdx.x & 31;
    int local = lane & 15;
    int node = w * 2 + (lane >> 4);
    int c = local;
    if (node >= n) return;

    float advv = __ldg(ad_v + node);
    int beg = __ldg(rowptr + node);
    int end = __ldg(rowptr + node + 1);

    const float NEG_INF = __int_as_float(0xFF800000);
    float m = NEG_INF, den = 0.0f, acc = 0.0f;

    for (int i = beg; i < end; i += 8) {
        int sb[8];
#pragma unroll
        for (int j = 0; j < 8; j++) {
            bool act = (i + j) < end;
            sb[j] = __ldg(col + (act ? i + j : beg));
        }
        float xb[8];
#pragma unroll
        for (int j = 0; j < 8; j++)
            xb[j] = (c < F_IN) ? __ldg(x + (size_t)sb[j] * F_IN + c) : 0.f;

        bool eact = (local < 8) && (i + local) < end;
        float e = eact ? (__ldg(as_v + sb[local & 7]) + advv) : NEG_INF;
        e = e > 0.f ? e : 0.2f * e;
        float cmax = e;
        cmax = fmaxf(cmax, __shfl_xor_sync(FULLM, cmax, 1, 8));
        cmax = fmaxf(cmax, __shfl_xor_sync(FULLM, cmax, 2, 8));
        cmax = fmaxf(cmax, __shfl_xor_sync(FULLM, cmax, 4, 8));
        cmax = __shfl_sync(FULLM, cmax, 0, 16);
        float nm = fmaxf(m, cmax);
        float scale = __expf(m - nm);
        float wgt = __expf(e - nm);
        float wsum = wgt;
        wsum += __shfl_xor_sync(FULLM, wsum, 1, 8);
        wsum += __shfl_xor_sync(FULLM, wsum, 2, 8);
        wsum += __shfl_xor_sync(FULLM, wsum, 4, 8);
        wsum = __shfl_sync(FULLM, wsum, 0, 16);
        den = den * scale + wsum;
        acc *= scale;
#pragma unroll
        for (int j = 0; j < 8; j++) {
            float wj = __shfl_sync(FULLM, wgt, j, 16);
            acc = fmaf(wj, xb[j], acc);
        }
        m = nm;
    }
    if (c < F_IN) G[(size_t)node * F_IN + c] = acc / den;
}

// --------------- layer-1 GEMM: A = relu(G1@W1+b1), epi: as2/ad2 -------------
__global__ void gemmK11_kernel(const float* __restrict__ in,
                               const float* __restrict__ W,
                               const float* __restrict__ bias,
                               const float* __restrict__ ws2,
                               const float* __restrict__ wd2,
                               __half* __restrict__ A,
                               float* __restrict__ as_o,
                               float* __restrict__ ad_o, int n) {
    int w    = (blockIdx.x * blockDim.x + threadIdx.x) >> 5;
    int lane = threadIdx.x & 31;
    int node0 = w * 8;
    if (node0 >= n) return;

    int nid[8];
#pragma unroll
    for (int i = 0; i < 8; i++) {
        int nn = node0 + i;
        nid[i] = nn < n ? nn : (n - 1);
    }

    float4 bv = *(const float4*)(bias + lane * 4);
    float4 acc[8];
#pragma unroll
    for (int i = 0; i < 8; i++) acc[i] = bv;

#pragma unroll
    for (int k = 0; k < F_IN; k++) {
        float4 wv = *(const float4*)(W + k * HID + lane * 4);
#pragma unroll
        for (int i = 0; i < 8; i++) {
            float a = __ldg(in + (size_t)nid[i] * F_IN + k);
            acc[i].x = fmaf(a, wv.x, acc[i].x);
            acc[i].y = fmaf(a, wv.y, acc[i].y);
            acc[i].z = fmaf(a, wv.z, acc[i].z);
            acc[i].w = fmaf(a, wv.w, acc[i].w);
        }
    }

    float4 sv = *(const float4*)(ws2 + lane * 4);
    float4 dv = *(const float4*)(wd2 + lane * 4);

#pragma unroll
    for (int i = 0; i < 8; i++) {
        float ox = fmaxf(acc[i].x, 0.f);
        float oy = fmaxf(acc[i].y, 0.f);
        float oz = fmaxf(acc[i].z, 0.f);
        float ow = fmaxf(acc[i].w, 0.f);
        __half2 p0 = __floats2half2_rn(ox, oy);
        __half2 p1 = __floats2half2_rn(oz, ow);
        uint2 packed = make_uint2(*(unsigned*)&p0, *(unsigned*)&p1);
        *(uint2*)(A + (size_t)nid[i] * HID + lane * 4) = packed;

        float ps = ox * sv.x + oy * sv.y + oz * sv.z + ow * sv.w;
        float pd = ox * dv.x + oy * dv.y + oz * dv.z + ow * dv.w;
#pragma unroll
        for (int o = 16; o > 0; o >>= 1) {
            ps += __shfl_xor_sync(FULLM, ps, o);
            pd += __shfl_xor_sync(FULLM, pd, o);
        }
        if (lane == 0) { as_o[nid[i]] = ps; ad_o[nid[i]] = pd; }
    }
}

// ------------------ raw softmax aggregation, C=128 (fp16) -------------------
__global__ void aggr128_raw_kernel(const int* __restrict__ rowptr,
                                   const int* __restrict__ col,
                                   const float* __restrict__ as_v,
                                   const float* __restrict__ ad_v,
                                   const __half* __restrict__ h,
                                   __half* __restrict__ out, int n) {
    int node = (blockIdx.x * blockDim.x + threadIdx.x) >> 5;
    if (node >= n) return;
    int lane = threadIdx.x & 31;

    float advv = __ldg(ad_v + node);
    int beg = __ldg(rowptr + node);
    int end = __ldg(rowptr + node + 1);

    const float NEG_INF = __int_as_float(0xFF800000);
    float m = NEG_INF, den = 0.0f;
    float4 acc = make_float4(0.f, 0.f, 0.f, 0.f);

    for (int i = beg; i < end; i += 8) {
        int sb[8];
#pragma unroll
        for (int j = 0; j < 8; j++) {
            bool act = (i + j) < end;
            sb[j] = __ldg(col + (act ? i + j : beg));
        }
        uint2 hb[8];
#pragma unroll
        for (int j = 0; j < 8; j++)
            hb[j] = *(const uint2*)(h + (size_t)sb[j] * HID + lane * 4);

        bool eact = (lane < 8) && (i + lane) < end;
        float e = eact ? (__ldg(as_v + sb[lane & 7]) + advv) : NEG_INF;
        e = e > 0.f ? e : 0.2f * e;
        float cmax = e;
        cmax = fmaxf(cmax, __shfl_xor_sync(FULLM, cmax, 1, 8));
        cmax = fmaxf(cmax, __shfl_xor_sync(FULLM, cmax, 2, 8));
        cmax = fmaxf(cmax, __shfl_xor_sync(FULLM, cmax, 4, 8));
        cmax = __shfl_sync(FULLM, cmax, 0, 32);
        float nm = fmaxf(m, cmax);
        float scale = __expf(m - nm);
        float wgt = __expf(e - nm);
        float wsum = wgt;
        wsum += __shfl_xor_sync(FULLM, wsum, 1, 8);
        wsum += __shfl_xor_sync(FULLM, wsum, 2, 8);
        wsum += __shfl_xor_sync(FULLM, wsum, 4, 8);
        wsum = __shfl_sync(FULLM, wsum, 0, 32);
        den = den * scale + wsum;
        acc.x *= scale; acc.y *= scale; acc.z *= scale; acc.w *= scale;
#pragma unroll
        for (int j = 0; j < 8; j++) {
            float wj = __shfl_sync(FULLM, wgt, j, 32);
            __half2 h0 = *(__half2*)&hb[j].x;
            __half2 h1 = *(__half2*)&hb[j].y;
            float2 f0 = __half22float2(h0);
            float2 f1 = __half22float2(h1);
            acc.x = fmaf(wj, f0.x, acc.x);
            acc.y = fmaf(wj, f0.y, acc.y);
            acc.z = fmaf(wj, f1.x, acc.z);
            acc.w = fmaf(wj, f1.y, acc.w);
        }
        m = nm;
    }

    float inv = 1.0f / den;
    __half2 p0 = __floats2half2_rn(acc.x * inv, acc.y * inv);
    __half2 p1 = __floats2half2_rn(acc.z * inv, acc.w * inv);
    uint2 packed = make_uint2(*(unsigned*)&p0, *(unsigned*)&p1);
    *(uint2*)(out + (size_t)node * HID + lane * 4) = packed;
}

// ---- layer-2 wmma GEMM + fused layer-3 GEMM --------------------------------
// stage 1: Cr = relu(G2@W2 + b2); epilogue: as3/ad3 dots, stage Cr fp16 in smem
// stage 2: h16 = Cr @ W3 (second wmma pass; Cr never hits global)
__global__ __launch_bounds__(128) void wmma_fused_kernel(
        const __half* __restrict__ A,
        const __half* __restrict__ Wh,    // W2 fp16
        const __half* __restrict__ Wh3,   // W3 fp16 [128,16]
        const float* __restrict__ bias,
        const float* __restrict__ ws3,
        const float* __restrict__ wd3,
        __half* __restrict__ h16,
        float* __restrict__ as_o,
        float* __restrict__ ad_o, int nPad, int n) {
    __shared__ float  s_c[64 * HID];      // 32 KB
    __shared__ __half s_ch[64 * HID];     // 16 KB
    int warp = threadIdx.x >> 5;
    int lane = threadIdx.x & 31;
    int row0 = blockIdx.x * 64 + warp * 16;
    if (row0 >= nPad) return;

    wmma::fragment<wmma::accumulator, 16, 16, 16, float> acc[8];
#pragma unroll
    for (int i = 0; i < 8; i++) wmma::fill_fragment(acc[i], 0.f);

#pragma unroll
    for (int k = 0; k < 8; k++) {
        wmma::fragment<wmma::matrix_a, 16, 16, 16, __half, wmma::row_major> a;
        wmma::load_matrix_sync(a, A + (size_t)row0 * HID + k * 16, HID);
#pragma unroll
        for (int nt = 0; nt < 8; nt++) {
            wmma::fragment<wmma::matrix_b, 16, 16, 16, __half, wmma::row_major> b;
            wmma::load_matrix_sync(b, Wh + k * 16 * HID + nt * 16, HID);
            wmma::mma_sync(acc[nt], a, b, acc[nt]);
        }
    }
    float*  my  = s_c  + warp * 16 * HID;
    __half* myh = s_ch + warp * 16 * HID;
#pragma unroll
    for (int nt = 0; nt < 8; nt++)
        wmma::store_matrix_sync(my + nt * 16, acc[nt], HID, wmma::mem_row_major);
    __syncwarp();

    float4 bv = *(const float4*)(bias + lane * 4);
    float4 sv = *(const float4*)(ws3 + lane * 4);
    float4 dv = *(const float4*)(wd3 + lane * 4);
#pragma unroll
    for (int r = 0; r < 16; r++) {
        int row = row0 + r;
        float4 v = *(const float4*)(my + r * HID + lane * 4);
        float ox = fmaxf(v.x + bv.x, 0.f);
        float oy = fmaxf(v.y + bv.y, 0.f);
        float oz = fmaxf(v.z + bv.z, 0.f);
        float ow = fmaxf(v.w + bv.w, 0.f);
        __half2 p0 = __floats2half2_rn(ox, oy);
        __half2 p1 = __floats2half2_rn(oz, ow);
        uint2 packed = make_uint2(*(unsigned*)&p0, *(unsigned*)&p1);
        *(uint2*)(myh + r * HID + lane * 4) = packed;   // stage fp16 C in smem
        if (row < n) {
            float ps = ox * sv.x + oy * sv.y + oz * sv.z + ow * sv.w;
            float pd = ox * dv.x + oy * dv.y + oz * dv.z + ow * dv.w;
#pragma unroll
            for (int o = 16; o > 0; o >>= 1) {
                ps += __shfl_xor_sync(FULLM, ps, o);
                pd += __shfl_xor_sync(FULLM, pd, o);
            }
            if (lane == 0) { as_o[row] = ps; ad_o[row] = pd; }
        }
    }
    __syncwarp();

    // stage 2: h16[row0..row0+16) = Cr @ W3
    wmma::fragment<wmma::accumulator, 16, 16, 16, float> acc3;
    wmma::fill_fragment(acc3, 0.f);
#pragma unroll
    for (int k = 0; k < 8; k++) {
        wmma::fragment<wmma::matrix_a, 16, 16, 16, __half, wmma::row_major> a;
        wmma::load_matrix_sync(a, myh + k * 16, HID);
        wmma::fragment<wmma::matrix_b, 16, 16, 16, __half, wmma::row_major> b;
        wmma::load_matrix_sync(b, Wh3 + k * 16 * NC, NC);
        wmma::mma_sync(acc3, a, b, acc3);
    }
    // store as fp32 frag -> convert via smem staging (reuse my)
    wmma::store_matrix_sync(my, acc3, NC, wmma::mem_row_major);
    __syncwarp();
    // 16 rows x 16 cols fp32 in my[0..256) -> fp16 global
    // each lane handles 8 elems (256/32)
#pragma unroll
    for (int q = 0; q < 8; q++) {
        int idx = q * 32 + lane;           // 0..255
        float fv = my[idx];
        h16[(size_t)row0 * NC + idx] = __float2half_rn(fv);
    }
}

// ------------- fused aggregation C=16 + pooling (layer 3) -------------------
__global__ void fused_aggr16_pool_kernel(const int* __restrict__ rowptr,
                                         const int* __restrict__ col,
                                         const float* __restrict__ as_v,
                                         const float* __restrict__ ad_v,
                                         const __half* __restrict__ h,
                                         const float* __restrict__ bias,
                                         const int* __restrict__ batch,
                                         float* __restrict__ pool,
                                         float* __restrict__ cnt, int n) {
    int w = (blockIdx.x * blockDim.x + threadIdx.x) >> 5;
    int lane = threadIdx.x & 31;
    int local = lane & 15;
    int node = w * 2 + (lane >> 4);
    int c = local;
    bool active = node < n;

    float advv = active ? __ldg(ad_v + node) : 0.f;
    int beg = active ? __ldg(rowptr + node) : 0;
    int end = active ? __ldg(rowptr + node + 1) : 0;

    const float NEG_INF = __int_as_float(0xFF800000);
    float m = NEG_INF, den = 0.0f, acc = 0.0f;

    for (int i = beg; i < end; i += 8) {
        int sb[8];
#pragma unroll
        for (int j = 0; j < 8; j++) {
            bool act = (i + j) < end;
            sb[j] = __ldg(col + (act ? i + j : beg));
        }
        float hb[8];
#pragma unroll
        for (int j = 0; j < 8; j++)
            hb[j] = __half2float(__ldg(h + (size_t)sb[j] * NC + c));

        bool eact = (local < 8) && (i + local) < end;
        float e = eact ? (__ldg(as_v + sb[local & 7]) + advv) : NEG_INF;
        e = e > 0.f ? e : 0.2f * e;
        float cmax = e;
        cmax = fmaxf(cmax, __shfl_xor_sync(FULLM, cmax, 1, 8));
        cmax = fmaxf(cmax, __shfl_xor_sync(FULLM, cmax, 2, 8));
        cmax = fmaxf(cmax, __shfl_xor_sync(FULLM, cmax, 4, 8));
        cmax = __shfl_sync(FULLM, cmax, 0, 16);
        float nm = fmaxf(m, cmax);
        float scale = __expf(m - nm);
        float wgt = __expf(e - nm);
        float wsum = wgt;
        wsum += __shfl_xor_sync(FULLM, wsum, 1, 8);
        wsum += __shfl_xor_sync(FULLM, wsum, 2, 8);
        wsum += __shfl_xor_sync(FULLM, wsum, 4, 8);
        wsum = __shfl_sync(FULLM, wsum, 0, 16);
        den = den * scale + wsum;
        acc *= scale;
#pragma unroll
        for (int j = 0; j < 8; j++) {
            float wj = __shfl_sync(FULLM, wgt, j, 16);
            acc = fmaf(wj, hb[j], acc);
        }
        m = nm;
    }

    if (active) {
        float val = fmaxf(acc / den + __ldg(bias + c), 0.f);
        int g = __ldg(batch + node);
        atomicAdd(&pool[g * NC + c], val);
        if (c == 0) atomicAdd(&cnt[g], 1.0f);
    }
}

__global__ void finalize_kernel(const float* __restrict__ pool,
                                const float* __restrict__ cnt,
                                float* __restrict__ outp) {
    int t = blockIdx.x * blockDim.x + threadIdx.x;
    if (t >= NG * NC) return;
    int g = t >> 4;
    float v = pool[t] / fmaxf(cnt[g], 1.0f);
    outp[t] = 1.0f / (1.0f + expf(-v));
}

// ---------------------------------------------------------------------------

extern "C" void kernel_launch(void* const* d_in, const int* in_sizes, int n_in,
                              void* d_out, int out_size) {
    const float* x     = (const float*)d_in[0];
    const int*   ei    = (const int*)  d_in[1];
    const int*   batch = (const int*)  d_in[3];
    const float* W1  = (const float*)d_in[4];
    const float* as1 = (const float*)d_in[5];
    const float* ad1 = (const float*)d_in[6];
    const float* b1  = (const float*)d_in[7];
    const float* W2  = (const float*)d_in[8];
    const float* as2 = (const float*)d_in[9];
    const float* ad2 = (const float*)d_in[10];
    const float* b2  = (const float*)d_in[11];
    const float* W3  = (const float*)d_in[12];
    const float* as3 = (const float*)d_in[13];
    const float* ad3 = (const float*)d_in[14];
    const float* b3  = (const float*)d_in[15];
    float* out = (float*)d_out;

    int n    = in_sizes[0] / F_IN;
    int E    = in_sizes[1] / 2;
    int Etot = E + n;
    const int* src = ei;
    const int* dst = ei + E;

    float *pas, *pad, *ppool, *pcnt, *pG1;
    float *pws1, *pwd1, *pws2, *pwd2, *pws3, *pwd3;
    __half *pA, *pG2, *ph16, *pWh, *pWh3;
    int *pdeg, *prow, *pcur, *pcol, *ppart;
    cudaGetSymbolAddress((void**)&pA,    g_A);
    cudaGetSymbolAddress((void**)&pG2,   g_G2);
    cudaGetSymbolAddress((void**)&ph16,  g_h16);
    cudaGetSymbolAddress((void**)&pWh,   g_Wh);
    cudaGetSymbolAddress((void**)&pWh3,  g_Wh3);
    cudaGetSymbolAddress((void**)&pG1,   g_G1);
    cudaGetSymbolAddress((void**)&pas,   g_as);
    cudaGetSymbolAddress((void**)&pad,   g_ad);
    cudaGetSymbolAddress((void**)&pws1,  g_ws1);
    cudaGetSymbolAddress((void**)&pwd1,  g_wd1);
    cudaGetSymbolAddress((void**)&pws2,  g_ws2);
    cudaGetSymbolAddress((void**)&pwd2,  g_wd2);
    cudaGetSymbolAddress((void**)&pws3,  g_ws3);
    cudaGetSymbolAddress((void**)&pwd3,  g_wd3);
    cudaGetSymbolAddress((void**)&ppool, g_pool);
    cudaGetSymbolAddress((void**)&pcnt,  g_cnt);
    cudaGetSymbolAddress((void**)&pdeg,  g_deg);
    cudaGetSymbolAddress((void**)&prow,  g_rowptr);
    cudaGetSymbolAddress((void**)&pcur,  g_cursor);
    cudaGetSymbolAddress((void**)&pcol,  g_col);
    cudaGetSymbolAddress((void**)&ppart, g_partial);

    const int TB = 256;
    int nPad     = (n + 127) & ~127;
    int nb       = (n + SCAN_CHUNK - 1) / SCAN_CHUNK;
    int gN       = (n + TB - 1) / TB;
    int gEdge4   = (Etot + TB * 4 - 1) / (TB * 4);
    int warps128 = (n + 7) / 8;
    int gGemmK11 = (warps128 * 32 + TB - 1) / TB;
    int gWmma    = nPad / 64;
    int gNodeWarp= (n * 32 + TB - 1) / TB;
    int gHalfWarp= (((n + 1) / 2) * 32 + TB - 1) / TB;
    int gPool    = (NG * NC + TB - 1) / TB;

    // ---- setup: zeroing + W@a matvecs + fp16 weight conversions ----
    setup_kernel<<<gN + 74, TB>>>(W1, as1, ad1, W2, as2, ad2, W3, as3, ad3,
                                  pws1, pwd1, pws2, pwd2, pws3, pwd3,
                                  pWh, pWh3, pdeg, ppool, pcnt, n, gN);
    // ---- degree count + layer-1 logits (fused) ----
    count_asad_kernel<<<gEdge4 + gN, TB>>>(dst, E, Etot, pdeg, x, pws1, pwd1,
                                           pas, pad, n, gEdge4);
    scan_partial_kernel<<<nb, 256>>>(pdeg, ppart, n);
    scan_final_kernel<<<nb, 256>>>(pdeg, ppart, prow, pcur, n, nb);
    scatter_kernel<<<gEdge4, TB>>>(src, dst, E, Etot, pcur, pcol);

    // ---- layer 1 ----
    aggr11_kernel<<<gHalfWarp, TB>>>(prow, pcol, pas, pad, x, pG1, n);
    gemmK11_kernel<<<gGemmK11, TB>>>(pG1, W1, b1, pws2, pwd2, pA, pas, pad, n);

    // ---- layer 2 + layer-3 GEMM (fused) ----
    aggr128_raw_kernel<<<gNodeWarp, TB>>>(prow, pcol, pas, pad, pA, pG2, n);
    wmma_fused_kernel<<<gWmma, 128>>>(pG2, pWh, pWh3, b2, pws3, pwd3,
                                      ph16, pas, pad, nPad, n);

    // ---- layer 3 aggregation + pooling ----
    fused_aggr16_pool_kernel<<<gHalfWarp, TB>>>(prow, pcol, pas, pad, ph16, b3,
                                                batch, ppool, pcnt, n);
    finalize_kernel<<<gPool, TB>>>(ppool, pcnt, out);
}

// round 11
// speedup vs baseline: 2.7477x; 1.0694x over previous
#include <cuda_runtime.h>
#include <cuda_fp16.h>
#include <mma.h>
#include <math.h>
#include <stdint.h>

using namespace nvcuda;

// ---------------------------------------------------------------------------
// GAT (3 layers) + mean pool + sigmoid.
// - Layer 1 aggregates RAW x (11-dim) via linearity; logits from x·(W@a).
// - Layer-2 GEMM on wmma; layer-3 GEMM fused into the same kernel.
// - Aggregations: direct-exp softmax (logits provably tiny), col-load dedup
//   via lane&7 + shuffle, deferred den reduce. Half-warp kernels use
//   WARP-UNIFORM trip counts so every lane participates in every shuffle
//   (R10 crash: shuffle-sourced addresses from non-participating lanes).
// ---------------------------------------------------------------------------

#define NMAX   50000
#define NPAD   50048
#define EMAX   800000
#define ETOTMX (EMAX + NMAX)
#define HID    128
#define F_IN   11
#define NC     16
#define NG     64
#define SCAN_CHUNK 1024
#define FULLM  0xffffffffu

__device__ __align__(16) __half g_A[NPAD * HID];    // layer-1 output (fp16)
__device__ __align__(16) __half g_G2[NPAD * HID];   // aggr of A (wmma input)
__device__ __align__(16) __half g_h16[NPAD * NC];   // h3 = relu(C)@W3 (fp16)
__device__ __align__(16) __half g_Wh[HID * HID];    // W2 fp16
__device__ __align__(16) __half g_Wh3[HID * NC];    // W3 fp16
__device__ float  g_G1[NMAX * F_IN];                // aggr of x (fp32)
__device__ float  g_as[NMAX];
__device__ float  g_ad[NMAX];
__device__ float  g_ws1[F_IN],  g_wd1[F_IN];
__device__ float  g_ws2[HID],   g_wd2[HID];
__device__ float  g_ws3[HID],   g_wd3[HID];
__device__ float  g_pool[NG * NC];
__device__ float  g_cnt[NG];
__device__ int    g_deg[NMAX];
__device__ int    g_rowptr[NMAX + 1];
__device__ int    g_cursor[NMAX];
__device__ int    g_partial[128];
__device__ int    g_col[ETOTMX];

// --------------------------- setup: zeroing + precompute --------------------
__global__ void setup_kernel(const float* __restrict__ W1,
                             const float* __restrict__ a_s1, const float* __restrict__ a_d1,
                             const float* __restrict__ W2,
                             const float* __restrict__ a_s2, const float* __restrict__ a_d2,
                             const float* __restrict__ W3,
                             const float* __restrict__ a_s3, const float* __restrict__ a_d3,
                             float* __restrict__ ws1, float* __restrict__ wd1,
                             float* __restrict__ ws2, float* __restrict__ wd2,
                             float* __restrict__ ws3, float* __restrict__ wd3,
                             __half* __restrict__ Wh, __half* __restrict__ Wh3,
                             int* __restrict__ deg,
                             float* __restrict__ pool, float* __restrict__ cnt,
                             int n, int nodeBlocks) {
    int b = blockIdx.x, t = threadIdx.x;
    if (b < nodeBlocks) {
        int i = b * 256 + t;
        if (i < n) deg[i] = 0;
        if (i < NG * NC) pool[i] = 0.f;
        if (i < NG) cnt[i] = 0.f;
    } else if (b == nodeBlocks) {
        if (t < HID) {
            float s = 0.f, d = 0.f;
            for (int c = 0; c < HID; c++) {
                float w = __ldg(W2 + t * HID + c);
                s = fmaf(w, __ldg(a_s2 + c), s);
                d = fmaf(w, __ldg(a_d2 + c), d);
            }
            ws2[t] = s; wd2[t] = d;
        } else {
            int k = t - HID;
            float s = 0.f, d = 0.f;
            for (int c = 0; c < NC; c++) {
                float w = __ldg(W3 + k * NC + c);
                s = fmaf(w, __ldg(a_s3 + c), s);
                d = fmaf(w, __ldg(a_d3 + c), d);
            }
            ws3[k] = s; wd3[k] = d;
        }
    } else if (b == nodeBlocks + 1) {
        if (t < F_IN) {
            float s = 0.f, d = 0.f;
            for (int c = 0; c < HID; c++) {
                float w = __ldg(W1 + t * HID + c);
                s = fmaf(w, __ldg(a_s1 + c), s);
                d = fmaf(w, __ldg(a_d1 + c), d);
            }
            ws1[t] = s; wd1[t] = d;
        }
    } else if (b < nodeBlocks + 66) {
        int i = (b - nodeBlocks - 2) * 256 + t;
        if (i < HID * HID) Wh[i] = __float2half_rn(__ldg(W2 + i));
    } else {
        int i = (b - nodeBlocks - 66) * 256 + t;
        if (i < HID * NC) Wh3[i] = __float2half_rn(__ldg(W3 + i));
    }
}

// ----------------- count_deg + layer-1 logits (fused) -----------------------
__global__ void count_asad_kernel(const int* __restrict__ dst, int E, int Etot,
                                  int* __restrict__ deg,
                                  const float* __restrict__ x,
                                  const float* __restrict__ ws1,
                                  const float* __restrict__ wd1,
                                  float* __restrict__ as_o, float* __restrict__ ad_o,
                                  int n, int edgeBlocks) {
    int b = blockIdx.x, tt = threadIdx.x;
    if (b < edgeBlocks) {
        int t = (b * 256 + tt) * 4;
        int d[4];
#pragma unroll
        for (int j = 0; j < 4; j++) {
            int i = t + j;
            d[j] = (i < Etot) ? (i < E ? __ldg(dst + i) : (i - E)) : -1;
        }
#pragma unroll
        for (int j = 0; j < 4; j++)
            if (d[j] >= 0) atomicAdd(&deg[d[j]], 1);
    } else {
        int i = (b - edgeBlocks) * 256 + tt;
        if (i >= n) return;
        const float* row = x + (size_t)i * F_IN;
        float s = 0.f, d = 0.f;
#pragma unroll
        for (int k = 0; k < F_IN; k++) {
            float v = __ldg(row + k);
            s = fmaf(v, __ldg(ws1 + k), s);
            d = fmaf(v, __ldg(wd1 + k), d);
        }
        as_o[i] = s; ad_o[i] = d;
    }
}

// --------------------------- scan (2 kernels) -------------------------------
__global__ void scan_partial_kernel(const int* __restrict__ deg,
                                    int* __restrict__ partial, int n) {
    __shared__ int ws[8];
    int base = blockIdx.x * SCAN_CHUNK + threadIdx.x * 4;
    int s = 0;
#pragma unroll
    for (int j = 0; j < 4; j++) {
        int i = base + j;
        if (i < n) s += __ldg(deg + i);
    }
#pragma unroll
    for (int o = 16; o > 0; o >>= 1) s += __shfl_xor_sync(FULLM, s, o);
    int lane = threadIdx.x & 31, wid = threadIdx.x >> 5;
    if (lane == 0) ws[wid] = s;
    __syncthreads();
    if (wid == 0 && lane < 8) {
        int v = ws[lane];
#pragma unroll
        for (int o = 4; o > 0; o >>= 1) v += __shfl_xor_sync(0xffu, v, o);
        if (lane == 0) partial[blockIdx.x] = v;
    }
}

__global__ void scan_final_kernel(const int* __restrict__ deg,
                                  const int* __restrict__ partial,
                                  int* __restrict__ rowptr,
                                  int* __restrict__ cursor, int n, int nb) {
    __shared__ int ws[8];
    __shared__ int w2s[2];
    __shared__ int s_off;
    int t = threadIdx.x, lane = t & 31, wid = t >> 5;

    int pv = 0;
    if (t < 64 && t < blockIdx.x && t < nb) pv = __ldg(partial + t);
    if (t < 64) {
#pragma unroll
        for (int o = 16; o > 0; o >>= 1) pv += __shfl_xor_sync(FULLM, pv, o);
        if (lane == 0) w2s[wid] = pv;
    }
    __syncthreads();
    if (t == 0) s_off = w2s[0] + w2s[1];

    int base = blockIdx.x * SCAN_CHUNK + t * 4;
    int v[4];
#pragma unroll
    for (int j = 0; j < 4; j++) {
        int i = base + j;
        v[j] = (i < n) ? __ldg(deg + i) : 0;
    }
    int tot = v[0] + v[1] + v[2] + v[3];
    int x = tot;
#pragma unroll
    for (int o = 1; o < 32; o <<= 1) {
        int u = __shfl_up_sync(FULLM, x, o);
        if (lane >= o) x += u;
    }
    int warp_excl = x - tot;
    if (lane == 31) ws[wid] = x;
    __syncthreads();
    if (wid == 0) {
        int val = (lane < 8) ? ws[lane] : 0;
#pragma unroll
        for (int o = 1; o < 8; o <<= 1) {
            int u = __shfl_up_sync(FULLM, val, o);
            if (lane >= o) val += u;
        }
        if (lane < 8) ws[lane] = val;
    }
    __syncthreads();
    int off = s_off + (wid > 0 ? ws[wid - 1] : 0) + warp_excl;
    int run = off;
#pragma unroll
    for (int j = 0; j < 4; j++) {
        run += v[j];
        int i = base + j;
        if (i < n) { rowptr[i + 1] = run; cursor[i] = run - v[j]; }
    }
    if (blockIdx.x == 0 && t == 0) rowptr[0] = 0;
}

__global__ void scatter_kernel(const int* __restrict__ src, const int* __restrict__ dst,
                               int E, int Etot,
                               int* __restrict__ cursor, int* __restrict__ col) {
    int t = (blockIdx.x * blockDim.x + threadIdx.x) * 4;
    int s[4], d[4];
#pragma unroll
    for (int j = 0; j < 4; j++) {
        int i = t + j;
        bool act = i < Etot;
        s[j] = act ? (i < E ? __ldg(src + i) : (i - E)) : 0;
        d[j] = act ? (i < E ? __ldg(dst + i) : (i - E)) : -1;
    }
#pragma unroll
    for (int j = 0; j < 4; j++) {
        if (d[j] >= 0) {
            int pos = atomicAdd(&cursor[d[j]], 1);
            col[pos] = s[j];
        }
    }
}

// ------------------ layer-1 aggregation of raw x (11-dim) -------------------
// 16-lane group per node; direct-exp softmax; WARP-UNIFORM trip count.
__global__ void aggr11_kernel(const int* __restrict__ rowptr,
                              const int* __restrict__ col,
                              const float* __restrict__ as_v,
                              const float* __restrict__ ad_v,
                              const float* __restrict__ x,
                              float* __restrict__ G, int n) {
    int w = (blockIdx.x * blockDim.x + threadIdx.x) >> 5;
    int lane = threadIdx.x & 31;
    int local = lane & 15;
    int slot = lane & 7;
    int node = w * 2 + (lane >> 4);
    int c = local;
    bool active = node < n;

    float advv = active ? __ldg(ad_v + node) : 0.f;
    int beg = active ? __ldg(rowptr + node) : 0;
    int end = active ? __ldg(rowptr + node + 1) : 0;

    // uniform trips across both half-warp groups (shuffle participation!)
    int iters = (end - beg + 7) >> 3;
    int oiters = __shfl_xor_sync(FULLM, iters, 16);
    int maxIters = iters > oiters ? iters : oiters;

    const float NEG_INF = __int_as_float(0xFF800000);
    float denp = 0.0f, acc = 0.0f;

    for (int it = 0; it < maxIters; it++) {
        int idx = beg + it * 8 + slot;
        bool eact = idx < end;
        int sc = __ldg(col + (eact ? idx : 0));    // col[0] always valid
        float e = eact ? (__ldg(as_v + sc) + advv) : NEG_INF;
        e = e > 0.f ? e : 0.2f * e;
        float wgt = __expf(e);                     // 0 for inactive
        denp += wgt;

        float xb[8];
#pragma unroll
        for (int j = 0; j < 8; j++) {
            int sj = __shfl_sync(FULLM, sc, j, 16);
            xb[j] = (c < F_IN) ? __ldg(x + (size_t)sj * F_IN + c) : 0.f;
        }
#pragma unroll
        for (int j = 0; j < 8; j++) {
            float wj = __shfl_sync(FULLM, wgt, j, 16);
            acc = fmaf(wj, xb[j], acc);
        }
    }
    denp += __shfl_xor_sync(FULLM, denp, 1, 8);
    denp += __shfl_xor_sync(FULLM, denp, 2, 8);
    denp += __shfl_xor_sync(FULLM, denp, 4, 8);
    if (active && c < F_IN) G[(size_t)node * F_IN + c] = acc / denp;
}

// --------------- layer-1 GEMM: A = relu(G1@W1+b1), epi: as2/ad2 -------------
__global__ void gemmK11_kernel(const float* __restrict__ in,
                               const float* __restrict__ W,
                               const float* __restrict__ bias,
                               const float* __restrict__ ws2,
                               const float* __restrict__ wd2,
                               __half* __restrict__ A,
                               float* __restrict__ as_o,
                               float* __restrict__ ad_o, int n) {
    int w    = (blockIdx.x * blockDim.x + threadIdx.x) >> 5;
    int lane = threadIdx.x & 31;
    int node0 = w * 8;
    if (node0 >= n) return;

    int nid[8];
#pragma unroll
    for (int i = 0; i < 8; i++) {
        int nn = node0 + i;
        nid[i] = nn < n ? nn : (n - 1);
    }

    float4 bv = *(const float4*)(bias + lane * 4);
    float4 acc[8];
#pragma unroll
    for (int i = 0; i < 8; i++) acc[i] = bv;

#pragma unroll
    for (int k = 0; k < F_IN; k++) {
        float4 wv = *(const float4*)(W + k * HID + lane * 4);
#pragma unroll
        for (int i = 0; i < 8; i++) {
            float a = __ldg(in + (size_t)nid[i] * F_IN + k);
            acc[i].x = fmaf(a, wv.x, acc[i].x);
            acc[i].y = fmaf(a, wv.y, acc[i].y);
            acc[i].z = fmaf(a, wv.z, acc[i].z);
            acc[i].w = fmaf(a, wv.w, acc[i].w);
        }
    }

    float4 sv = *(const float4*)(ws2 + lane * 4);
    float4 dv = *(const float4*)(wd2 + lane * 4);

#pragma unroll
    for (int i = 0; i < 8; i++) {
        float ox = fmaxf(acc[i].x, 0.f);
        float oy = fmaxf(acc[i].y, 0.f);
        float oz = fmaxf(acc[i].z, 0.f);
        float ow = fmaxf(acc[i].w, 0.f);
        __half2 p0 = __floats2half2_rn(ox, oy);
        __half2 p1 = __floats2half2_rn(oz, ow);
        uint2 packed = make_uint2(*(unsigned*)&p0, *(unsigned*)&p1);
        *(uint2*)(A + (size_t)nid[i] * HID + lane * 4) = packed;

        float ps = ox * sv.x + oy * sv.y + oz * sv.z + ow * sv.w;
        float pd = ox * dv.x + oy * dv.y + oz * dv.z + ow * dv.w;
#pragma unroll
        for (int o = 16; o > 0; o >>= 1) {
            ps += __shfl_xor_sync(FULLM, ps, o);
            pd += __shfl_xor_sync(FULLM, pd, o);
        }
        if (lane == 0) { as_o[nid[i]] = ps; ad_o[nid[i]] = pd; }
    }
}

// ------------------ raw softmax aggregation, C=128 (fp16) -------------------
// warp per node (uniform trips by construction); direct-exp; col dedup.
__global__ void aggr128_raw_kernel(const int* __restrict__ rowptr,
                                   const int* __restrict__ col,
                                   const float* __restrict__ as_v,
                                   const float* __restrict__ ad_v,
                                   const __half* __restrict__ h,
                                   __half* __restrict__ out, int n) {
    int node = (blockIdx.x * blockDim.x + threadIdx.x) >> 5;
    if (node >= n) return;
    int lane = threadIdx.x & 31;
    int slot = lane & 7;

    float advv = __ldg(ad_v + node);
    int beg = __ldg(rowptr + node);
    int end = __ldg(rowptr + node + 1);

    const float NEG_INF = __int_as_float(0xFF800000);
    float denp = 0.0f;
    float4 acc = make_float4(0.f, 0.f, 0.f, 0.f);

    for (int i = beg; i < end; i += 8) {
        int idx = i + slot;
        bool eact = idx < end;
        int sc = __ldg(col + (eact ? idx : beg));
        float e = eact ? (__ldg(as_v + sc) + advv) : NEG_INF;
        e = e > 0.f ? e : 0.2f * e;
        float wgt = __expf(e);
        denp += wgt;

        uint2 hb[8];
#pragma unroll
        for (int j = 0; j < 8; j++) {
            int sj = __shfl_sync(FULLM, sc, j);
            hb[j] = *(const uint2*)(h + (size_t)sj * HID + lane * 4);
        }
#pragma unroll
        for (int j = 0; j < 8; j++) {
            float wj = __shfl_sync(FULLM, wgt, j);
            __half2 h0 = *(__half2*)&hb[j].x;
            __half2 h1 = *(__half2*)&hb[j].y;
            float2 f0 = __half22float2(h0);
            float2 f1 = __half22float2(h1);
            acc.x = fmaf(wj, f0.x, acc.x);
            acc.y = fmaf(wj, f0.y, acc.y);
            acc.z = fmaf(wj, f1.x, acc.z);
            acc.w = fmaf(wj, f1.y, acc.w);
        }
    }

    denp += __shfl_xor_sync(FULLM, denp, 1, 8);
    denp += __shfl_xor_sync(FULLM, denp, 2, 8);
    denp += __shfl_xor_sync(FULLM, denp, 4, 8);

    float inv = 1.0f / denp;
    __half2 p0 = __floats2half2_rn(acc.x * inv, acc.y * inv);
    __half2 p1 = __floats2half2_rn(acc.z * inv, acc.w * inv);
    uint2 packed = make_uint2(*(unsigned*)&p0, *(unsigned*)&p1);
    *(uint2*)(out + (size_t)node * HID + lane * 4) = packed;
}

// ---- layer-2 wmma GEMM + fused layer-3 GEMM --------------------------------
__global__ __launch_bounds__(128) void wmma_fused_kernel(
        const __half* __restrict__ A,
        const __half* __restrict__ Wh,    // W2 fp16
        const __half* __restrict__ Wh3,   // W3 fp16 [128,16]
        const float* __restrict__ bias,
        const float* __restrict__ ws3,
        const float* __restrict__ wd3,
        __half* __restrict__ h16,
        float* __restrict__ as_o,
        float* __restrict__ ad_o, int nPad, int n) {
    __shared__ float  s_c[64 * HID];
    __shared__ __half s_ch[64 * HID];
    int warp = threadIdx.x >> 5;
    int lane = threadIdx.x & 31;
    int row0 = blockIdx.x * 64 + warp * 16;
    if (row0 >= nPad) return;

    wmma::fragment<wmma::accumulator, 16, 16, 16, float> acc[8];
#pragma unroll
    for (int i = 0; i < 8; i++) wmma::fill_fragment(acc[i], 0.f);

#pragma unroll
    for (int k = 0; k < 8; k++) {
        wmma::fragment<wmma::matrix_a, 16, 16, 16, __half, wmma::row_major> a;
        wmma::load_matrix_sync(a, A + (size_t)row0 * HID + k * 16, HID);
#pragma unroll
        for (int nt = 0; nt < 8; nt++) {
            wmma::fragment<wmma::matrix_b, 16, 16, 16, __half, wmma::row_major> b;
            wmma::load_matrix_sync(b, Wh + k * 16 * HID + nt * 16, HID);
            wmma::mma_sync(acc[nt], a, b, acc[nt]);
        }
    }
    float*  my  = s_c  + warp * 16 * HID;
    __half* myh = s_ch + warp * 16 * HID;
#pragma unroll
    for (int nt = 0; nt < 8; nt++)
        wmma::store_matrix_sync(my + nt * 16, acc[nt], HID, wmma::mem_row_major);
    __syncwarp();

    float4 bv = *(const float4*)(bias + lane * 4);
    float4 sv = *(const float4*)(ws3 + lane * 4);
    float4 dv = *(const float4*)(wd3 + lane * 4);
#pragma unroll
    for (int r = 0; r < 16; r++) {
        int row = row0 + r;
        float4 v = *(const float4*)(my + r * HID + lane * 4);
        float ox = fmaxf(v.x + bv.x, 0.f);
        float oy = fmaxf(v.y + bv.y, 0.f);
        float oz = fmaxf(v.z + bv.z, 0.f);
        float ow = fmaxf(v.w + bv.w, 0.f);
        __half2 p0 = __floats2half2_rn(ox, oy);
        __half2 p1 = __floats2half2_rn(oz, ow);
        uint2 packed = make_uint2(*(unsigned*)&p0, *(unsigned*)&p1);
        *(uint2*)(myh + r * HID + lane * 4) = packed;
        if (row < n) {
            float ps = ox * sv.x + oy * sv.y + oz * sv.z + ow * sv.w;
            float pd = ox * dv.x + oy * dv.y + oz * dv.z + ow * dv.w;
#pragma unroll
            for (int o = 16; o > 0; o >>= 1) {
                ps += __shfl_xor_sync(FULLM, ps, o);
                pd += __shfl_xor_sync(FULLM, pd, o);
            }
            if (lane == 0) { as_o[row] = ps; ad_o[row] = pd; }
        }
    }
    __syncwarp();

    wmma::fragment<wmma::accumulator, 16, 16, 16, float> acc3;
    wmma::fill_fragment(acc3, 0.f);
#pragma unroll
    for (int k = 0; k < 8; k++) {
        wmma::fragment<wmma::matrix_a, 16, 16, 16, __half, wmma::row_major> a;
        wmma::load_matrix_sync(a, myh + k * 16, HID);
        wmma::fragment<wmma::matrix_b, 16, 16, 16, __half, wmma::row_major> b;
        wmma::load_matrix_sync(b, Wh3 + k * 16 * NC, NC);
        wmma::mma_sync(acc3, a, b, acc3);
    }
    wmma::store_matrix_sync(my, acc3, NC, wmma::mem_row_major);
    __syncwarp();
#pragma unroll
    for (int q = 0; q < 8; q++) {
        int idx = q * 32 + lane;
        h16[(size_t)row0 * NC + idx] = __float2half_rn(my[idx]);
    }
}

// ------------- fused aggregation C=16 + pooling (layer 3) -------------------
// half-warp per node; WARP-UNIFORM trip count; direct-exp softmax.
__global__ void fused_aggr16_pool_kernel(const int* __restrict__ rowptr,
                                         const int* __restrict__ col,
                                         const float* __restrict__ as_v,
                                         const float* __restrict__ ad_v,
                                         const __half* __restrict__ h,
                                         const float* __restrict__ bias,
                                         const int* __restrict__ batch,
                                         float* __restrict__ pool,
                                         float* __restrict__ cnt, int n) {
    int w = (blockIdx.x * blockDim.x + threadIdx.x) >> 5;
    int lane = threadIdx.x & 31;
    int local = lane & 15;
    int slot = lane & 7;
    int node = w * 2 + (lane >> 4);
    int c = local;
    bool active = node < n;

    float advv = active ? __ldg(ad_v + node) : 0.f;
    int beg = active ? __ldg(rowptr + node) : 0;
    int end = active ? __ldg(rowptr + node + 1) : 0;

    int iters = (end - beg + 7) >> 3;
    int oiters = __shfl_xor_sync(FULLM, iters, 16);
    int maxIters = iters > oiters ? iters : oiters;

    const float NEG_INF = __int_as_float(0xFF800000);
    float denp = 0.0f, acc = 0.0f;

    for (int it = 0; it < maxIters; it++) {
        int idx = beg + it * 8 + slot;
        bool eact = idx < end;
        int sc = __ldg(col + (eact ? idx : 0));
        float e = eact ? (__ldg(as_v + sc) + advv) : NEG_INF;
        e = e > 0.f ? e : 0.2f * e;
        float wgt = __expf(e);
        denp += wgt;

        float hb[8];
#pragma unroll
        for (int j = 0; j < 8; j++) {
            int sj = __shfl_sync(FULLM, sc, j, 16);
            hb[j] = __half2float(__ldg(h + (size_t)sj * NC + c));
        }
#pragma unroll
        for (int j = 0; j < 8; j++) {
            float wj = __shfl_sync(FULLM, wgt, j, 16);
            acc = fmaf(wj, hb[j], acc);
        }
    }

    denp += __shfl_xor_sync(FULLM, denp, 1, 8);
    denp += __shfl_xor_sync(FULLM, denp, 2, 8);
    denp += __shfl_xor_sync(FULLM, denp, 4, 8);

    if (active) {
        float val = fmaxf(acc / denp + __ldg(bias + c), 0.f);
        int g = __ldg(batch + node);
        atomicAdd(&pool[g * NC + c], val);
        if (c == 0) atomicAdd(&cnt[g], 1.0f);
    }
}

__global__ void finalize_kernel(const float* __restrict__ pool,
                                const float* __restrict__ cnt,
                                float* __restrict__ outp) {
    int t = blockIdx.x * blockDim.x + threadIdx.x;
    if (t >= NG * NC) return;
    int g = t >> 4;
    float v = pool[t] / fmaxf(cnt[g], 1.0f);
    outp[t] = 1.0f / (1.0f + expf(-v));
}

// ---------------------------------------------------------------------------

extern "C" void kernel_launch(void* const* d_in, const int* in_sizes, int n_in,
                              void* d_out, int out_size) {
    const float* x     = (const float*)d_in[0];
    const int*   ei    = (const int*)  d_in[1];
    const int*   batch = (const int*)  d_in[3];
    const float* W1  = (const float*)d_in[4];
    const float* as1 = (const float*)d_in[5];
    const float* ad1 = (const float*)d_in[6];
    const float* b1  = (const float*)d_in[7];
    const float* W2  = (const float*)d_in[8];
    const float* as2 = (const float*)d_in[9];
    const float* ad2 = (const float*)d_in[10];
    const float* b2  = (const float*)d_in[11];
    const float* W3  = (const float*)d_in[12];
    const float* as3 = (const float*)d_in[13];
    const float* ad3 = (const float*)d_in[14];
    const float* b3  = (const float*)d_in[15];
    float* out = (float*)d_out;

    int n    = in_sizes[0] / F_IN;
    int E    = in_sizes[1] / 2;
    int Etot = E + n;
    const int* src = ei;
    const int* dst = ei + E;

    float *pas, *pad, *ppool, *pcnt, *pG1;
    float *pws1, *pwd1, *pws2, *pwd2, *pws3, *pwd3;
    __half *pA, *pG2, *ph16, *pWh, *pWh3;
    int *pdeg, *prow, *pcur, *pcol, *ppart;
    cudaGetSymbolAddress((void**)&pA,    g_A);
    cudaGetSymbolAddress((void**)&pG2,   g_G2);
    cudaGetSymbolAddress((void**)&ph16,  g_h16);
    cudaGetSymbolAddress((void**)&pWh,   g_Wh);
    cudaGetSymbolAddress((void**)&pWh3,  g_Wh3);
    cudaGetSymbolAddress((void**)&pG1,   g_G1);
    cudaGetSymbolAddress((void**)&pas,   g_as);
    cudaGetSymbolAddress((void**)&pad,   g_ad);
    cudaGetSymbolAddress((void**)&pws1,  g_ws1);
    cudaGetSymbolAddress((void**)&pwd1,  g_wd1);
    cudaGetSymbolAddress((void**)&pws2,  g_ws2);
    cudaGetSymbolAddress((void**)&pwd2,  g_wd2);
    cudaGetSymbolAddress((void**)&pws3,  g_ws3);
    cudaGetSymbolAddress((void**)&pwd3,  g_wd3);
    cudaGetSymbolAddress((void**)&ppool, g_pool);
    cudaGetSymbolAddress((void**)&pcnt,  g_cnt);
    cudaGetSymbolAddress((void**)&pdeg,  g_deg);
    cudaGetSymbolAddress((void**)&prow,  g_rowptr);
    cudaGetSymbolAddress((void**)&pcur,  g_cursor);
    cudaGetSymbolAddress((void**)&pcol,  g_col);
    cudaGetSymbolAddress((void**)&ppart, g_partial);

    const int TB = 256;
    int nPad     = (n + 127) & ~127;
    int nb       = (n + SCAN_CHUNK - 1) / SCAN_CHUNK;
    int gN       = (n + TB - 1) / TB;
    int gEdge4   = (Etot + TB * 4 - 1) / (TB * 4);
    int warps128 = (n + 7) / 8;
    int gGemmK11 = (warps128 * 32 + TB - 1) / TB;
    int gWmma    = nPad / 64;
    int gNodeWarp= (n * 32 + TB - 1) / TB;
    int gHalfWarp= (((n + 1) / 2) * 32 + TB - 1) / TB;
    int gPool    = (NG * NC + TB - 1) / TB;

    setup_kernel<<<gN + 74, TB>>>(W1, as1, ad1, W2, as2, ad2, W3, as3, ad3,
                                  pws1, pwd1, pws2, pwd2, pws3, pwd3,
                                  pWh, pWh3, pdeg, ppool, pcnt, n, gN);
    count_asad_kernel<<<gEdge4 + gN, TB>>>(dst, E, Etot, pdeg, x, pws1, pwd1,
                                           pas, pad, n, gEdge4);
    scan_partial_kernel<<<nb, 256>>>(pdeg, ppart, n);
    scan_final_kernel<<<nb, 256>>>(pdeg, ppart, prow, pcur, n, nb);
    scatter_kernel<<<gEdge4, TB>>>(src, dst, E, Etot, pcur, pcol);

    aggr11_kernel<<<gHalfWarp, TB>>>(prow, pcol, pas, pad, x, pG1, n);
    gemmK11_kernel<<<gGemmK11, TB>>>(pG1, W1, b1, pws2, pwd2, pA, pas, pad, n);

    aggr128_raw_kernel<<<gNodeWarp, TB>>>(prow, pcol, pas, pad, pA, pG2, n);
    wmma_fused_kernel<<<gWmma, 128>>>(pG2, pWh, pWh3, b2, pws3, pwd3,
                                      ph16, pas, pad, nPad, n);

    fused_aggr16_pool_kernel<<<gHalfWarp, TB>>>(prow, pcol, pas, pad, ph16, b3,
                                                batch, ppool, pcnt, n);
    finalize_kernel<<<gPool, TB>>>(ppool, pcnt, out);
}